// round 12
// baseline (speedup 1.0000x reference)
#include <cuda_runtime.h>
#include <cstdint>

#define BDIM 16
#define SEQ  1024
#define CDIM 768
#define NH   9
#define HDIM 64
#define MTOT (BDIM*SEQ)        // 16384
#define QKVN (3*NH*HDIM)       // 1728
#define PK   (NH*HDIM)         // 576

// Does THIS device-compile stage support tcgen05 (arch-/family-specific target)?
#if defined(__CUDA_ARCH__)
#  if defined(__CUDA_ARCH_FEAT_SM103_ALL) || defined(__CUDA_ARCH_FEAT_SM100_ALL) || \
      (defined(__CUDA_ARCH_FAMILY_SPECIFIC__) && (__CUDA_ARCH_FAMILY_SPECIFIC__ >= 1000))
#    define HAS_TCGEN05 1
#  else
#    define HAS_TCGEN05 0
#  endif
#else
#  define HAS_TCGEN05 0
#endif

// Scratch (device globals: allocation-free per harness rules). tf32 bit patterns.
__device__ uint32_t g_x_tf[(size_t)MTOT * CDIM];
__device__ uint32_t g_qw_tf[(size_t)QKVN * CDIM];
__device__ uint32_t g_pw_tf[(size_t)CDIM * PK];
__device__ uint32_t g_qkv[(size_t)MTOT * QKVN];
__device__ uint32_t g_vt[(size_t)BDIM * NH * HDIM * SEQ];   // V^T [b,h,d,seq]
__device__ uint32_t g_attn[(size_t)MTOT * PK];

__device__ __forceinline__ uint32_t f2tf(float f) {
    uint32_t u;
    asm("cvt.rna.tf32.f32 %0, %1;" : "=r"(u) : "f"(f));
    return u;
}
__device__ __forceinline__ void mma_tf32(float* d, const uint32_t* a,
                                         uint32_t b0, uint32_t b1) {
    asm volatile(
        "mma.sync.aligned.m16n8k8.row.col.f32.tf32.tf32.f32 "
        "{%0,%1,%2,%3},{%4,%5,%6,%7},{%8,%9},{%0,%1,%2,%3};\n"
        : "+f"(d[0]), "+f"(d[1]), "+f"(d[2]), "+f"(d[3])
        : "r"(a[0]), "r"(a[1]), "r"(a[2]), "r"(a[3]), "r"(b0), "r"(b1));
}
__device__ __forceinline__ uint32_t smaddr(const void* p) {
    return (uint32_t)__cvta_generic_to_shared(p);
}
__device__ __forceinline__ void cpa16(uint32_t s, const void* g) {
    asm volatile("cp.async.cg.shared.global [%0], [%1], 16;" :: "r"(s), "l"(g));
}
#define CPA_COMMIT() asm volatile("cp.async.commit_group;")
#define CPA_WAIT0()  asm volatile("cp.async.wait_group 0;")
#define CPA_WAIT1()  asm volatile("cp.async.wait_group 1;")
#define CPA_WAIT2()  asm volatile("cp.async.wait_group 2;")
#define SWZ128(x) ((x) ^ (((x) >> 3) & 0x70))

// ---------------------------------------------------------------------------
__global__ void cvt_tf32_kernel(const float4* __restrict__ in,
                                uint4* __restrict__ out, int n4) {
    const int i = blockIdx.x * blockDim.x + threadIdx.x;
    if (i < n4) {
        float4 v = in[i];
        uint4 o = { f2tf(v.x), f2tf(v.y), f2tf(v.z), f2tf(v.w) };
        out[i] = o;
    }
}

// V transpose: g_qkv[token][1152 + h*64 + d] -> g_vt[(bh*64+d)*SEQ + n]
__global__ void transpose_v_kernel(const uint32_t* __restrict__ qkv,
                                   uint32_t* __restrict__ vt) {
    __shared__ uint32_t tile[32][33];
    const int bh = blockIdx.z, b = bh / NH, h = bh % NH;
    const int n0 = blockIdx.x * 32, d0 = blockIdx.y * 32;
    const int tx = threadIdx.x, ty = threadIdx.y;
    #pragma unroll
    for (int i = ty; i < 32; i += 8)
        tile[i][tx] = qkv[(size_t)(b * SEQ + n0 + i) * QKVN
                          + 2 * NH * HDIM + h * HDIM + d0 + tx];
    __syncthreads();
    #pragma unroll
    for (int i = ty; i < 32; i += 8)
        vt[((size_t)bh * HDIM + d0 + i) * SEQ + n0 + tx] = tile[tx][i];
}

#if HAS_TCGEN05
__device__ __forceinline__ uint32_t elect_one_pred() {
    uint32_t pred;
    asm volatile("{\n\t.reg .pred p;\n\telect.sync _|p, 0xFFFFFFFF;\n\t"
                 "selp.b32 %0, 1, 0, p;\n\t}" : "=r"(pred));
    return pred;
}
#define TC_ALLOC(sm_res, n) \
    asm volatile("tcgen05.alloc.cta_group::1.sync.aligned.shared::cta.b32 [%0], %1;" \
                 :: "r"((uint32_t)(sm_res)), "r"((uint32_t)(n)) : "memory")
#define TC_RELINQ() \
    asm volatile("tcgen05.relinquish_alloc_permit.cta_group::1.sync.aligned;")
#define TC_DEALLOC(tm, n) \
    asm volatile("tcgen05.dealloc.cta_group::1.sync.aligned.b32 %0, %1;" :: "r"(tm), "r"((uint32_t)(n)))
#define TC_COMMIT(mb) \
    asm volatile("tcgen05.commit.cta_group::1.mbarrier::arrive::one.shared::cluster.b64 [%0];" \
                 :: "r"((uint32_t)(mb)) : "memory")
#define TC_FENCE_AFTER()  asm volatile("tcgen05.fence::after_thread_sync;" ::: "memory")
#define TC_FENCE_BEFORE() asm volatile("tcgen05.fence::before_thread_sync;" ::: "memory")
#define TC_WAIT_LD() asm volatile("tcgen05.wait::ld.sync.aligned;" ::: "memory")
#define TC_WAIT_ST() asm volatile("tcgen05.wait::st.sync.aligned;" ::: "memory")
#define MBAR_INIT(mb, c) \
    asm volatile("mbarrier.init.shared.b64 [%0], %1;" :: "r"((uint32_t)(mb)), "r"((uint32_t)(c)) : "memory")
#define MBAR_WAIT(mb, par) do { \
    uint32_t _m = (uint32_t)(mb), _p = (uint32_t)(par), _d; \
    asm volatile("{\n\t.reg .pred p;\n\t" \
        "mbarrier.try_wait.parity.acquire.cta.shared::cta.b64 p, [%1], %2;\n\t" \
        "selp.b32 %0, 1, 0, p;\n\t}" : "=r"(_d) : "r"(_m), "r"(_p) : "memory"); \
    if (!_d) { \
        asm volatile("{\n\t.reg .pred P1;\n\tWL_%=:\n\t" \
            "mbarrier.try_wait.parity.acquire.cta.shared::cta.b64 P1, [%0], %1, 0x989680;\n\t" \
            "@P1 bra.uni WD_%=;\n\tbra.uni WL_%=;\n\tWD_%=:\n\t}" \
            :: "r"(_m), "r"(_p) : "memory"); \
    } } while (0)

__device__ __forceinline__ void tc_mma_tf32_ss(uint32_t d_tmem, uint64_t ad,
                                               uint64_t bd, uint32_t idesc,
                                               uint32_t en) {
    asm volatile(
        "{\n\t.reg .pred p;\n\tsetp.ne.u32 p, %4, 0;\n\t"
        "tcgen05.mma.cta_group::1.kind::tf32 [%0], %1, %2, %3, p;\n\t}"
        :: "r"(d_tmem), "l"(ad), "l"(bd), "r"(idesc), "r"(en) : "memory");
}
__device__ __forceinline__ void tc_mma_tf32_ts(uint32_t d_tmem, uint32_t a_tmem,
                                               uint64_t bd, uint32_t idesc,
                                               uint32_t en) {
    asm volatile(
        "{\n\t.reg .pred p;\n\tsetp.ne.u32 p, %4, 0;\n\t"
        "tcgen05.mma.cta_group::1.kind::tf32 [%0], [%1], %2, %3, p;\n\t}"
        :: "r"(d_tmem), "r"(a_tmem), "l"(bd), "r"(idesc), "r"(en) : "memory");
}
#define TC_LD32(r, ta) \
    asm volatile( \
        "tcgen05.ld.sync.aligned.32x32b.x32.b32 " \
        "{%0,%1,%2,%3,%4,%5,%6,%7,%8,%9,%10,%11,%12,%13,%14,%15," \
        "%16,%17,%18,%19,%20,%21,%22,%23,%24,%25,%26,%27,%28,%29,%30,%31},[%32];" \
        : "=r"((r)[0]), "=r"((r)[1]), "=r"((r)[2]), "=r"((r)[3]), "=r"((r)[4]), \
          "=r"((r)[5]), "=r"((r)[6]), "=r"((r)[7]), "=r"((r)[8]), "=r"((r)[9]), \
          "=r"((r)[10]), "=r"((r)[11]), "=r"((r)[12]), "=r"((r)[13]), "=r"((r)[14]), \
          "=r"((r)[15]), "=r"((r)[16]), "=r"((r)[17]), "=r"((r)[18]), "=r"((r)[19]), \
          "=r"((r)[20]), "=r"((r)[21]), "=r"((r)[22]), "=r"((r)[23]), "=r"((r)[24]), \
          "=r"((r)[25]), "=r"((r)[26]), "=r"((r)[27]), "=r"((r)[28]), "=r"((r)[29]), \
          "=r"((r)[30]), "=r"((r)[31]) \
        : "r"(ta))
#define TC_ST32(ta, r) \
    asm volatile( \
        "tcgen05.st.sync.aligned.32x32b.x32.b32 [%0], " \
        "{%1,%2,%3,%4,%5,%6,%7,%8,%9,%10,%11,%12,%13,%14,%15,%16," \
        "%17,%18,%19,%20,%21,%22,%23,%24,%25,%26,%27,%28,%29,%30,%31,%32};" \
        :: "r"(ta), \
           "r"((r)[0]), "r"((r)[1]), "r"((r)[2]), "r"((r)[3]), "r"((r)[4]), \
           "r"((r)[5]), "r"((r)[6]), "r"((r)[7]), "r"((r)[8]), "r"((r)[9]), \
           "r"((r)[10]), "r"((r)[11]), "r"((r)[12]), "r"((r)[13]), "r"((r)[14]), \
           "r"((r)[15]), "r"((r)[16]), "r"((r)[17]), "r"((r)[18]), "r"((r)[19]), \
           "r"((r)[20]), "r"((r)[21]), "r"((r)[22]), "r"((r)[23]), "r"((r)[24]), \
           "r"((r)[25]), "r"((r)[26]), "r"((r)[27]), "r"((r)[28]), "r"((r)[29]), \
           "r"((r)[30]), "r"((r)[31]) \
        : "memory")
__device__ __forceinline__ uint64_t mk_desc(uint32_t addr) {
    return ((uint64_t)2 << 61) | ((uint64_t)1 << 46) | ((uint64_t)64 << 32)
         | ((uint64_t)1 << 16) | (uint64_t)((addr >> 4) & 0x3FFF);
}
#endif // HAS_TCGEN05

// ===========================================================================
// tcgen05 tf32 GEMM (R8/R9-proven, frozen), 4-stage cp.async, 256 threads.
// ===========================================================================
#define TC_BN 192
#define OFF_A0 1024
#define OFF_B0 (OFF_A0 + 4*16384)
#define TC_SMEM (OFF_B0 + 4*(TC_BN*128))
#if HAS_TCGEN05
#define TC_IDESC ((1u<<4) | (2u<<7) | (2u<<10) | ((TC_BN/8)<<17) | (8u<<24))
#endif

template <bool OUT_TF>
__global__ __launch_bounds__(256) void gemm_tc(
    const uint32_t* __restrict__ A, const uint32_t* __restrict__ W,
    const float* __restrict__ bias, void* __restrict__ Cout,
    int Kdim, int Ndim)
{
#if HAS_TCGEN05
    extern __shared__ char smem[];
    const uint32_t sbase = smaddr(smem);
    const int t = threadIdx.x, lane = t & 31, warp = t >> 5;
    const int m0 = blockIdx.y * 128, n0 = blockIdx.x * TC_BN;
    const uint32_t mb0 = sbase + 8, mb1 = sbase + 16;

    if (warp == 0) { TC_ALLOC(sbase, 256); TC_RELINQ(); }
    if (t == 0) { MBAR_INIT(mb0, 1); MBAR_INIT(mb1, 1); }
    __syncthreads();
    uint32_t tmem;
    asm volatile("ld.shared.b32 %0, [%1];" : "=r"(tmem) : "r"(sbase));

    const int KT = Kdim >> 5;

    auto loadA = [&](int st, int k0) {
        const uint32_t base = sbase + OFF_A0 + st * 16384;
        #pragma unroll
        for (int i = 0; i < 4; i++) {
            const int idx = t + 256 * i, row = idx >> 3, ch = idx & 7;
            cpa16(base + SWZ128((uint32_t)(row * 128 + ch * 16)),
                  A + (size_t)(m0 + row) * Kdim + k0 + ch * 4);
        }
    };
    auto loadB = [&](int st, int k0) {
        const uint32_t base = sbase + OFF_B0 + st * (TC_BN * 128);
        #pragma unroll
        for (int i = 0; i < 6; i++) {
            const int idx = t + 256 * i, row = idx >> 3, ch = idx & 7;
            cpa16(base + SWZ128((uint32_t)(row * 128 + ch * 16)),
                  W + (size_t)(n0 + row) * Kdim + k0 + ch * 4);
        }
    };

    #pragma unroll
    for (int p = 0; p < 3; p++) {
        loadA(p, p * 32); loadB(p, p * 32); CPA_COMMIT();
    }
    int pw0 = 0, pw1 = 0;

    for (int kt = 0; kt < KT; kt++) {
        CPA_WAIT2();
        asm volatile("fence.proxy.async.shared::cta;" ::: "memory");
        __syncthreads();
        if (warp == 0 && elect_one_pred()) {
            const int st = kt & 3;
            const uint64_t ad = mk_desc(sbase + OFF_A0 + st * 16384);
            const uint64_t bd = mk_desc(sbase + OFF_B0 + st * (TC_BN * 128));
            #pragma unroll
            for (int s = 0; s < 4; s++)
                tc_mma_tf32_ss(tmem, ad + 2 * s, bd + 2 * s, TC_IDESC,
                               (kt > 0 || s > 0) ? 1u : 0u);
            TC_COMMIT((kt & 1) ? mb1 : mb0);
        }
        if (kt >= 1) {
            if ((kt - 1) & 1) { MBAR_WAIT(mb1, pw1 & 1); pw1++; }
            else              { MBAR_WAIT(mb0, pw0 & 1); pw0++; }
        }
        if (kt + 3 < KT) {
            loadA((kt + 3) & 3, (kt + 3) * 32);
            loadB((kt + 3) & 3, (kt + 3) * 32);
        }
        CPA_COMMIT();
    }
    if ((KT - 1) & 1) { MBAR_WAIT(mb1, pw1 & 1); }
    else              { MBAR_WAIT(mb0, pw0 & 1); }
    TC_FENCE_AFTER();

    const int row = m0 + (warp & 3) * 32 + lane;
    const int ch0 = (warp >> 2) * 96;
    #pragma unroll
    for (int cc = 0; cc < 96; cc += 32) {
        const int c0 = ch0 + cc;
        uint32_t dr[32];
        TC_LD32(dr, tmem + c0);
        TC_WAIT_LD();
        #pragma unroll
        for (int j = 0; j < 32; j += 4) {
            const int c = n0 + c0 + j;
            float v0 = __uint_as_float(dr[j])     + bias[c];
            float v1 = __uint_as_float(dr[j + 1]) + bias[c + 1];
            float v2 = __uint_as_float(dr[j + 2]) + bias[c + 2];
            float v3 = __uint_as_float(dr[j + 3]) + bias[c + 3];
            if (OUT_TF) {
                uint4 o = { f2tf(v0), f2tf(v1), f2tf(v2), f2tf(v3) };
                *(uint4*)((uint32_t*)Cout + (size_t)row * Ndim + c) = o;
            } else {
                float4 o = { v0, v1, v2, v3 };
                *(float4*)((float*)Cout + (size_t)row * Ndim + c) = o;
            }
        }
    }
    __syncthreads();
    if (warp == 0) TC_DEALLOC(tmem, 256);
#endif
}

// ===========================================================================
// tcgen05 fused attention v3b: pipelined, TWO mbarriers (deadlock fix).
// mbS  <- S-MMA commits only  (wait cursor jt BEFORE S(jt+1) is issued)
// mbPV <- PV-MMA commits only (wait cursor jt-1 BEFORE PV(jt) is issued)
// => completions never lead either cursor by 2: parity aliasing impossible.
// Everything else identical to v3: V pre-transposed, K/VT double-buffered,
// S(j+1) issued before softmax(j) so tensor work overlaps MUFU.
// TMEM: O 0-63, S0 64-127, S1 128-191 (alloc 256; 2 CTAs/SM = 512).
// ===========================================================================
#define AT3_Q   1024
#define AT3_K0  (AT3_Q  + 32768)
#define AT3_K1  (AT3_K0 + 16384)
#define AT3_V0  (AT3_K1 + 16384)
#define AT3_V1  (AT3_V0 + 16384)
#define AT3_SMEM (AT3_V1 + 16384)
#if HAS_TCGEN05
#define AT_IDESC ((1u<<4) | (2u<<7) | (2u<<10) | (8u<<17) | (8u<<24))
__device__ __forceinline__ uint32_t blk_off(int r, int cb, int atomrows) {
    const uint32_t local = (uint32_t)(((r & 7) << 7) | (cb & 127));
    const uint32_t atom = (uint32_t)((r >> 3) + ((cb >> 7) * atomrows));
    return (atom << 10) + SWZ128(local);
}
#endif

__global__ __launch_bounds__(128) void attn_tc(
    const uint32_t* __restrict__ qkv, const uint32_t* __restrict__ vt,
    uint32_t* __restrict__ outp)
{
#if HAS_TCGEN05
    extern __shared__ char smem[];
    const uint32_t sbase = smaddr(smem);
    const int t = threadIdx.x, lane = t & 31, warp = t >> 5;
    const int bh = blockIdx.y, b = bh / NH, h = bh % NH;
    const int q0 = blockIdx.x * 128;
    const uint32_t mbS = sbase + 8, mbPV = sbase + 16;
    const uint32_t woff = (uint32_t)warp << 21;

    const uint32_t* Qg = qkv + (size_t)b * SEQ * QKVN + h * HDIM;
    const uint32_t* Kg = Qg + NH * HDIM;
    const uint32_t* Vt = vt + (size_t)bh * HDIM * SEQ;   // [d][seq]

    if (warp == 0) { TC_ALLOC(sbase, 256); TC_RELINQ(); }
    if (t == 0) { MBAR_INIT(mbS, 1); MBAR_INIT(mbPV, 1); }
    __syncthreads();
    uint32_t tmem;
    asm volatile("ld.shared.b32 %0, [%1];" : "=r"(tmem) : "r"(sbase));
    const uint32_t tO = tmem;
    const uint32_t tSb[2] = { tmem + 64, tmem + 128 };
    const uint32_t KST[2] = { sbase + AT3_K0, sbase + AT3_K1 };
    const uint32_t VST[2] = { sbase + AT3_V0, sbase + AT3_V1 };

    auto loadK = [&](int st, int j0) {   // 64 rows x 256B from g_qkv
        #pragma unroll
        for (int i = 0; i < 8; i++) {
            const int c = t + 128 * i, row = c >> 4, cb = (c & 15) * 16;
            cpa16(KST[st] + blk_off(row, cb, 8),
                  Kg + (size_t)(j0 + row) * QKVN + (cb >> 2));
        }
    };
    auto loadV = [&](int st, int j0) {   // 64 d-rows x 256B window from g_vt
        #pragma unroll
        for (int i = 0; i < 8; i++) {
            const int c = t + 128 * i, row = c >> 4, cb = (c & 15) * 16;
            cpa16(VST[st] + blk_off(row, cb, 8),
                  Vt + (size_t)row * SEQ + j0 + (cb >> 2));
        }
    };

    // prologue: group0 = Q + K(0) + VT(0); group1 = K(1)
    #pragma unroll
    for (int i = 0; i < 16; i++) {
        const int c = t + 128 * i, row = c >> 4, cb = (c & 15) * 16;
        cpa16(sbase + AT3_Q + blk_off(row, cb, 16),
              Qg + (size_t)(q0 + row) * QKVN + (cb >> 2));
    }
    loadK(0, 0); loadV(0, 0); CPA_COMMIT();
    loadK(1, 64); CPA_COMMIT();

    const uint64_t qdesc = mk_desc(sbase + AT3_Q);
    const uint32_t QSTEP[8] = {0, 2, 4, 6, 1024, 1026, 1028, 1030};
    const uint32_t KSTEP[8] = {0, 2, 4, 6, 512, 514, 516, 518};

    CPA_WAIT1();
    asm volatile("fence.proxy.async.shared::cta;" ::: "memory");
    __syncthreads();
    if (warp == 0 && elect_one_pred()) {   // S(0) -> mbS
        const uint64_t kd = mk_desc(KST[0]);
        #pragma unroll
        for (int s = 0; s < 8; s++)
            tc_mma_tf32_ss(tSb[0], qdesc + QSTEP[s], kd + KSTEP[s],
                           AT_IDESC, s > 0 ? 1u : 0u);
        TC_COMMIT(mbS);
    }

    const int r0 = warp * 32 + lane;       // this thread's q-row
    float l = 0.f;
    const float scale = 0.125f;

    for (int jt = 0; jt < 16; jt++) {
        // wait S(jt) on mbS (cursor jt); S(jt+1) not yet issued -> no aliasing
        MBAR_WAIT(mbS, jt & 1);
        // wait PV(jt-1) on mbPV (cursor jt-1); PV(jt) not yet issued
        if (jt > 0) MBAR_WAIT(mbPV, (jt - 1) & 1);
        TC_FENCE_AFTER();

        // prefetch: K(jt+2) -> stage jt&1 (old reader S(jt): waited);
        //           VT(jt+1) -> stage (jt+1)&1 (old reader PV(jt-1): waited)
        if (jt + 2 < 16) loadK(jt & 1, (jt + 2) * 64);
        if (jt + 1 < 16) loadV((jt + 1) & 1, (jt + 1) * 64);
        CPA_COMMIT();
        CPA_WAIT1();   // completes prior iter's group: K(jt+1), VT(jt)
        asm volatile("fence.proxy.async.shared::cta;" ::: "memory");
        __syncthreads();

        // issue S(jt+1) NOW -> tensor pipe works during softmax(jt)
        if (jt + 1 < 16 && warp == 0 && elect_one_pred()) {
            const uint64_t kd = mk_desc(KST[(jt + 1) & 1]);
            #pragma unroll
            for (int s = 0; s < 8; s++)
                tc_mma_tf32_ss(tSb[(jt + 1) & 1], qdesc + QSTEP[s],
                               kd + KSTEP[s], AT_IDESC, s > 0 ? 1u : 0u);
            TC_COMMIT(mbS);
        }

        // softmax(jt): thread owns q-row r0, 64 scores
        const uint32_t tS = tSb[jt & 1];
        float lsum = 0.f;
        {
            uint32_t sr[32];
            TC_LD32(sr, tS);
            TC_WAIT_LD();
            #pragma unroll
            for (int i = 0; i < 32; i++) {
                const float p = __expf(__uint_as_float(sr[i]) * scale);
                lsum += p;
                sr[i] = f2tf(p);
            }
            TC_ST32(tS + woff, sr);
            TC_LD32(sr, tS + 32);
            TC_WAIT_LD();
            #pragma unroll
            for (int i = 0; i < 32; i++) {
                const float p = __expf(__uint_as_float(sr[i]) * scale);
                lsum += p;
                sr[i] = f2tf(p);
            }
            TC_ST32(tS + 32 + woff, sr);
            TC_WAIT_ST();
        }
        l += lsum;
        TC_FENCE_BEFORE();
        __syncthreads();

        // PV(jt): A = P (TMEM), B = VT stage jt&1 -> mbPV
        if (warp == 0 && elect_one_pred()) {
            TC_FENCE_AFTER();
            const uint64_t vd = mk_desc(VST[jt & 1]);
            #pragma unroll
            for (int s = 0; s < 8; s++)
                tc_mma_tf32_ts(tO, tS + 8 * s, vd + KSTEP[s],
                               AT_IDESC, (jt > 0 || s > 0) ? 1u : 0u);
            TC_COMMIT(mbPV);
        }
    }

    // epilogue: wait PV(15) (mbPV cursor 15), normalize, store
    MBAR_WAIT(mbPV, 15 & 1);
    TC_FENCE_AFTER();
    const float inv = 1.0f / l;
    uint32_t* ob = outp + (size_t)(b * SEQ + q0 + r0) * PK + h * HDIM;
    {
        uint32_t orr[32];
        TC_LD32(orr, tO);
        TC_WAIT_LD();
        #pragma unroll
        for (int j = 0; j < 32; j += 4) {
            uint4 o = { f2tf(__uint_as_float(orr[j])     * inv),
                        f2tf(__uint_as_float(orr[j + 1]) * inv),
                        f2tf(__uint_as_float(orr[j + 2]) * inv),
                        f2tf(__uint_as_float(orr[j + 3]) * inv) };
            *(uint4*)(ob + j) = o;
        }
        TC_LD32(orr, tO + 32);
        TC_WAIT_LD();
        #pragma unroll
        for (int j = 0; j < 32; j += 4) {
            uint4 o = { f2tf(__uint_as_float(orr[j])     * inv),
                        f2tf(__uint_as_float(orr[j + 1]) * inv),
                        f2tf(__uint_as_float(orr[j + 2]) * inv),
                        f2tf(__uint_as_float(orr[j + 3]) * inv) };
            *(uint4*)(ob + 32 + j) = o;
        }
    }
    __syncthreads();
    if (warp == 0) TC_DEALLOC(tmem, 256);
#endif
}

// ===========================================================================
// Fallback attention (R6-proven mma.sync) — only in base-target stages.
// ===========================================================================
#define AT_KSTAGE (64 * 68)
#define AT_VSTAGE (64 * 72)
#define AT_SMEM_BYTES ((128 * 68 + 2 * AT_KSTAGE + 2 * AT_VSTAGE) * 4)

__global__ __launch_bounds__(256, 2) void attn_v2(
    const uint32_t* __restrict__ qkv, uint32_t* __restrict__ outp)
{
#if !HAS_TCGEN05
    extern __shared__ uint32_t sm[];
    uint32_t* Qs = sm;
    uint32_t* Ks = Qs + 128 * 68;
    uint32_t* Vs = Ks + 2 * AT_KSTAGE;

    const int t = threadIdx.x, lane = t & 31, warp = t >> 5;
    const int q = lane & 3, r8 = lane >> 2;
    const int bh = blockIdx.y, b = bh / NH, h = bh % NH;
    const int q0 = blockIdx.x * 128;
    const float scale = 0.125f;

    const uint32_t* Qg = qkv + (size_t)b * SEQ * QKVN + h * HDIM;
    const uint32_t* Kg = Qg + NH * HDIM;
    const uint32_t* Vg = Qg + 2 * NH * HDIM;
    const int r0 = warp * 16 + r8;
    const int c4 = (t & 15) * 4, rb = t >> 4;

    {
        #pragma unroll
        for (int i = 0; i < 8; i++) {
            const int r = rb + 16 * i;
            cpa16(smaddr(&Qs[r * 68 + c4]), Qg + (size_t)(q0 + r) * QKVN + c4);
        }
        #pragma unroll
        for (int i = 0; i < 4; i++) {
            const int r = rb + 16 * i;
            cpa16(smaddr(&Ks[r * 68 + c4]), Kg + (size_t)r * QKVN + c4);
            cpa16(smaddr(&Vs[r * 72 + c4]), Vg + (size_t)r * QKVN + c4);
        }
        CPA_COMMIT();
    }

    float O[8][4] = {};
    float m0 = -1e30f, m1 = -1e30f, l0 = 0.f, l1 = 0.f;
    const int src1 = (lane & 28) | (q >> 1);
    const int src2 = src1 | 2;

    for (int jt = 0; jt < SEQ / 64; jt++) {
        CPA_WAIT0();
        __syncthreads();
        if (jt + 1 < SEQ / 64) {
            const int s = (jt + 1) & 1;
            const int j0 = (jt + 1) * 64;
            #pragma unroll
            for (int i = 0; i < 4; i++) {
                const int r = rb + 16 * i;
                cpa16(smaddr(&Ks[s * AT_KSTAGE + r * 68 + c4]),
                      Kg + (size_t)(j0 + r) * QKVN + c4);
                cpa16(smaddr(&Vs[s * AT_VSTAGE + r * 72 + c4]),
                      Vg + (size_t)(j0 + r) * QKVN + c4);
            }
            CPA_COMMIT();
        }
        const uint32_t* Kst = Ks + (jt & 1) * AT_KSTAGE;
        const uint32_t* Vst = Vs + (jt & 1) * AT_VSTAGE;

        float s[8][4] = {};
        #pragma unroll
        for (int kc = 0; kc < 8; kc++) {
            const int kb = kc * 8 + q;
            uint32_t a[4];
            a[0] = Qs[r0 * 68 + kb];     a[1] = Qs[(r0 + 8) * 68 + kb];
            a[2] = Qs[r0 * 68 + kb + 4]; a[3] = Qs[(r0 + 8) * 68 + kb + 4];
            #pragma unroll
            for (int ni = 0; ni < 8; ni++) {
                const int n = ni * 8 + r8;
                mma_tf32(s[ni], a, Kst[n * 68 + kb], Kst[n * 68 + kb + 4]);
            }
        }

        float mx0 = -1e30f, mx1 = -1e30f;
        #pragma unroll
        for (int ni = 0; ni < 8; ni++) {
            s[ni][0] *= scale; s[ni][1] *= scale;
            s[ni][2] *= scale; s[ni][3] *= scale;
            mx0 = fmaxf(mx0, fmaxf(s[ni][0], s[ni][1]));
            mx1 = fmaxf(mx1, fmaxf(s[ni][2], s[ni][3]));
        }
        mx0 = fmaxf(mx0, __shfl_xor_sync(0xffffffffu, mx0, 1));
        mx0 = fmaxf(mx0, __shfl_xor_sync(0xffffffffu, mx0, 2));
        mx1 = fmaxf(mx1, __shfl_xor_sync(0xffffffffu, mx1, 1));
        mx1 = fmaxf(mx1, __shfl_xor_sync(0xffffffffu, mx1, 2));
        const float mn0 = fmaxf(m0, mx0), mn1 = fmaxf(m1, mx1);
        const float al0 = __expf(m0 - mn0), al1 = __expf(m1 - mn1);
        m0 = mn0; m1 = mn1;
        float sum0 = 0.f, sum1 = 0.f;
        #pragma unroll
        for (int ni = 0; ni < 8; ni++) {
            s[ni][0] = __expf(s[ni][0] - mn0); sum0 += s[ni][0];
            s[ni][1] = __expf(s[ni][1] - mn0); sum0 += s[ni][1];
            s[ni][2] = __expf(s[ni][2] - mn1); sum1 += s[ni][2];
            s[ni][3] = __expf(s[ni][3] - mn1); sum1 += s[ni][3];
        }
        sum0 += __shfl_xor_sync(0xffffffffu, sum0, 1);
        sum0 += __shfl_xor_sync(0xffffffffu, sum0, 2);
        sum1 += __shfl_xor_sync(0xffffffffu, sum1, 1);
        sum1 += __shfl_xor_sync(0xffffffffu, sum1, 2);
        l0 = l0 * al0 + sum0;
        l1 = l1 * al1 + sum1;
        #pragma unroll
        for (int ni = 0; ni < 8; ni++) {
            O[ni][0] *= al0; O[ni][1] *= al0;
            O[ni][2] *= al1; O[ni][3] *= al1;
        }

        #pragma unroll
        for (int kc = 0; kc < 8; kc++) {
            const float v0 = __shfl_sync(0xffffffffu, s[kc][0], src1);
            const float v1 = __shfl_sync(0xffffffffu, s[kc][1], src1);
            const float v2 = __shfl_sync(0xffffffffu, s[kc][2], src1);
            const float v3 = __shfl_sync(0xffffffffu, s[kc][3], src1);
            const float w0 = __shfl_sync(0xffffffffu, s[kc][0], src2);
            const float w1 = __shfl_sync(0xffffffffu, s[kc][1], src2);
            const float w2 = __shfl_sync(0xffffffffu, s[kc][2], src2);
            const float w3 = __shfl_sync(0xffffffffu, s[kc][3], src2);
            const bool odd = (q & 1);
            uint32_t a[4];
            a[0] = f2tf(odd ? v1 : v0);
            a[1] = f2tf(odd ? v3 : v2);
            a[2] = f2tf(odd ? w1 : w0);
            a[3] = f2tf(odd ? w3 : w2);
            const int kb = kc * 8 + q;
            #pragma unroll
            for (int ni = 0; ni < 8; ni++) {
                const int dv = ni * 8 + r8;
                mma_tf32(O[ni], a, Vst[kb * 72 + dv], Vst[(kb + 4) * 72 + dv]);
            }
        }
    }

    const float inv0 = 1.0f / l0, inv1 = 1.0f / l1;
    uint32_t* ob = outp + (size_t)(b * SEQ + q0) * PK + h * HDIM;
    #pragma unroll
    for (int ni = 0; ni < 8; ni++) {
        const int c = ni * 8 + 2 * q;
        uint2 o0 = { f2tf(O[ni][0] * inv0), f2tf(O[ni][1] * inv0) };
        uint2 o1 = { f2tf(O[ni][2] * inv1), f2tf(O[ni][3] * inv1) };
        *(uint2*)(ob + (size_t)r0 * PK + c)       = o0;
        *(uint2*)(ob + (size_t)(r0 + 8) * PK + c) = o1;
    }
#endif
}

// ===========================================================================
// Fallback GEMM (R6-proven mma.sync) — only in base-target stages.
// ===========================================================================
#define G_ASTRIDE 36
#define G_ASTAGE  (256 * G_ASTRIDE)
#define G_BSTAGE  (64 * G_ASTRIDE)
#define G_SMEM_BYTES ((2 * G_ASTAGE + 2 * G_BSTAGE) * 4)

template <bool OUT_TF>
__global__ __launch_bounds__(256, 2) void gemm_fb(
    const uint32_t* __restrict__ A, const uint32_t* __restrict__ W,
    const float* __restrict__ bias, void* __restrict__ Cout,
    int Kdim, int Ndim)
{
#if !HAS_TCGEN05
    extern __shared__ uint32_t dsm[];
    uint32_t* As = dsm;
    uint32_t* Bs = dsm + 2 * G_ASTAGE;

    const int t = threadIdx.x, lane = t & 31, warp = t >> 5;
    const int wm = warp >> 1, wn = warp & 1;
    const int q = lane & 3, r8 = lane >> 2;
    const int m0 = blockIdx.y * 256, n0 = blockIdx.x * 64;
    const int lr = t >> 3, lc4 = (t & 7) * 4;
    const int KT = Kdim >> 5;

    float acc[16][4] = {};

    const uint32_t* Ag = A + (size_t)(m0 + lr) * Kdim + lc4;
    const uint32_t* Wg = W + (size_t)(n0 + lr) * Kdim + lc4;

    {
        #pragma unroll
        for (int i = 0; i < 8; i++)
            cpa16(smaddr(&As[(lr + 32 * i) * G_ASTRIDE + lc4]),
                  Ag + (size_t)(32 * i) * Kdim);
        #pragma unroll
        for (int i = 0; i < 2; i++)
            cpa16(smaddr(&Bs[(lr + 32 * i) * G_ASTRIDE + lc4]),
                  Wg + (size_t)(32 * i) * Kdim);
        CPA_COMMIT();
    }

    for (int kt = 0; kt < KT; kt++) {
        CPA_WAIT0();
        __syncthreads();
        if (kt + 1 < KT) {
            const int s = (kt + 1) & 1;
            const int k0 = (kt + 1) << 5;
            #pragma unroll
            for (int i = 0; i < 8; i++)
                cpa16(smaddr(&As[s * G_ASTAGE + (lr + 32 * i) * G_ASTRIDE + lc4]),
                      Ag + (size_t)(32 * i) * Kdim + k0);
            #pragma unroll
            for (int i = 0; i < 2; i++)
                cpa16(smaddr(&Bs[s * G_BSTAGE + (lr + 32 * i) * G_ASTRIDE + lc4]),
                      Wg + (size_t)(32 * i) * Kdim + k0);
            CPA_COMMIT();
        }
        const uint32_t* Ast = As + (kt & 1) * G_ASTAGE;
        const uint32_t* Bst = Bs + (kt & 1) * G_BSTAGE;
        #pragma unroll
        for (int kc = 0; kc < 4; kc++) {
            const int kb = kc * 8 + q;
            uint32_t a[4][4];
            #pragma unroll
            for (int mi = 0; mi < 4; mi++) {
                const int r = wm * 64 + mi * 16 + r8;
                a[mi][0] = Ast[r * G_ASTRIDE + kb];
                a[mi][1] = Ast[(r + 8) * G_ASTRIDE + kb];
                a[mi][2] = Ast[r * G_ASTRIDE + kb + 4];
                a[mi][3] = Ast[(r + 8) * G_ASTRIDE + kb + 4];
            }
            #pragma unroll
            for (int ni = 0; ni < 4; ni++) {
                const int n = wn * 32 + ni * 8 + r8;
                const uint32_t b0 = Bst[n * G_ASTRIDE + kb];
                const uint32_t b1 = Bst[n * G_ASTRIDE + kb + 4];
                #pragma unroll
                for (int mi = 0; mi < 4; mi++)
                    mma_tf32(acc[mi * 4 + ni], a[mi], b0, b1);
            }
        }
    }

    #pragma unroll
    for (int mi = 0; mi < 4; mi++)
        #pragma unroll
        for (int ni = 0; ni < 4; ni++) {
            const float* d = acc[mi * 4 + ni];
            const int r0g = m0 + wm * 64 + mi * 16 + r8;
            const int c   = n0 + wn * 32 + ni * 8 + 2 * q;
            const float bx = bias[c], by = bias[c + 1];
            if (OUT_TF) {
                uint32_t* C = (uint32_t*)Cout;
                uint2 o0 = { f2tf(d[0] + bx), f2tf(d[1] + by) };
                uint2 o1 = { f2tf(d[2] + bx), f2tf(d[3] + by) };
                *(uint2*)(C + (size_t)r0g * Ndim + c)       = o0;
                *(uint2*)(C + (size_t)(r0g + 8) * Ndim + c) = o1;
            } else {
                float* C = (float*)Cout;
                float2 o0 = { d[0] + bx, d[1] + by };
                float2 o1 = { d[2] + bx, d[3] + by };
                *(float2*)(C + (size_t)r0g * Ndim + c)       = o0;
                *(float2*)(C + (size_t)(r0g + 8) * Ndim + c) = o1;
            }
        }
#endif
}

// ---------------------------------------------------------------------------
extern "C" void kernel_launch(void* const* d_in, const int* in_sizes, int n_in,
                              void* d_out, int out_size)
{
    const float* x      = (const float*)d_in[0];
    const float* qkv_w  = (const float*)d_in[1];
    const float* qkv_b  = (const float*)d_in[2];
    const float* proj_w = (const float*)d_in[3];
    const float* proj_b = (const float*)d_in[4];
    float* outp = (float*)d_out;

    uint32_t *x_tf, *qw_tf, *pw_tf, *qkv, *vt, *attn;
    cudaGetSymbolAddress((void**)&x_tf,  g_x_tf);
    cudaGetSymbolAddress((void**)&qw_tf, g_qw_tf);
    cudaGetSymbolAddress((void**)&pw_tf, g_pw_tf);
    cudaGetSymbolAddress((void**)&qkv,   g_qkv);
    cudaGetSymbolAddress((void**)&vt,    g_vt);
    cudaGetSymbolAddress((void**)&attn,  g_attn);

    // 0) Pre-convert inputs to tf32 bits
    {
        const int nx = MTOT * CDIM / 4, nw = QKVN * CDIM / 4, np = CDIM * PK / 4;
        cvt_tf32_kernel<<<(nx + 255) / 256, 256>>>((const float4*)x,      (uint4*)x_tf,  nx);
        cvt_tf32_kernel<<<(nw + 255) / 256, 256>>>((const float4*)qkv_w,  (uint4*)qw_tf, nw);
        cvt_tf32_kernel<<<(np + 255) / 256, 256>>>((const float4*)proj_w, (uint4*)pw_tf, np);
    }

    cudaFuncSetAttribute(gemm_tc<true>,  cudaFuncAttributeMaxDynamicSharedMemorySize, TC_SMEM);
    cudaFuncSetAttribute(gemm_tc<false>, cudaFuncAttributeMaxDynamicSharedMemorySize, TC_SMEM);
    cudaFuncSetAttribute(gemm_fb<true>,  cudaFuncAttributeMaxDynamicSharedMemorySize, G_SMEM_BYTES);
    cudaFuncSetAttribute(gemm_fb<false>, cudaFuncAttributeMaxDynamicSharedMemorySize, G_SMEM_BYTES);
    cudaFuncSetAttribute(attn_tc, cudaFuncAttributeMaxDynamicSharedMemorySize, AT3_SMEM);
    cudaFuncSetAttribute(attn_v2, cudaFuncAttributeMaxDynamicSharedMemorySize, AT_SMEM_BYTES);

    // 1) QKV projection -> tf32 bits (exactly one path does work)
    gemm_tc<true><<<dim3(QKVN / TC_BN, MTOT / 128), 256, TC_SMEM>>>(
        x_tf, qw_tf, qkv_b, qkv, CDIM, QKVN);
    gemm_fb<true><<<dim3(QKVN / 64, MTOT / 256), 256, G_SMEM_BYTES>>>(
        x_tf, qw_tf, qkv_b, qkv, CDIM, QKVN);

    // 1b) Transpose V for the tcgen05 attention's B operand
    transpose_v_kernel<<<dim3(SEQ / 32, HDIM / 32, BDIM * NH), dim3(32, 8)>>>(qkv, vt);

    // 2) Fused attention -> tf32 bits (exactly one path does work)
    attn_tc<<<dim3(SEQ / 128, BDIM * NH), 128, AT3_SMEM>>>(qkv, vt, attn);
    attn_v2<<<dim3(SEQ / 128, BDIM * NH), 256, AT_SMEM_BYTES>>>(qkv, attn);

    // 3) Output projection -> fp32 (exactly one path does work)
    gemm_tc<false><<<dim3(CDIM / TC_BN, MTOT / 128), 256, TC_SMEM>>>(
        attn, pw_tf, proj_b, outp, PK, CDIM);
    gemm_fb<false><<<dim3(CDIM / 64, MTOT / 256), 256, G_SMEM_BYTES>>>(
        attn, pw_tf, proj_b, outp, PK, CDIM);
}

// round 13
// speedup vs baseline: 1.4966x; 1.4966x over previous
#include <cuda_runtime.h>
#include <cstdint>

#define BDIM 16
#define SEQ  1024
#define CDIM 768
#define NH   9
#define HDIM 64
#define MTOT (BDIM*SEQ)        // 16384
#define QKVN (3*NH*HDIM)       // 1728
#define PK   (NH*HDIM)         // 576

// Does THIS device-compile stage support tcgen05 (arch-/family-specific target)?
#if defined(__CUDA_ARCH__)
#  if defined(__CUDA_ARCH_FEAT_SM103_ALL) || defined(__CUDA_ARCH_FEAT_SM100_ALL) || \
      (defined(__CUDA_ARCH_FAMILY_SPECIFIC__) && (__CUDA_ARCH_FAMILY_SPECIFIC__ >= 1000))
#    define HAS_TCGEN05 1
#  else
#    define HAS_TCGEN05 0
#  endif
#else
#  define HAS_TCGEN05 0
#endif

// Scratch (device globals: allocation-free per harness rules). tf32 bit patterns.
__device__ uint32_t g_x_tf[(size_t)MTOT * CDIM];
__device__ uint32_t g_qw_tf[(size_t)QKVN * CDIM];
__device__ uint32_t g_pw_tf[(size_t)CDIM * PK];
__device__ uint32_t g_qkv[(size_t)MTOT * QKVN];
__device__ uint32_t g_vt[(size_t)BDIM * NH * HDIM * SEQ];   // V^T [b,h,d,seq]
__device__ uint32_t g_attn[(size_t)MTOT * PK];

__device__ __forceinline__ uint32_t f2tf(float f) {
    uint32_t u;
    asm("cvt.rna.tf32.f32 %0, %1;" : "=r"(u) : "f"(f));
    return u;
}
__device__ __forceinline__ void mma_tf32(float* d, const uint32_t* a,
                                         uint32_t b0, uint32_t b1) {
    asm volatile(
        "mma.sync.aligned.m16n8k8.row.col.f32.tf32.tf32.f32 "
        "{%0,%1,%2,%3},{%4,%5,%6,%7},{%8,%9},{%0,%1,%2,%3};\n"
        : "+f"(d[0]), "+f"(d[1]), "+f"(d[2]), "+f"(d[3])
        : "r"(a[0]), "r"(a[1]), "r"(a[2]), "r"(a[3]), "r"(b0), "r"(b1));
}
__device__ __forceinline__ uint32_t smaddr(const void* p) {
    return (uint32_t)__cvta_generic_to_shared(p);
}
__device__ __forceinline__ void cpa16(uint32_t s, const void* g) {
    asm volatile("cp.async.cg.shared.global [%0], [%1], 16;" :: "r"(s), "l"(g));
}
#define CPA_COMMIT() asm volatile("cp.async.commit_group;")
#define CPA_WAIT0()  asm volatile("cp.async.wait_group 0;")
#define CPA_WAIT1()  asm volatile("cp.async.wait_group 1;")
#define CPA_WAIT2()  asm volatile("cp.async.wait_group 2;")
#define SWZ128(x) ((x) ^ (((x) >> 3) & 0x70))

// ---------------------------------------------------------------------------
__global__ void cvt_tf32_kernel(const float4* __restrict__ in,
                                uint4* __restrict__ out, int n4) {
    const int i = blockIdx.x * blockDim.x + threadIdx.x;
    if (i < n4) {
        float4 v = in[i];
        uint4 o = { f2tf(v.x), f2tf(v.y), f2tf(v.z), f2tf(v.w) };
        out[i] = o;
    }
}

// V transpose: g_qkv[token][1152 + h*64 + d] -> g_vt[(bh*64+d)*SEQ + n]
__global__ void transpose_v_kernel(const uint32_t* __restrict__ qkv,
                                   uint32_t* __restrict__ vt) {
    __shared__ uint32_t tile[32][33];
    const int bh = blockIdx.z, b = bh / NH, h = bh % NH;
    const int n0 = blockIdx.x * 32, d0 = blockIdx.y * 32;
    const int tx = threadIdx.x, ty = threadIdx.y;
    #pragma unroll
    for (int i = ty; i < 32; i += 8)
        tile[i][tx] = qkv[(size_t)(b * SEQ + n0 + i) * QKVN
                          + 2 * NH * HDIM + h * HDIM + d0 + tx];
    __syncthreads();
    #pragma unroll
    for (int i = ty; i < 32; i += 8)
        vt[((size_t)bh * HDIM + d0 + i) * SEQ + n0 + tx] = tile[tx][i];
}

#if HAS_TCGEN05
__device__ __forceinline__ uint32_t elect_one_pred() {
    uint32_t pred;
    asm volatile("{\n\t.reg .pred p;\n\telect.sync _|p, 0xFFFFFFFF;\n\t"
                 "selp.b32 %0, 1, 0, p;\n\t}" : "=r"(pred));
    return pred;
}
#define TC_ALLOC(sm_res, n) \
    asm volatile("tcgen05.alloc.cta_group::1.sync.aligned.shared::cta.b32 [%0], %1;" \
                 :: "r"((uint32_t)(sm_res)), "r"((uint32_t)(n)) : "memory")
#define TC_RELINQ() \
    asm volatile("tcgen05.relinquish_alloc_permit.cta_group::1.sync.aligned;")
#define TC_DEALLOC(tm, n) \
    asm volatile("tcgen05.dealloc.cta_group::1.sync.aligned.b32 %0, %1;" :: "r"(tm), "r"((uint32_t)(n)))
#define TC_COMMIT(mb) \
    asm volatile("tcgen05.commit.cta_group::1.mbarrier::arrive::one.shared::cluster.b64 [%0];" \
                 :: "r"((uint32_t)(mb)) : "memory")
#define TC_FENCE_AFTER()  asm volatile("tcgen05.fence::after_thread_sync;" ::: "memory")
#define TC_FENCE_BEFORE() asm volatile("tcgen05.fence::before_thread_sync;" ::: "memory")
#define TC_WAIT_LD() asm volatile("tcgen05.wait::ld.sync.aligned;" ::: "memory")
#define TC_WAIT_ST() asm volatile("tcgen05.wait::st.sync.aligned;" ::: "memory")
#define MBAR_INIT(mb, c) \
    asm volatile("mbarrier.init.shared.b64 [%0], %1;" :: "r"((uint32_t)(mb)), "r"((uint32_t)(c)) : "memory")
#define MBAR_WAIT(mb, par) do { \
    uint32_t _m = (uint32_t)(mb), _p = (uint32_t)(par), _d; \
    asm volatile("{\n\t.reg .pred p;\n\t" \
        "mbarrier.try_wait.parity.acquire.cta.shared::cta.b64 p, [%1], %2;\n\t" \
        "selp.b32 %0, 1, 0, p;\n\t}" : "=r"(_d) : "r"(_m), "r"(_p) : "memory"); \
    if (!_d) { \
        asm volatile("{\n\t.reg .pred P1;\n\tWL_%=:\n\t" \
            "mbarrier.try_wait.parity.acquire.cta.shared::cta.b64 P1, [%0], %1, 0x989680;\n\t" \
            "@P1 bra.uni WD_%=;\n\tbra.uni WL_%=;\n\tWD_%=:\n\t}" \
            :: "r"(_m), "r"(_p) : "memory"); \
    } } while (0)

__device__ __forceinline__ void tc_mma_tf32_ss(uint32_t d_tmem, uint64_t ad,
                                               uint64_t bd, uint32_t idesc,
                                               uint32_t en) {
    asm volatile(
        "{\n\t.reg .pred p;\n\tsetp.ne.u32 p, %4, 0;\n\t"
        "tcgen05.mma.cta_group::1.kind::tf32 [%0], %1, %2, %3, p;\n\t}"
        :: "r"(d_tmem), "l"(ad), "l"(bd), "r"(idesc), "r"(en) : "memory");
}
__device__ __forceinline__ void tc_mma_tf32_ts(uint32_t d_tmem, uint32_t a_tmem,
                                               uint64_t bd, uint32_t idesc,
                                               uint32_t en) {
    asm volatile(
        "{\n\t.reg .pred p;\n\tsetp.ne.u32 p, %4, 0;\n\t"
        "tcgen05.mma.cta_group::1.kind::tf32 [%0], [%1], %2, %3, p;\n\t}"
        :: "r"(d_tmem), "r"(a_tmem), "l"(bd), "r"(idesc), "r"(en) : "memory");
}
#define TC_LD32(r, ta) \
    asm volatile( \
        "tcgen05.ld.sync.aligned.32x32b.x32.b32 " \
        "{%0,%1,%2,%3,%4,%5,%6,%7,%8,%9,%10,%11,%12,%13,%14,%15," \
        "%16,%17,%18,%19,%20,%21,%22,%23,%24,%25,%26,%27,%28,%29,%30,%31},[%32];" \
        : "=r"((r)[0]), "=r"((r)[1]), "=r"((r)[2]), "=r"((r)[3]), "=r"((r)[4]), \
          "=r"((r)[5]), "=r"((r)[6]), "=r"((r)[7]), "=r"((r)[8]), "=r"((r)[9]), \
          "=r"((r)[10]), "=r"((r)[11]), "=r"((r)[12]), "=r"((r)[13]), "=r"((r)[14]), \
          "=r"((r)[15]), "=r"((r)[16]), "=r"((r)[17]), "=r"((r)[18]), "=r"((r)[19]), \
          "=r"((r)[20]), "=r"((r)[21]), "=r"((r)[22]), "=r"((r)[23]), "=r"((r)[24]), \
          "=r"((r)[25]), "=r"((r)[26]), "=r"((r)[27]), "=r"((r)[28]), "=r"((r)[29]), \
          "=r"((r)[30]), "=r"((r)[31]) \
        : "r"(ta))
#define TC_ST32(ta, r) \
    asm volatile( \
        "tcgen05.st.sync.aligned.32x32b.x32.b32 [%0], " \
        "{%1,%2,%3,%4,%5,%6,%7,%8,%9,%10,%11,%12,%13,%14,%15,%16," \
        "%17,%18,%19,%20,%21,%22,%23,%24,%25,%26,%27,%28,%29,%30,%31,%32};" \
        :: "r"(ta), \
           "r"((r)[0]), "r"((r)[1]), "r"((r)[2]), "r"((r)[3]), "r"((r)[4]), \
           "r"((r)[5]), "r"((r)[6]), "r"((r)[7]), "r"((r)[8]), "r"((r)[9]), \
           "r"((r)[10]), "r"((r)[11]), "r"((r)[12]), "r"((r)[13]), "r"((r)[14]), \
           "r"((r)[15]), "r"((r)[16]), "r"((r)[17]), "r"((r)[18]), "r"((r)[19]), \
           "r"((r)[20]), "r"((r)[21]), "r"((r)[22]), "r"((r)[23]), "r"((r)[24]), \
           "r"((r)[25]), "r"((r)[26]), "r"((r)[27]), "r"((r)[28]), "r"((r)[29]), \
           "r"((r)[30]), "r"((r)[31]) \
        : "memory")
__device__ __forceinline__ uint64_t mk_desc(uint32_t addr) {
    return ((uint64_t)2 << 61) | ((uint64_t)1 << 46) | ((uint64_t)64 << 32)
         | ((uint64_t)1 << 16) | (uint64_t)((addr >> 4) & 0x3FFF);
}
#endif // HAS_TCGEN05

// ===========================================================================
// tcgen05 tf32 GEMM (R8/R9-proven, frozen), 4-stage cp.async, 256 threads.
// ===========================================================================
#define TC_BN 192
#define OFF_A0 1024
#define OFF_B0 (OFF_A0 + 4*16384)
#define TC_SMEM (OFF_B0 + 4*(TC_BN*128))
#if HAS_TCGEN05
#define TC_IDESC ((1u<<4) | (2u<<7) | (2u<<10) | ((TC_BN/8)<<17) | (8u<<24))
#endif

template <bool OUT_TF>
__global__ __launch_bounds__(256) void gemm_tc(
    const uint32_t* __restrict__ A, const uint32_t* __restrict__ W,
    const float* __restrict__ bias, void* __restrict__ Cout,
    int Kdim, int Ndim)
{
#if HAS_TCGEN05
    extern __shared__ char smem[];
    const uint32_t sbase = smaddr(smem);
    const int t = threadIdx.x, lane = t & 31, warp = t >> 5;
    const int m0 = blockIdx.y * 128, n0 = blockIdx.x * TC_BN;
    const uint32_t mb0 = sbase + 8, mb1 = sbase + 16;

    if (warp == 0) { TC_ALLOC(sbase, 256); TC_RELINQ(); }
    if (t == 0) { MBAR_INIT(mb0, 1); MBAR_INIT(mb1, 1); }
    __syncthreads();
    uint32_t tmem;
    asm volatile("ld.shared.b32 %0, [%1];" : "=r"(tmem) : "r"(sbase));

    const int KT = Kdim >> 5;

    auto loadA = [&](int st, int k0) {
        const uint32_t base = sbase + OFF_A0 + st * 16384;
        #pragma unroll
        for (int i = 0; i < 4; i++) {
            const int idx = t + 256 * i, row = idx >> 3, ch = idx & 7;
            cpa16(base + SWZ128((uint32_t)(row * 128 + ch * 16)),
                  A + (size_t)(m0 + row) * Kdim + k0 + ch * 4);
        }
    };
    auto loadB = [&](int st, int k0) {
        const uint32_t base = sbase + OFF_B0 + st * (TC_BN * 128);
        #pragma unroll
        for (int i = 0; i < 6; i++) {
            const int idx = t + 256 * i, row = idx >> 3, ch = idx & 7;
            cpa16(base + SWZ128((uint32_t)(row * 128 + ch * 16)),
                  W + (size_t)(n0 + row) * Kdim + k0 + ch * 4);
        }
    };

    #pragma unroll
    for (int p = 0; p < 3; p++) {
        loadA(p, p * 32); loadB(p, p * 32); CPA_COMMIT();
    }
    int pw0 = 0, pw1 = 0;

    for (int kt = 0; kt < KT; kt++) {
        CPA_WAIT2();
        asm volatile("fence.proxy.async.shared::cta;" ::: "memory");
        __syncthreads();
        if (warp == 0 && elect_one_pred()) {
            const int st = kt & 3;
            const uint64_t ad = mk_desc(sbase + OFF_A0 + st * 16384);
            const uint64_t bd = mk_desc(sbase + OFF_B0 + st * (TC_BN * 128));
            #pragma unroll
            for (int s = 0; s < 4; s++)
                tc_mma_tf32_ss(tmem, ad + 2 * s, bd + 2 * s, TC_IDESC,
                               (kt > 0 || s > 0) ? 1u : 0u);
            TC_COMMIT((kt & 1) ? mb1 : mb0);
        }
        if (kt >= 1) {
            if ((kt - 1) & 1) { MBAR_WAIT(mb1, pw1 & 1); pw1++; }
            else              { MBAR_WAIT(mb0, pw0 & 1); pw0++; }
        }
        if (kt + 3 < KT) {
            loadA((kt + 3) & 3, (kt + 3) * 32);
            loadB((kt + 3) & 3, (kt + 3) * 32);
        }
        CPA_COMMIT();
    }
    if ((KT - 1) & 1) { MBAR_WAIT(mb1, pw1 & 1); }
    else              { MBAR_WAIT(mb0, pw0 & 1); }
    TC_FENCE_AFTER();

    const int row = m0 + (warp & 3) * 32 + lane;
    const int ch0 = (warp >> 2) * 96;
    #pragma unroll
    for (int cc = 0; cc < 96; cc += 32) {
        const int c0 = ch0 + cc;
        uint32_t dr[32];
        TC_LD32(dr, tmem + c0);
        TC_WAIT_LD();
        #pragma unroll
        for (int j = 0; j < 32; j += 4) {
            const int c = n0 + c0 + j;
            float v0 = __uint_as_float(dr[j])     + bias[c];
            float v1 = __uint_as_float(dr[j + 1]) + bias[c + 1];
            float v2 = __uint_as_float(dr[j + 2]) + bias[c + 2];
            float v3 = __uint_as_float(dr[j + 3]) + bias[c + 3];
            if (OUT_TF) {
                uint4 o = { f2tf(v0), f2tf(v1), f2tf(v2), f2tf(v3) };
                *(uint4*)((uint32_t*)Cout + (size_t)row * Ndim + c) = o;
            } else {
                float4 o = { v0, v1, v2, v3 };
                *(float4*)((float*)Cout + (size_t)row * Ndim + c) = o;
            }
        }
    }
    __syncthreads();
    if (warp == 0) TC_DEALLOC(tmem, 256);
#endif
}

// ===========================================================================
// tcgen05 fused attention v4: serial MMA chain (R10-proven ordering, one
// commit+wait per iter on mbS -> k<=c+1, no parity aliasing), but with
// V pre-transposed and K/VT double-buffered cp.async prefetch (2/1 ahead).
// Tensor pipe and LDTM/STTM kept temporally disjoint (R12's overlap caused
// TMEM-port contention). PV completion implied by next S wait (in-order
// queue); PV commits a barrier only at jt=15 for the epilogue.
// TMEM: O 0-63, S0 64-127, S1 128-191 (alloc 256; 2 CTAs/SM = 512).
// ===========================================================================
#define AT3_Q   1024
#define AT3_K0  (AT3_Q  + 32768)
#define AT3_K1  (AT3_K0 + 16384)
#define AT3_V0  (AT3_K1 + 16384)
#define AT3_V1  (AT3_V0 + 16384)
#define AT3_SMEM (AT3_V1 + 16384)
#if HAS_TCGEN05
#define AT_IDESC ((1u<<4) | (2u<<7) | (2u<<10) | (8u<<17) | (8u<<24))
__device__ __forceinline__ uint32_t blk_off(int r, int cb, int atomrows) {
    const uint32_t local = (uint32_t)(((r & 7) << 7) | (cb & 127));
    const uint32_t atom = (uint32_t)((r >> 3) + ((cb >> 7) * atomrows));
    return (atom << 10) + SWZ128(local);
}
#endif

__global__ __launch_bounds__(128) void attn_tc(
    const uint32_t* __restrict__ qkv, const uint32_t* __restrict__ vt,
    uint32_t* __restrict__ outp)
{
#if HAS_TCGEN05
    extern __shared__ char smem[];
    const uint32_t sbase = smaddr(smem);
    const int t = threadIdx.x, lane = t & 31, warp = t >> 5;
    const int bh = blockIdx.y, b = bh / NH, h = bh % NH;
    const int q0 = blockIdx.x * 128;
    const uint32_t mbS = sbase + 8, mbPV = sbase + 16;
    const uint32_t woff = (uint32_t)warp << 21;

    const uint32_t* Qg = qkv + (size_t)b * SEQ * QKVN + h * HDIM;
    const uint32_t* Kg = Qg + NH * HDIM;
    const uint32_t* Vt = vt + (size_t)bh * HDIM * SEQ;   // [d][seq]

    if (warp == 0) { TC_ALLOC(sbase, 256); TC_RELINQ(); }
    if (t == 0) { MBAR_INIT(mbS, 1); MBAR_INIT(mbPV, 1); }
    __syncthreads();
    uint32_t tmem;
    asm volatile("ld.shared.b32 %0, [%1];" : "=r"(tmem) : "r"(sbase));
    const uint32_t tO = tmem;
    const uint32_t tSb[2] = { tmem + 64, tmem + 128 };
    const uint32_t KST[2] = { sbase + AT3_K0, sbase + AT3_K1 };
    const uint32_t VST[2] = { sbase + AT3_V0, sbase + AT3_V1 };

    auto loadK = [&](int st, int j0) {   // 64 rows x 256B from g_qkv
        #pragma unroll
        for (int i = 0; i < 8; i++) {
            const int c = t + 128 * i, row = c >> 4, cb = (c & 15) * 16;
            cpa16(KST[st] + blk_off(row, cb, 8),
                  Kg + (size_t)(j0 + row) * QKVN + (cb >> 2));
        }
    };
    auto loadV = [&](int st, int j0) {   // 64 d-rows x 256B window from g_vt
        #pragma unroll
        for (int i = 0; i < 8; i++) {
            const int c = t + 128 * i, row = c >> 4, cb = (c & 15) * 16;
            cpa16(VST[st] + blk_off(row, cb, 8),
                  Vt + (size_t)row * SEQ + j0 + (cb >> 2));
        }
    };

    // prologue: group0 = Q + K(0) + VT(0); group1 = K(1)
    #pragma unroll
    for (int i = 0; i < 16; i++) {
        const int c = t + 128 * i, row = c >> 4, cb = (c & 15) * 16;
        cpa16(sbase + AT3_Q + blk_off(row, cb, 16),
              Qg + (size_t)(q0 + row) * QKVN + (cb >> 2));
    }
    loadK(0, 0); loadV(0, 0); CPA_COMMIT();
    loadK(1, 64); CPA_COMMIT();

    const uint64_t qdesc = mk_desc(sbase + AT3_Q);
    const uint32_t QSTEP[8] = {0, 2, 4, 6, 1024, 1026, 1028, 1030};
    const uint32_t KSTEP[8] = {0, 2, 4, 6, 512, 514, 516, 518};

    CPA_WAIT1();   // group0 (Q, K0, VT0) complete
    asm volatile("fence.proxy.async.shared::cta;" ::: "memory");
    __syncthreads();
    if (warp == 0 && elect_one_pred()) {   // S(0) -> mbS
        const uint64_t kd = mk_desc(KST[0]);
        #pragma unroll
        for (int s = 0; s < 8; s++)
            tc_mma_tf32_ss(tSb[0], qdesc + QSTEP[s], kd + KSTEP[s],
                           AT_IDESC, s > 0 ? 1u : 0u);
        TC_COMMIT(mbS);
    }

    const int r0 = warp * 32 + lane;       // this thread's q-row
    float l = 0.f;
    const float scale = 0.125f;

    for (int jt = 0; jt < 16; jt++) {
        // wait S(jt): one commit per iter on mbS, waited at lag 1 -> safe.
        // Also implies PV(jt-1) done (queued before S(jt), in-order).
        MBAR_WAIT(mbS, jt & 1);
        TC_FENCE_AFTER();

        // prefetch: K(jt+2) -> stage jt&1 (old reader S(jt): done);
        //           VT(jt+1) -> stage (jt+1)&1 (old reader PV(jt-1): done)
        if (jt + 2 < 16) loadK(jt & 1, (jt + 2) * 64);
        if (jt + 1 < 16) loadV((jt + 1) & 1, (jt + 1) * 64);
        CPA_COMMIT();
        CPA_WAIT1();   // prior iter's group done: K(jt+1), VT(jt) ready
        asm volatile("fence.proxy.async.shared::cta;" ::: "memory");
        __syncthreads();

        // softmax(jt): tensor pipe idle here -> no TMEM port contention
        const uint32_t tS = tSb[jt & 1];
        float lsum = 0.f;
        {
            uint32_t sr[32];
            TC_LD32(sr, tS);
            TC_WAIT_LD();
            #pragma unroll
            for (int i = 0; i < 32; i++) {
                const float p = __expf(__uint_as_float(sr[i]) * scale);
                lsum += p;
                sr[i] = f2tf(p);
            }
            TC_ST32(tS + woff, sr);
            TC_LD32(sr, tS + 32);
            TC_WAIT_LD();
            #pragma unroll
            for (int i = 0; i < 32; i++) {
                const float p = __expf(__uint_as_float(sr[i]) * scale);
                lsum += p;
                sr[i] = f2tf(p);
            }
            TC_ST32(tS + 32 + woff, sr);
            TC_WAIT_ST();
        }
        l += lsum;
        TC_FENCE_BEFORE();
        __syncthreads();

        // issue PV(jt) then S(jt+1) back-to-back (in-order queue guards
        // tSb WAR: S(jt+1) writes the OTHER buffer; PV reads this one).
        if (warp == 0 && elect_one_pred()) {
            TC_FENCE_AFTER();
            const uint64_t vd = mk_desc(VST[jt & 1]);
            #pragma unroll
            for (int s = 0; s < 8; s++)
                tc_mma_tf32_ts(tO, tS + 8 * s, vd + KSTEP[s],
                               AT_IDESC, (jt > 0 || s > 0) ? 1u : 0u);
            if (jt == 15) {
                TC_COMMIT(mbPV);           // only commit PV at the end
            } else {
                const uint64_t kd = mk_desc(KST[(jt + 1) & 1]);
                #pragma unroll
                for (int s = 0; s < 8; s++)
                    tc_mma_tf32_ss(tSb[(jt + 1) & 1], qdesc + QSTEP[s],
                                   kd + KSTEP[s], AT_IDESC, s > 0 ? 1u : 0u);
                TC_COMMIT(mbS);            // covers PV(jt) + S(jt+1)
            }
        }
    }

    // epilogue: wait PV(15), normalize, store
    MBAR_WAIT(mbPV, 0);
    TC_FENCE_AFTER();
    const float inv = 1.0f / l;
    uint32_t* ob = outp + (size_t)(b * SEQ + q0 + r0) * PK + h * HDIM;
    {
        uint32_t orr[32];
        TC_LD32(orr, tO);
        TC_WAIT_LD();
        #pragma unroll
        for (int j = 0; j < 32; j += 4) {
            uint4 o = { f2tf(__uint_as_float(orr[j])     * inv),
                        f2tf(__uint_as_float(orr[j + 1]) * inv),
                        f2tf(__uint_as_float(orr[j + 2]) * inv),
                        f2tf(__uint_as_float(orr[j + 3]) * inv) };
            *(uint4*)(ob + j) = o;
        }
        TC_LD32(orr, tO + 32);
        TC_WAIT_LD();
        #pragma unroll
        for (int j = 0; j < 32; j += 4) {
            uint4 o = { f2tf(__uint_as_float(orr[j])     * inv),
                        f2tf(__uint_as_float(orr[j + 1]) * inv),
                        f2tf(__uint_as_float(orr[j + 2]) * inv),
                        f2tf(__uint_as_float(orr[j + 3]) * inv) };
            *(uint4*)(ob + 32 + j) = o;
        }
    }
    __syncthreads();
    if (warp == 0) TC_DEALLOC(tmem, 256);
#endif
}

// ===========================================================================
// Fallback attention (R6-proven mma.sync) — only in base-target stages.
// ===========================================================================
#define AT_KSTAGE (64 * 68)
#define AT_VSTAGE (64 * 72)
#define AT_SMEM_BYTES ((128 * 68 + 2 * AT_KSTAGE + 2 * AT_VSTAGE) * 4)

__global__ __launch_bounds__(256, 2) void attn_v2(
    const uint32_t* __restrict__ qkv, uint32_t* __restrict__ outp)
{
#if !HAS_TCGEN05
    extern __shared__ uint32_t sm[];
    uint32_t* Qs = sm;
    uint32_t* Ks = Qs + 128 * 68;
    uint32_t* Vs = Ks + 2 * AT_KSTAGE;

    const int t = threadIdx.x, lane = t & 31, warp = t >> 5;
    const int q = lane & 3, r8 = lane >> 2;
    const int bh = blockIdx.y, b = bh / NH, h = bh % NH;
    const int q0 = blockIdx.x * 128;
    const float scale = 0.125f;

    const uint32_t* Qg = qkv + (size_t)b * SEQ * QKVN + h * HDIM;
    const uint32_t* Kg = Qg + NH * HDIM;
    const uint32_t* Vg = Qg + 2 * NH * HDIM;
    const int r0 = warp * 16 + r8;
    const int c4 = (t & 15) * 4, rb = t >> 4;

    {
        #pragma unroll
        for (int i = 0; i < 8; i++) {
            const int r = rb + 16 * i;
            cpa16(smaddr(&Qs[r * 68 + c4]), Qg + (size_t)(q0 + r) * QKVN + c4);
        }
        #pragma unroll
        for (int i = 0; i < 4; i++) {
            const int r = rb + 16 * i;
            cpa16(smaddr(&Ks[r * 68 + c4]), Kg + (size_t)r * QKVN + c4);
            cpa16(smaddr(&Vs[r * 72 + c4]), Vg + (size_t)r * QKVN + c4);
        }
        CPA_COMMIT();
    }

    float O[8][4] = {};
    float m0 = -1e30f, m1 = -1e30f, l0 = 0.f, l1 = 0.f;
    const int src1 = (lane & 28) | (q >> 1);
    const int src2 = src1 | 2;

    for (int jt = 0; jt < SEQ / 64; jt++) {
        CPA_WAIT0();
        __syncthreads();
        if (jt + 1 < SEQ / 64) {
            const int s = (jt + 1) & 1;
            const int j0 = (jt + 1) * 64;
            #pragma unroll
            for (int i = 0; i < 4; i++) {
                const int r = rb + 16 * i;
                cpa16(smaddr(&Ks[s * AT_KSTAGE + r * 68 + c4]),
                      Kg + (size_t)(j0 + r) * QKVN + c4);
                cpa16(smaddr(&Vs[s * AT_VSTAGE + r * 72 + c4]),
                      Vg + (size_t)(j0 + r) * QKVN + c4);
            }
            CPA_COMMIT();
        }
        const uint32_t* Kst = Ks + (jt & 1) * AT_KSTAGE;
        const uint32_t* Vst = Vs + (jt & 1) * AT_VSTAGE;

        float s[8][4] = {};
        #pragma unroll
        for (int kc = 0; kc < 8; kc++) {
            const int kb = kc * 8 + q;
            uint32_t a[4];
            a[0] = Qs[r0 * 68 + kb];     a[1] = Qs[(r0 + 8) * 68 + kb];
            a[2] = Qs[r0 * 68 + kb + 4]; a[3] = Qs[(r0 + 8) * 68 + kb + 4];
            #pragma unroll
            for (int ni = 0; ni < 8; ni++) {
                const int n = ni * 8 + r8;
                mma_tf32(s[ni], a, Kst[n * 68 + kb], Kst[n * 68 + kb + 4]);
            }
        }

        float mx0 = -1e30f, mx1 = -1e30f;
        #pragma unroll
        for (int ni = 0; ni < 8; ni++) {
            s[ni][0] *= scale; s[ni][1] *= scale;
            s[ni][2] *= scale; s[ni][3] *= scale;
            mx0 = fmaxf(mx0, fmaxf(s[ni][0], s[ni][1]));
            mx1 = fmaxf(mx1, fmaxf(s[ni][2], s[ni][3]));
        }
        mx0 = fmaxf(mx0, __shfl_xor_sync(0xffffffffu, mx0, 1));
        mx0 = fmaxf(mx0, __shfl_xor_sync(0xffffffffu, mx0, 2));
        mx1 = fmaxf(mx1, __shfl_xor_sync(0xffffffffu, mx1, 1));
        mx1 = fmaxf(mx1, __shfl_xor_sync(0xffffffffu, mx1, 2));
        const float mn0 = fmaxf(m0, mx0), mn1 = fmaxf(m1, mx1);
        const float al0 = __expf(m0 - mn0), al1 = __expf(m1 - mn1);
        m0 = mn0; m1 = mn1;
        float sum0 = 0.f, sum1 = 0.f;
        #pragma unroll
        for (int ni = 0; ni < 8; ni++) {
            s[ni][0] = __expf(s[ni][0] - mn0); sum0 += s[ni][0];
            s[ni][1] = __expf(s[ni][1] - mn0); sum0 += s[ni][1];
            s[ni][2] = __expf(s[ni][2] - mn1); sum1 += s[ni][2];
            s[ni][3] = __expf(s[ni][3] - mn1); sum1 += s[ni][3];
        }
        sum0 += __shfl_xor_sync(0xffffffffu, sum0, 1);
        sum0 += __shfl_xor_sync(0xffffffffu, sum0, 2);
        sum1 += __shfl_xor_sync(0xffffffffu, sum1, 1);
        sum1 += __shfl_xor_sync(0xffffffffu, sum1, 2);
        l0 = l0 * al0 + sum0;
        l1 = l1 * al1 + sum1;
        #pragma unroll
        for (int ni = 0; ni < 8; ni++) {
            O[ni][0] *= al0; O[ni][1] *= al0;
            O[ni][2] *= al1; O[ni][3] *= al1;
        }

        #pragma unroll
        for (int kc = 0; kc < 8; kc++) {
            const float v0 = __shfl_sync(0xffffffffu, s[kc][0], src1);
            const float v1 = __shfl_sync(0xffffffffu, s[kc][1], src1);
            const float v2 = __shfl_sync(0xffffffffu, s[kc][2], src1);
            const float v3 = __shfl_sync(0xffffffffu, s[kc][3], src1);
            const float w0 = __shfl_sync(0xffffffffu, s[kc][0], src2);
            const float w1 = __shfl_sync(0xffffffffu, s[kc][1], src2);
            const float w2 = __shfl_sync(0xffffffffu, s[kc][2], src2);
            const float w3 = __shfl_sync(0xffffffffu, s[kc][3], src2);
            const bool odd = (q & 1);
            uint32_t a[4];
            a[0] = f2tf(odd ? v1 : v0);
            a[1] = f2tf(odd ? v3 : v2);
            a[2] = f2tf(odd ? w1 : w0);
            a[3] = f2tf(odd ? w3 : w2);
            const int kb = kc * 8 + q;
            #pragma unroll
            for (int ni = 0; ni < 8; ni++) {
                const int dv = ni * 8 + r8;
                mma_tf32(O[ni], a, Vst[kb * 72 + dv], Vst[(kb + 4) * 72 + dv]);
            }
        }
    }

    const float inv0 = 1.0f / l0, inv1 = 1.0f / l1;
    uint32_t* ob = outp + (size_t)(b * SEQ + q0) * PK + h * HDIM;
    #pragma unroll
    for (int ni = 0; ni < 8; ni++) {
        const int c = ni * 8 + 2 * q;
        uint2 o0 = { f2tf(O[ni][0] * inv0), f2tf(O[ni][1] * inv0) };
        uint2 o1 = { f2tf(O[ni][2] * inv1), f2tf(O[ni][3] * inv1) };
        *(uint2*)(ob + (size_t)r0 * PK + c)       = o0;
        *(uint2*)(ob + (size_t)(r0 + 8) * PK + c) = o1;
    }
#endif
}

// ===========================================================================
// Fallback GEMM (R6-proven mma.sync) — only in base-target stages.
// ===========================================================================
#define G_ASTRIDE 36
#define G_ASTAGE  (256 * G_ASTRIDE)
#define G_BSTAGE  (64 * G_ASTRIDE)
#define G_SMEM_BYTES ((2 * G_ASTAGE + 2 * G_BSTAGE) * 4)

template <bool OUT_TF>
__global__ __launch_bounds__(256, 2) void gemm_fb(
    const uint32_t* __restrict__ A, const uint32_t* __restrict__ W,
    const float* __restrict__ bias, void* __restrict__ Cout,
    int Kdim, int Ndim)
{
#if !HAS_TCGEN05
    extern __shared__ uint32_t dsm[];
    uint32_t* As = dsm;
    uint32_t* Bs = dsm + 2 * G_ASTAGE;

    const int t = threadIdx.x, lane = t & 31, warp = t >> 5;
    const int wm = warp >> 1, wn = warp & 1;
    const int q = lane & 3, r8 = lane >> 2;
    const int m0 = blockIdx.y * 256, n0 = blockIdx.x * 64;
    const int lr = t >> 3, lc4 = (t & 7) * 4;
    const int KT = Kdim >> 5;

    float acc[16][4] = {};

    const uint32_t* Ag = A + (size_t)(m0 + lr) * Kdim + lc4;
    const uint32_t* Wg = W + (size_t)(n0 + lr) * Kdim + lc4;

    {
        #pragma unroll
        for (int i = 0; i < 8; i++)
            cpa16(smaddr(&As[(lr + 32 * i) * G_ASTRIDE + lc4]),
                  Ag + (size_t)(32 * i) * Kdim);
        #pragma unroll
        for (int i = 0; i < 2; i++)
            cpa16(smaddr(&Bs[(lr + 32 * i) * G_ASTRIDE + lc4]),
                  Wg + (size_t)(32 * i) * Kdim);
        CPA_COMMIT();
    }

    for (int kt = 0; kt < KT; kt++) {
        CPA_WAIT0();
        __syncthreads();
        if (kt + 1 < KT) {
            const int s = (kt + 1) & 1;
            const int k0 = (kt + 1) << 5;
            #pragma unroll
            for (int i = 0; i < 8; i++)
                cpa16(smaddr(&As[s * G_ASTAGE + (lr + 32 * i) * G_ASTRIDE + lc4]),
                      Ag + (size_t)(32 * i) * Kdim + k0);
            #pragma unroll
            for (int i = 0; i < 2; i++)
                cpa16(smaddr(&Bs[s * G_BSTAGE + (lr + 32 * i) * G_ASTRIDE + lc4]),
                      Wg + (size_t)(32 * i) * Kdim + k0);
            CPA_COMMIT();
        }
        const uint32_t* Ast = As + (kt & 1) * G_ASTAGE;
        const uint32_t* Bst = Bs + (kt & 1) * G_BSTAGE;
        #pragma unroll
        for (int kc = 0; kc < 4; kc++) {
            const int kb = kc * 8 + q;
            uint32_t a[4][4];
            #pragma unroll
            for (int mi = 0; mi < 4; mi++) {
                const int r = wm * 64 + mi * 16 + r8;
                a[mi][0] = Ast[r * G_ASTRIDE + kb];
                a[mi][1] = Ast[(r + 8) * G_ASTRIDE + kb];
                a[mi][2] = Ast[r * G_ASTRIDE + kb + 4];
                a[mi][3] = Ast[(r + 8) * G_ASTRIDE + kb + 4];
            }
            #pragma unroll
            for (int ni = 0; ni < 4; ni++) {
                const int n = wn * 32 + ni * 8 + r8;
                const uint32_t b0 = Bst[n * G_ASTRIDE + kb];
                const uint32_t b1 = Bst[n * G_ASTRIDE + kb + 4];
                #pragma unroll
                for (int mi = 0; mi < 4; mi++)
                    mma_tf32(acc[mi * 4 + ni], a[mi], b0, b1);
            }
        }
    }

    #pragma unroll
    for (int mi = 0; mi < 4; mi++)
        #pragma unroll
        for (int ni = 0; ni < 4; ni++) {
            const float* d = acc[mi * 4 + ni];
            const int r0g = m0 + wm * 64 + mi * 16 + r8;
            const int c   = n0 + wn * 32 + ni * 8 + 2 * q;
            const float bx = bias[c], by = bias[c + 1];
            if (OUT_TF) {
                uint32_t* C = (uint32_t*)Cout;
                uint2 o0 = { f2tf(d[0] + bx), f2tf(d[1] + by) };
                uint2 o1 = { f2tf(d[2] + bx), f2tf(d[3] + by) };
                *(uint2*)(C + (size_t)r0g * Ndim + c)       = o0;
                *(uint2*)(C + (size_t)(r0g + 8) * Ndim + c) = o1;
            } else {
                float* C = (float*)Cout;
                float2 o0 = { d[0] + bx, d[1] + by };
                float2 o1 = { d[2] + bx, d[3] + by };
                *(float2*)(C + (size_t)r0g * Ndim + c)       = o0;
                *(float2*)(C + (size_t)(r0g + 8) * Ndim + c) = o1;
            }
        }
#endif
}

// ---------------------------------------------------------------------------
extern "C" void kernel_launch(void* const* d_in, const int* in_sizes, int n_in,
                              void* d_out, int out_size)
{
    const float* x      = (const float*)d_in[0];
    const float* qkv_w  = (const float*)d_in[1];
    const float* qkv_b  = (const float*)d_in[2];
    const float* proj_w = (const float*)d_in[3];
    const float* proj_b = (const float*)d_in[4];
    float* outp = (float*)d_out;

    uint32_t *x_tf, *qw_tf, *pw_tf, *qkv, *vt, *attn;
    cudaGetSymbolAddress((void**)&x_tf,  g_x_tf);
    cudaGetSymbolAddress((void**)&qw_tf, g_qw_tf);
    cudaGetSymbolAddress((void**)&pw_tf, g_pw_tf);
    cudaGetSymbolAddress((void**)&qkv,   g_qkv);
    cudaGetSymbolAddress((void**)&vt,    g_vt);
    cudaGetSymbolAddress((void**)&attn,  g_attn);

    // 0) Pre-convert inputs to tf32 bits
    {
        const int nx = MTOT * CDIM / 4, nw = QKVN * CDIM / 4, np = CDIM * PK / 4;
        cvt_tf32_kernel<<<(nx + 255) / 256, 256>>>((const float4*)x,      (uint4*)x_tf,  nx);
        cvt_tf32_kernel<<<(nw + 255) / 256, 256>>>((const float4*)qkv_w,  (uint4*)qw_tf, nw);
        cvt_tf32_kernel<<<(np + 255) / 256, 256>>>((const float4*)proj_w, (uint4*)pw_tf, np);
    }

    cudaFuncSetAttribute(gemm_tc<true>,  cudaFuncAttributeMaxDynamicSharedMemorySize, TC_SMEM);
    cudaFuncSetAttribute(gemm_tc<false>, cudaFuncAttributeMaxDynamicSharedMemorySize, TC_SMEM);
    cudaFuncSetAttribute(gemm_fb<true>,  cudaFuncAttributeMaxDynamicSharedMemorySize, G_SMEM_BYTES);
    cudaFuncSetAttribute(gemm_fb<false>, cudaFuncAttributeMaxDynamicSharedMemorySize, G_SMEM_BYTES);
    cudaFuncSetAttribute(attn_tc, cudaFuncAttributeMaxDynamicSharedMemorySize, AT3_SMEM);
    cudaFuncSetAttribute(attn_v2, cudaFuncAttributeMaxDynamicSharedMemorySize, AT_SMEM_BYTES);

    // 1) QKV projection -> tf32 bits (exactly one path does work)
    gemm_tc<true><<<dim3(QKVN / TC_BN, MTOT / 128), 256, TC_SMEM>>>(
        x_tf, qw_tf, qkv_b, qkv, CDIM, QKVN);
    gemm_fb<true><<<dim3(QKVN / 64, MTOT / 256), 256, G_SMEM_BYTES>>>(
        x_tf, qw_tf, qkv_b, qkv, CDIM, QKVN);

    // 1b) Transpose V for the tcgen05 attention's B operand
    transpose_v_kernel<<<dim3(SEQ / 32, HDIM / 32, BDIM * NH), dim3(32, 8)>>>(qkv, vt);

    // 2) Fused attention -> tf32 bits (exactly one path does work)
    attn_tc<<<dim3(SEQ / 128, BDIM * NH), 128, AT3_SMEM>>>(qkv, vt, attn);
    attn_v2<<<dim3(SEQ / 128, BDIM * NH), 256, AT_SMEM_BYTES>>>(qkv, attn);

    // 3) Output projection -> fp32 (exactly one path does work)
    gemm_tc<false><<<dim3(CDIM / TC_BN, MTOT / 128), 256, TC_SMEM>>>(
        attn, pw_tf, proj_b, outp, PK, CDIM);
    gemm_fb<false><<<dim3(CDIM / 64, MTOT / 256), 256, G_SMEM_BYTES>>>(
        attn, pw_tf, proj_b, outp, PK, CDIM);
}

// round 14
// speedup vs baseline: 1.6670x; 1.1139x over previous
#include <cuda_runtime.h>
#include <cstdint>

#define BDIM 16
#define SEQ  1024
#define CDIM 768
#define NH   9
#define HDIM 64
#define MTOT (BDIM*SEQ)        // 16384
#define QKVN (3*NH*HDIM)       // 1728
#define PK   (NH*HDIM)         // 576

// Does THIS device-compile stage support tcgen05 (arch-/family-specific target)?
#if defined(__CUDA_ARCH__)
#  if defined(__CUDA_ARCH_FEAT_SM103_ALL) || defined(__CUDA_ARCH_FEAT_SM100_ALL) || \
      (defined(__CUDA_ARCH_FAMILY_SPECIFIC__) && (__CUDA_ARCH_FAMILY_SPECIFIC__ >= 1000))
#    define HAS_TCGEN05 1
#  else
#    define HAS_TCGEN05 0
#  endif
#else
#  define HAS_TCGEN05 0
#endif

// Scratch (device globals: allocation-free per harness rules). tf32 bit patterns.
__device__ uint32_t g_x_tf[(size_t)MTOT * CDIM];
__device__ uint32_t g_qw_tf[(size_t)QKVN * CDIM];
__device__ uint32_t g_pw_tf[(size_t)CDIM * PK];
__device__ uint32_t g_qkv[(size_t)MTOT * QKVN];
__device__ uint32_t g_vt[(size_t)BDIM * NH * HDIM * SEQ];   // V^T [b,h,d,seq]
__device__ uint32_t g_attn[(size_t)MTOT * PK];

__device__ __forceinline__ uint32_t f2tf(float f) {
    uint32_t u;
    asm("cvt.rna.tf32.f32 %0, %1;" : "=r"(u) : "f"(f));
    return u;
}
__device__ __forceinline__ void mma_tf32(float* d, const uint32_t* a,
                                         uint32_t b0, uint32_t b1) {
    asm volatile(
        "mma.sync.aligned.m16n8k8.row.col.f32.tf32.tf32.f32 "
        "{%0,%1,%2,%3},{%4,%5,%6,%7},{%8,%9},{%0,%1,%2,%3};\n"
        : "+f"(d[0]), "+f"(d[1]), "+f"(d[2]), "+f"(d[3])
        : "r"(a[0]), "r"(a[1]), "r"(a[2]), "r"(a[3]), "r"(b0), "r"(b1));
}
__device__ __forceinline__ uint32_t smaddr(const void* p) {
    return (uint32_t)__cvta_generic_to_shared(p);
}
__device__ __forceinline__ void cpa16(uint32_t s, const void* g) {
    asm volatile("cp.async.cg.shared.global [%0], [%1], 16;" :: "r"(s), "l"(g));
}
#define CPA_COMMIT() asm volatile("cp.async.commit_group;")
#define CPA_WAIT0()  asm volatile("cp.async.wait_group 0;")
#define CPA_WAIT1()  asm volatile("cp.async.wait_group 1;")
#define CPA_WAIT2()  asm volatile("cp.async.wait_group 2;")
#define SWZ128(x) ((x) ^ (((x) >> 3) & 0x70))

// ---------------------------------------------------------------------------
__global__ void cvt_tf32_kernel(const float4* __restrict__ in,
                                uint4* __restrict__ out, int n4) {
    const int i = blockIdx.x * blockDim.x + threadIdx.x;
    if (i < n4) {
        float4 v = in[i];
        uint4 o = { f2tf(v.x), f2tf(v.y), f2tf(v.z), f2tf(v.w) };
        out[i] = o;
    }
}

// V transpose: g_qkv[token][1152 + h*64 + d] -> g_vt[(bh*64+d)*SEQ + n]
__global__ void transpose_v_kernel(const uint32_t* __restrict__ qkv,
                                   uint32_t* __restrict__ vt) {
    __shared__ uint32_t tile[32][33];
    const int bh = blockIdx.z, b = bh / NH, h = bh % NH;
    const int n0 = blockIdx.x * 32, d0 = blockIdx.y * 32;
    const int tx = threadIdx.x, ty = threadIdx.y;
    #pragma unroll
    for (int i = ty; i < 32; i += 8)
        tile[i][tx] = qkv[(size_t)(b * SEQ + n0 + i) * QKVN
                          + 2 * NH * HDIM + h * HDIM + d0 + tx];
    __syncthreads();
    #pragma unroll
    for (int i = ty; i < 32; i += 8)
        vt[((size_t)bh * HDIM + d0 + i) * SEQ + n0 + tx] = tile[tx][i];
}

#if HAS_TCGEN05
__device__ __forceinline__ uint32_t elect_one_pred() {
    uint32_t pred;
    asm volatile("{\n\t.reg .pred p;\n\telect.sync _|p, 0xFFFFFFFF;\n\t"
                 "selp.b32 %0, 1, 0, p;\n\t}" : "=r"(pred));
    return pred;
}
#define TC_ALLOC(sm_res, n) \
    asm volatile("tcgen05.alloc.cta_group::1.sync.aligned.shared::cta.b32 [%0], %1;" \
                 :: "r"((uint32_t)(sm_res)), "r"((uint32_t)(n)) : "memory")
#define TC_RELINQ() \
    asm volatile("tcgen05.relinquish_alloc_permit.cta_group::1.sync.aligned;")
#define TC_DEALLOC(tm, n) \
    asm volatile("tcgen05.dealloc.cta_group::1.sync.aligned.b32 %0, %1;" :: "r"(tm), "r"((uint32_t)(n)))
#define TC_COMMIT(mb) \
    asm volatile("tcgen05.commit.cta_group::1.mbarrier::arrive::one.shared::cluster.b64 [%0];" \
                 :: "r"((uint32_t)(mb)) : "memory")
#define TC_FENCE_AFTER()  asm volatile("tcgen05.fence::after_thread_sync;" ::: "memory")
#define TC_FENCE_BEFORE() asm volatile("tcgen05.fence::before_thread_sync;" ::: "memory")
#define TC_WAIT_LD() asm volatile("tcgen05.wait::ld.sync.aligned;" ::: "memory")
#define TC_WAIT_ST() asm volatile("tcgen05.wait::st.sync.aligned;" ::: "memory")
#define MBAR_INIT(mb, c) \
    asm volatile("mbarrier.init.shared.b64 [%0], %1;" :: "r"((uint32_t)(mb)), "r"((uint32_t)(c)) : "memory")
#define MBAR_WAIT(mb, par) do { \
    uint32_t _m = (uint32_t)(mb), _p = (uint32_t)(par), _d; \
    asm volatile("{\n\t.reg .pred p;\n\t" \
        "mbarrier.try_wait.parity.acquire.cta.shared::cta.b64 p, [%1], %2;\n\t" \
        "selp.b32 %0, 1, 0, p;\n\t}" : "=r"(_d) : "r"(_m), "r"(_p) : "memory"); \
    if (!_d) { \
        asm volatile("{\n\t.reg .pred P1;\n\tWL_%=:\n\t" \
            "mbarrier.try_wait.parity.acquire.cta.shared::cta.b64 P1, [%0], %1, 0x989680;\n\t" \
            "@P1 bra.uni WD_%=;\n\tbra.uni WL_%=;\n\tWD_%=:\n\t}" \
            :: "r"(_m), "r"(_p) : "memory"); \
    } } while (0)

__device__ __forceinline__ void tc_mma_tf32_ss(uint32_t d_tmem, uint64_t ad,
                                               uint64_t bd, uint32_t idesc,
                                               uint32_t en) {
    asm volatile(
        "{\n\t.reg .pred p;\n\tsetp.ne.u32 p, %4, 0;\n\t"
        "tcgen05.mma.cta_group::1.kind::tf32 [%0], %1, %2, %3, p;\n\t}"
        :: "r"(d_tmem), "l"(ad), "l"(bd), "r"(idesc), "r"(en) : "memory");
}
__device__ __forceinline__ void tc_mma_tf32_ts(uint32_t d_tmem, uint32_t a_tmem,
                                               uint64_t bd, uint32_t idesc,
                                               uint32_t en) {
    asm volatile(
        "{\n\t.reg .pred p;\n\tsetp.ne.u32 p, %4, 0;\n\t"
        "tcgen05.mma.cta_group::1.kind::tf32 [%0], [%1], %2, %3, p;\n\t}"
        :: "r"(d_tmem), "r"(a_tmem), "l"(bd), "r"(idesc), "r"(en) : "memory");
}
#define TC_LD32(r, ta) \
    asm volatile( \
        "tcgen05.ld.sync.aligned.32x32b.x32.b32 " \
        "{%0,%1,%2,%3,%4,%5,%6,%7,%8,%9,%10,%11,%12,%13,%14,%15," \
        "%16,%17,%18,%19,%20,%21,%22,%23,%24,%25,%26,%27,%28,%29,%30,%31},[%32];" \
        : "=r"((r)[0]), "=r"((r)[1]), "=r"((r)[2]), "=r"((r)[3]), "=r"((r)[4]), \
          "=r"((r)[5]), "=r"((r)[6]), "=r"((r)[7]), "=r"((r)[8]), "=r"((r)[9]), \
          "=r"((r)[10]), "=r"((r)[11]), "=r"((r)[12]), "=r"((r)[13]), "=r"((r)[14]), \
          "=r"((r)[15]), "=r"((r)[16]), "=r"((r)[17]), "=r"((r)[18]), "=r"((r)[19]), \
          "=r"((r)[20]), "=r"((r)[21]), "=r"((r)[22]), "=r"((r)[23]), "=r"((r)[24]), \
          "=r"((r)[25]), "=r"((r)[26]), "=r"((r)[27]), "=r"((r)[28]), "=r"((r)[29]), \
          "=r"((r)[30]), "=r"((r)[31]) \
        : "r"(ta))
#define TC_ST32(ta, r) \
    asm volatile( \
        "tcgen05.st.sync.aligned.32x32b.x32.b32 [%0], " \
        "{%1,%2,%3,%4,%5,%6,%7,%8,%9,%10,%11,%12,%13,%14,%15,%16," \
        "%17,%18,%19,%20,%21,%22,%23,%24,%25,%26,%27,%28,%29,%30,%31,%32};" \
        :: "r"(ta), \
           "r"((r)[0]), "r"((r)[1]), "r"((r)[2]), "r"((r)[3]), "r"((r)[4]), \
           "r"((r)[5]), "r"((r)[6]), "r"((r)[7]), "r"((r)[8]), "r"((r)[9]), \
           "r"((r)[10]), "r"((r)[11]), "r"((r)[12]), "r"((r)[13]), "r"((r)[14]), \
           "r"((r)[15]), "r"((r)[16]), "r"((r)[17]), "r"((r)[18]), "r"((r)[19]), \
           "r"((r)[20]), "r"((r)[21]), "r"((r)[22]), "r"((r)[23]), "r"((r)[24]), \
           "r"((r)[25]), "r"((r)[26]), "r"((r)[27]), "r"((r)[28]), "r"((r)[29]), \
           "r"((r)[30]), "r"((r)[31]) \
        : "memory")
__device__ __forceinline__ uint64_t mk_desc(uint32_t addr) {
    return ((uint64_t)2 << 61) | ((uint64_t)1 << 46) | ((uint64_t)64 << 32)
         | ((uint64_t)1 << 16) | (uint64_t)((addr >> 4) & 0x3FFF);
}
#endif // HAS_TCGEN05

// ===========================================================================
// tcgen05 tf32 GEMM v3: BM=256 (two M=128 D-tiles in TMEM), BN=192, BK=32.
// 3-stage cp.async ring, 256 threads. Halves W re-reads vs BM=128 ->
// L2 traffic 1.13GB -> 793MB (gemm1). 1 CTA/SM (169KB smem).
// ===========================================================================
#define TC_BN 192
#define G_ASTG 32768
#define G_BSTG (TC_BN*128)
#define OFF_A0 1024
#define OFF_B0 (OFF_A0 + 3*G_ASTG)
#define TC_SMEM (OFF_B0 + 3*G_BSTG)
#if HAS_TCGEN05
#define TC_IDESC ((1u<<4) | (2u<<7) | (2u<<10) | ((TC_BN/8)<<17) | (8u<<24))
#endif

template <bool OUT_TF>
__global__ __launch_bounds__(256) void gemm_tc(
    const uint32_t* __restrict__ A, const uint32_t* __restrict__ W,
    const float* __restrict__ bias, void* __restrict__ Cout,
    int Kdim, int Ndim)
{
#if HAS_TCGEN05
    extern __shared__ char smem[];
    const uint32_t sbase = smaddr(smem);
    const int t = threadIdx.x, lane = t & 31, warp = t >> 5;
    const int m0 = blockIdx.y * 256, n0 = blockIdx.x * TC_BN;
    const uint32_t mb0 = sbase + 8, mb1 = sbase + 16;

    if (warp == 0) { TC_ALLOC(sbase, 512); TC_RELINQ(); }
    if (t == 0) { MBAR_INIT(mb0, 1); MBAR_INIT(mb1, 1); }
    __syncthreads();
    uint32_t tmem;
    asm volatile("ld.shared.b32 %0, [%1];" : "=r"(tmem) : "r"(sbase));

    const int KT = Kdim >> 5;

    // A: 256 rows x 32 tf32 (8 cpa/thr); B: 192 rows x 32 (6 cpa/thr)
    auto loadA = [&](int st, int k0) {
        const uint32_t base = sbase + OFF_A0 + st * G_ASTG;
        #pragma unroll
        for (int i = 0; i < 8; i++) {
            const int idx = t + 256 * i, row = idx >> 3, ch = idx & 7;
            cpa16(base + (uint32_t)((row >> 3) << 10)
                       + SWZ128((uint32_t)(((row & 7) << 7) + ch * 16)),
                  A + (size_t)(m0 + row) * Kdim + k0 + ch * 4);
        }
    };
    auto loadB = [&](int st, int k0) {
        const uint32_t base = sbase + OFF_B0 + st * G_BSTG;
        #pragma unroll
        for (int i = 0; i < 6; i++) {
            const int idx = t + 256 * i, row = idx >> 3, ch = idx & 7;
            cpa16(base + (uint32_t)((row >> 3) << 10)
                       + SWZ128((uint32_t)(((row & 7) << 7) + ch * 16)),
                  W + (size_t)(n0 + row) * Kdim + k0 + ch * 4);
        }
    };

    loadA(0, 0); loadB(0, 0); CPA_COMMIT();
    loadA(1, 32); loadB(1, 32); CPA_COMMIT();
    int pw0 = 0, pw1 = 0;

    for (int kt = 0; kt < KT; kt++) {
        CPA_WAIT1();
        asm volatile("fence.proxy.async.shared::cta;" ::: "memory");
        __syncthreads();
        if (warp == 0 && elect_one_pred()) {
            const int st = kt % 3;
            const uint32_t abase = sbase + OFF_A0 + st * G_ASTG;
            const uint64_t ad0 = mk_desc(abase);
            const uint64_t ad1 = mk_desc(abase + 16384);   // rows 128-255
            const uint64_t bd  = mk_desc(sbase + OFF_B0 + st * G_BSTG);
            const uint32_t en = (kt > 0) ? 1u : 0u;
            #pragma unroll
            for (int s = 0; s < 4; s++) {
                const uint32_t e = (en || s > 0) ? 1u : 0u;
                tc_mma_tf32_ss(tmem,          ad0 + 2 * s, bd + 2 * s, TC_IDESC, e);
                tc_mma_tf32_ss(tmem + TC_BN,  ad1 + 2 * s, bd + 2 * s, TC_IDESC, e);
            }
            TC_COMMIT((kt & 1) ? mb1 : mb0);
        }
        if (kt >= 1) {   // MMA kt-1 must be done before overwriting its stage
            if ((kt - 1) & 1) { MBAR_WAIT(mb1, pw1 & 1); pw1++; }
            else              { MBAR_WAIT(mb0, pw0 & 1); pw0++; }
        }
        if (kt + 2 < KT) {
            loadA((kt + 2) % 3, (kt + 2) * 32);
            loadB((kt + 2) % 3, (kt + 2) * 32);
        }
        CPA_COMMIT();
    }
    if ((KT - 1) & 1) { MBAR_WAIT(mb1, pw1 & 1); }
    else              { MBAR_WAIT(mb0, pw0 & 1); }
    TC_FENCE_AFTER();

    // Epilogue: warp -> (M-half = warp>>2, subpartition = warp&3)
    const int row = m0 + (warp >> 2) * 128 + (warp & 3) * 32 + lane;
    const uint32_t dbase = tmem + (warp >> 2) * TC_BN;
    #pragma unroll
    for (int cc = 0; cc < TC_BN; cc += 32) {
        uint32_t dr[32];
        TC_LD32(dr, dbase + cc);
        TC_WAIT_LD();
        #pragma unroll
        for (int j = 0; j < 32; j += 4) {
            const int c = n0 + cc + j;
            float v0 = __uint_as_float(dr[j])     + bias[c];
            float v1 = __uint_as_float(dr[j + 1]) + bias[c + 1];
            float v2 = __uint_as_float(dr[j + 2]) + bias[c + 2];
            float v3 = __uint_as_float(dr[j + 3]) + bias[c + 3];
            if (OUT_TF) {
                uint4 o = { f2tf(v0), f2tf(v1), f2tf(v2), f2tf(v3) };
                *(uint4*)((uint32_t*)Cout + (size_t)row * Ndim + c) = o;
            } else {
                float4 o = { v0, v1, v2, v3 };
                *(float4*)((float*)Cout + (size_t)row * Ndim + c) = o;
            }
        }
    }
    __syncthreads();
    if (warp == 0) TC_DEALLOC(tmem, 512);
#endif
}

// ===========================================================================
// tcgen05 fused attention v4 (R13-proven, frozen except exp2 fold).
// ===========================================================================
#define AT3_Q   1024
#define AT3_K0  (AT3_Q  + 32768)
#define AT3_K1  (AT3_K0 + 16384)
#define AT3_V0  (AT3_K1 + 16384)
#define AT3_V1  (AT3_V0 + 16384)
#define AT3_SMEM (AT3_V1 + 16384)
#if HAS_TCGEN05
#define AT_IDESC ((1u<<4) | (2u<<7) | (2u<<10) | (8u<<17) | (8u<<24))
__device__ __forceinline__ uint32_t blk_off(int r, int cb, int atomrows) {
    const uint32_t local = (uint32_t)(((r & 7) << 7) | (cb & 127));
    const uint32_t atom = (uint32_t)((r >> 3) + ((cb >> 7) * atomrows));
    return (atom << 10) + SWZ128(local);
}
#endif

__global__ __launch_bounds__(128) void attn_tc(
    const uint32_t* __restrict__ qkv, const uint32_t* __restrict__ vt,
    uint32_t* __restrict__ outp)
{
#if HAS_TCGEN05
    extern __shared__ char smem[];
    const uint32_t sbase = smaddr(smem);
    const int t = threadIdx.x, lane = t & 31, warp = t >> 5;
    const int bh = blockIdx.y, b = bh / NH, h = bh % NH;
    const int q0 = blockIdx.x * 128;
    const uint32_t mbS = sbase + 8, mbPV = sbase + 16;
    const uint32_t woff = (uint32_t)warp << 21;

    const uint32_t* Qg = qkv + (size_t)b * SEQ * QKVN + h * HDIM;
    const uint32_t* Kg = Qg + NH * HDIM;
    const uint32_t* Vt = vt + (size_t)bh * HDIM * SEQ;   // [d][seq]

    if (warp == 0) { TC_ALLOC(sbase, 256); TC_RELINQ(); }
    if (t == 0) { MBAR_INIT(mbS, 1); MBAR_INIT(mbPV, 1); }
    __syncthreads();
    uint32_t tmem;
    asm volatile("ld.shared.b32 %0, [%1];" : "=r"(tmem) : "r"(sbase));
    const uint32_t tO = tmem;
    const uint32_t tSb[2] = { tmem + 64, tmem + 128 };
    const uint32_t KST[2] = { sbase + AT3_K0, sbase + AT3_K1 };
    const uint32_t VST[2] = { sbase + AT3_V0, sbase + AT3_V1 };

    auto loadK = [&](int st, int j0) {
        #pragma unroll
        for (int i = 0; i < 8; i++) {
            const int c = t + 128 * i, row = c >> 4, cb = (c & 15) * 16;
            cpa16(KST[st] + blk_off(row, cb, 8),
                  Kg + (size_t)(j0 + row) * QKVN + (cb >> 2));
        }
    };
    auto loadV = [&](int st, int j0) {
        #pragma unroll
        for (int i = 0; i < 8; i++) {
            const int c = t + 128 * i, row = c >> 4, cb = (c & 15) * 16;
            cpa16(VST[st] + blk_off(row, cb, 8),
                  Vt + (size_t)row * SEQ + j0 + (cb >> 2));
        }
    };

    #pragma unroll
    for (int i = 0; i < 16; i++) {
        const int c = t + 128 * i, row = c >> 4, cb = (c & 15) * 16;
        cpa16(sbase + AT3_Q + blk_off(row, cb, 16),
              Qg + (size_t)(q0 + row) * QKVN + (cb >> 2));
    }
    loadK(0, 0); loadV(0, 0); CPA_COMMIT();
    loadK(1, 64); CPA_COMMIT();

    const uint64_t qdesc = mk_desc(sbase + AT3_Q);
    const uint32_t QSTEP[8] = {0, 2, 4, 6, 1024, 1026, 1028, 1030};
    const uint32_t KSTEP[8] = {0, 2, 4, 6, 512, 514, 516, 518};

    CPA_WAIT1();
    asm volatile("fence.proxy.async.shared::cta;" ::: "memory");
    __syncthreads();
    if (warp == 0 && elect_one_pred()) {
        const uint64_t kd = mk_desc(KST[0]);
        #pragma unroll
        for (int s = 0; s < 8; s++)
            tc_mma_tf32_ss(tSb[0], qdesc + QSTEP[s], kd + KSTEP[s],
                           AT_IDESC, s > 0 ? 1u : 0u);
        TC_COMMIT(mbS);
    }

    const int r0 = warp * 32 + lane;
    float l = 0.f;
    const float cexp = 0.18033688f;   // 0.125 * log2(e), folded

    for (int jt = 0; jt < 16; jt++) {
        MBAR_WAIT(mbS, jt & 1);
        TC_FENCE_AFTER();

        if (jt + 2 < 16) loadK(jt & 1, (jt + 2) * 64);
        if (jt + 1 < 16) loadV((jt + 1) & 1, (jt + 1) * 64);
        CPA_COMMIT();
        CPA_WAIT1();
        asm volatile("fence.proxy.async.shared::cta;" ::: "memory");
        __syncthreads();

        const uint32_t tS = tSb[jt & 1];
        float lsum = 0.f;
        {
            uint32_t sr[32];
            TC_LD32(sr, tS);
            TC_WAIT_LD();
            #pragma unroll
            for (int i = 0; i < 32; i++) {
                const float p = exp2f(__uint_as_float(sr[i]) * cexp);
                lsum += p;
                sr[i] = f2tf(p);
            }
            TC_ST32(tS + woff, sr);
            TC_LD32(sr, tS + 32);
            TC_WAIT_LD();
            #pragma unroll
            for (int i = 0; i < 32; i++) {
                const float p = exp2f(__uint_as_float(sr[i]) * cexp);
                lsum += p;
                sr[i] = f2tf(p);
            }
            TC_ST32(tS + 32 + woff, sr);
            TC_WAIT_ST();
        }
        l += lsum;
        TC_FENCE_BEFORE();
        __syncthreads();

        if (warp == 0 && elect_one_pred()) {
            TC_FENCE_AFTER();
            const uint64_t vd = mk_desc(VST[jt & 1]);
            #pragma unroll
            for (int s = 0; s < 8; s++)
                tc_mma_tf32_ts(tO, tS + 8 * s, vd + KSTEP[s],
                               AT_IDESC, (jt > 0 || s > 0) ? 1u : 0u);
            if (jt == 15) {
                TC_COMMIT(mbPV);
            } else {
                const uint64_t kd = mk_desc(KST[(jt + 1) & 1]);
                #pragma unroll
                for (int s = 0; s < 8; s++)
                    tc_mma_tf32_ss(tSb[(jt + 1) & 1], qdesc + QSTEP[s],
                                   kd + KSTEP[s], AT_IDESC, s > 0 ? 1u : 0u);
                TC_COMMIT(mbS);
            }
        }
    }

    MBAR_WAIT(mbPV, 0);
    TC_FENCE_AFTER();
    const float inv = 1.0f / l;
    uint32_t* ob = outp + (size_t)(b * SEQ + q0 + r0) * PK + h * HDIM;
    {
        uint32_t orr[32];
        TC_LD32(orr, tO);
        TC_WAIT_LD();
        #pragma unroll
        for (int j = 0; j < 32; j += 4) {
            uint4 o = { f2tf(__uint_as_float(orr[j])     * inv),
                        f2tf(__uint_as_float(orr[j + 1]) * inv),
                        f2tf(__uint_as_float(orr[j + 2]) * inv),
                        f2tf(__uint_as_float(orr[j + 3]) * inv) };
            *(uint4*)(ob + j) = o;
        }
        TC_LD32(orr, tO + 32);
        TC_WAIT_LD();
        #pragma unroll
        for (int j = 0; j < 32; j += 4) {
            uint4 o = { f2tf(__uint_as_float(orr[j])     * inv),
                        f2tf(__uint_as_float(orr[j + 1]) * inv),
                        f2tf(__uint_as_float(orr[j + 2]) * inv),
                        f2tf(__uint_as_float(orr[j + 3]) * inv) };
            *(uint4*)(ob + 32 + j) = o;
        }
    }
    __syncthreads();
    if (warp == 0) TC_DEALLOC(tmem, 256);
#endif
}

// ===========================================================================
// Fallback attention (R6-proven mma.sync) — only in base-target stages.
// ===========================================================================
#define AT_KSTAGE (64 * 68)
#define AT_VSTAGE (64 * 72)
#define AT_SMEM_BYTES ((128 * 68 + 2 * AT_KSTAGE + 2 * AT_VSTAGE) * 4)

__global__ __launch_bounds__(256, 2) void attn_v2(
    const uint32_t* __restrict__ qkv, uint32_t* __restrict__ outp)
{
#if !HAS_TCGEN05
    extern __shared__ uint32_t sm[];
    uint32_t* Qs = sm;
    uint32_t* Ks = Qs + 128 * 68;
    uint32_t* Vs = Ks + 2 * AT_KSTAGE;

    const int t = threadIdx.x, lane = t & 31, warp = t >> 5;
    const int q = lane & 3, r8 = lane >> 2;
    const int bh = blockIdx.y, b = bh / NH, h = bh % NH;
    const int q0 = blockIdx.x * 128;
    const float scale = 0.125f;

    const uint32_t* Qg = qkv + (size_t)b * SEQ * QKVN + h * HDIM;
    const uint32_t* Kg = Qg + NH * HDIM;
    const uint32_t* Vg = Qg + 2 * NH * HDIM;
    const int r0 = warp * 16 + r8;
    const int c4 = (t & 15) * 4, rb = t >> 4;

    {
        #pragma unroll
        for (int i = 0; i < 8; i++) {
            const int r = rb + 16 * i;
            cpa16(smaddr(&Qs[r * 68 + c4]), Qg + (size_t)(q0 + r) * QKVN + c4);
        }
        #pragma unroll
        for (int i = 0; i < 4; i++) {
            const int r = rb + 16 * i;
            cpa16(smaddr(&Ks[r * 68 + c4]), Kg + (size_t)r * QKVN + c4);
            cpa16(smaddr(&Vs[r * 72 + c4]), Vg + (size_t)r * QKVN + c4);
        }
        CPA_COMMIT();
    }

    float O[8][4] = {};
    float m0 = -1e30f, m1 = -1e30f, l0 = 0.f, l1 = 0.f;
    const int src1 = (lane & 28) | (q >> 1);
    const int src2 = src1 | 2;

    for (int jt = 0; jt < SEQ / 64; jt++) {
        CPA_WAIT0();
        __syncthreads();
        if (jt + 1 < SEQ / 64) {
            const int s = (jt + 1) & 1;
            const int j0 = (jt + 1) * 64;
            #pragma unroll
            for (int i = 0; i < 4; i++) {
                const int r = rb + 16 * i;
                cpa16(smaddr(&Ks[s * AT_KSTAGE + r * 68 + c4]),
                      Kg + (size_t)(j0 + r) * QKVN + c4);
                cpa16(smaddr(&Vs[s * AT_VSTAGE + r * 72 + c4]),
                      Vg + (size_t)(j0 + r) * QKVN + c4);
            }
            CPA_COMMIT();
        }
        const uint32_t* Kst = Ks + (jt & 1) * AT_KSTAGE;
        const uint32_t* Vst = Vs + (jt & 1) * AT_VSTAGE;

        float s[8][4] = {};
        #pragma unroll
        for (int kc = 0; kc < 8; kc++) {
            const int kb = kc * 8 + q;
            uint32_t a[4];
            a[0] = Qs[r0 * 68 + kb];     a[1] = Qs[(r0 + 8) * 68 + kb];
            a[2] = Qs[r0 * 68 + kb + 4]; a[3] = Qs[(r0 + 8) * 68 + kb + 4];
            #pragma unroll
            for (int ni = 0; ni < 8; ni++) {
                const int n = ni * 8 + r8;
                mma_tf32(s[ni], a, Kst[n * 68 + kb], Kst[n * 68 + kb + 4]);
            }
        }

        float mx0 = -1e30f, mx1 = -1e30f;
        #pragma unroll
        for (int ni = 0; ni < 8; ni++) {
            s[ni][0] *= scale; s[ni][1] *= scale;
            s[ni][2] *= scale; s[ni][3] *= scale;
            mx0 = fmaxf(mx0, fmaxf(s[ni][0], s[ni][1]));
            mx1 = fmaxf(mx1, fmaxf(s[ni][2], s[ni][3]));
        }
        mx0 = fmaxf(mx0, __shfl_xor_sync(0xffffffffu, mx0, 1));
        mx0 = fmaxf(mx0, __shfl_xor_sync(0xffffffffu, mx0, 2));
        mx1 = fmaxf(mx1, __shfl_xor_sync(0xffffffffu, mx1, 1));
        mx1 = fmaxf(mx1, __shfl_xor_sync(0xffffffffu, mx1, 2));
        const float mn0 = fmaxf(m0, mx0), mn1 = fmaxf(m1, mx1);
        const float al0 = __expf(m0 - mn0), al1 = __expf(m1 - mn1);
        m0 = mn0; m1 = mn1;
        float sum0 = 0.f, sum1 = 0.f;
        #pragma unroll
        for (int ni = 0; ni < 8; ni++) {
            s[ni][0] = __expf(s[ni][0] - mn0); sum0 += s[ni][0];
            s[ni][1] = __expf(s[ni][1] - mn0); sum0 += s[ni][1];
            s[ni][2] = __expf(s[ni][2] - mn1); sum1 += s[ni][2];
            s[ni][3] = __expf(s[ni][3] - mn1); sum1 += s[ni][3];
        }
        sum0 += __shfl_xor_sync(0xffffffffu, sum0, 1);
        sum0 += __shfl_xor_sync(0xffffffffu, sum0, 2);
        sum1 += __shfl_xor_sync(0xffffffffu, sum1, 1);
        sum1 += __shfl_xor_sync(0xffffffffu, sum1, 2);
        l0 = l0 * al0 + sum0;
        l1 = l1 * al1 + sum1;
        #pragma unroll
        for (int ni = 0; ni < 8; ni++) {
            O[ni][0] *= al0; O[ni][1] *= al0;
            O[ni][2] *= al1; O[ni][3] *= al1;
        }

        #pragma unroll
        for (int kc = 0; kc < 8; kc++) {
            const float v0 = __shfl_sync(0xffffffffu, s[kc][0], src1);
            const float v1 = __shfl_sync(0xffffffffu, s[kc][1], src1);
            const float v2 = __shfl_sync(0xffffffffu, s[kc][2], src1);
            const float v3 = __shfl_sync(0xffffffffu, s[kc][3], src1);
            const float w0 = __shfl_sync(0xffffffffu, s[kc][0], src2);
            const float w1 = __shfl_sync(0xffffffffu, s[kc][1], src2);
            const float w2 = __shfl_sync(0xffffffffu, s[kc][2], src2);
            const float w3 = __shfl_sync(0xffffffffu, s[kc][3], src2);
            const bool odd = (q & 1);
            uint32_t a[4];
            a[0] = f2tf(odd ? v1 : v0);
            a[1] = f2tf(odd ? v3 : v2);
            a[2] = f2tf(odd ? w1 : w0);
            a[3] = f2tf(odd ? w3 : w2);
            const int kb = kc * 8 + q;
            #pragma unroll
            for (int ni = 0; ni < 8; ni++) {
                const int dv = ni * 8 + r8;
                mma_tf32(O[ni], a, Vst[kb * 72 + dv], Vst[(kb + 4) * 72 + dv]);
            }
        }
    }

    const float inv0 = 1.0f / l0, inv1 = 1.0f / l1;
    uint32_t* ob = outp + (size_t)(b * SEQ + q0) * PK + h * HDIM;
    #pragma unroll
    for (int ni = 0; ni < 8; ni++) {
        const int c = ni * 8 + 2 * q;
        uint2 o0 = { f2tf(O[ni][0] * inv0), f2tf(O[ni][1] * inv0) };
        uint2 o1 = { f2tf(O[ni][2] * inv1), f2tf(O[ni][3] * inv1) };
        *(uint2*)(ob + (size_t)r0 * PK + c)       = o0;
        *(uint2*)(ob + (size_t)(r0 + 8) * PK + c) = o1;
    }
#endif
}

// ===========================================================================
// Fallback GEMM (R6-proven mma.sync) — only in base-target stages.
// ===========================================================================
#define G_ASTRIDE 36
#define G_ASTAGE  (256 * G_ASTRIDE)
#define G_BSTAGE  (64 * G_ASTRIDE)
#define G_SMEM_BYTES ((2 * G_ASTAGE + 2 * G_BSTAGE) * 4)

template <bool OUT_TF>
__global__ __launch_bounds__(256, 2) void gemm_fb(
    const uint32_t* __restrict__ A, const uint32_t* __restrict__ W,
    const float* __restrict__ bias, void* __restrict__ Cout,
    int Kdim, int Ndim)
{
#if !HAS_TCGEN05
    extern __shared__ uint32_t dsm[];
    uint32_t* As = dsm;
    uint32_t* Bs = dsm + 2 * G_ASTAGE;

    const int t = threadIdx.x, lane = t & 31, warp = t >> 5;
    const int wm = warp >> 1, wn = warp & 1;
    const int q = lane & 3, r8 = lane >> 2;
    const int m0 = blockIdx.y * 256, n0 = blockIdx.x * 64;
    const int lr = t >> 3, lc4 = (t & 7) * 4;
    const int KT = Kdim >> 5;

    float acc[16][4] = {};

    const uint32_t* Ag = A + (size_t)(m0 + lr) * Kdim + lc4;
    const uint32_t* Wg = W + (size_t)(n0 + lr) * Kdim + lc4;

    {
        #pragma unroll
        for (int i = 0; i < 8; i++)
            cpa16(smaddr(&As[(lr + 32 * i) * G_ASTRIDE + lc4]),
                  Ag + (size_t)(32 * i) * Kdim);
        #pragma unroll
        for (int i = 0; i < 2; i++)
            cpa16(smaddr(&Bs[(lr + 32 * i) * G_ASTRIDE + lc4]),
                  Wg + (size_t)(32 * i) * Kdim);
        CPA_COMMIT();
    }

    for (int kt = 0; kt < KT; kt++) {
        CPA_WAIT0();
        __syncthreads();
        if (kt + 1 < KT) {
            const int s = (kt + 1) & 1;
            const int k0 = (kt + 1) << 5;
            #pragma unroll
            for (int i = 0; i < 8; i++)
                cpa16(smaddr(&As[s * G_ASTAGE + (lr + 32 * i) * G_ASTRIDE + lc4]),
                      Ag + (size_t)(32 * i) * Kdim + k0);
            #pragma unroll
            for (int i = 0; i < 2; i++)
                cpa16(smaddr(&Bs[s * G_BSTAGE + (lr + 32 * i) * G_ASTRIDE + lc4]),
                      Wg + (size_t)(32 * i) * Kdim + k0);
            CPA_COMMIT();
        }
        const uint32_t* Ast = As + (kt & 1) * G_ASTAGE;
        const uint32_t* Bst = Bs + (kt & 1) * G_BSTAGE;
        #pragma unroll
        for (int kc = 0; kc < 4; kc++) {
            const int kb = kc * 8 + q;
            uint32_t a[4][4];
            #pragma unroll
            for (int mi = 0; mi < 4; mi++) {
                const int r = wm * 64 + mi * 16 + r8;
                a[mi][0] = Ast[r * G_ASTRIDE + kb];
                a[mi][1] = Ast[(r + 8) * G_ASTRIDE + kb];
                a[mi][2] = Ast[r * G_ASTRIDE + kb + 4];
                a[mi][3] = Ast[(r + 8) * G_ASTRIDE + kb + 4];
            }
            #pragma unroll
            for (int ni = 0; ni < 4; ni++) {
                const int n = wn * 32 + ni * 8 + r8;
                const uint32_t b0 = Bst[n * G_ASTRIDE + kb];
                const uint32_t b1 = Bst[n * G_ASTRIDE + kb + 4];
                #pragma unroll
                for (int mi = 0; mi < 4; mi++)
                    mma_tf32(acc[mi * 4 + ni], a[mi], b0, b1);
            }
        }
    }

    #pragma unroll
    for (int mi = 0; mi < 4; mi++)
        #pragma unroll
        for (int ni = 0; ni < 4; ni++) {
            const float* d = acc[mi * 4 + ni];
            const int r0g = m0 + wm * 64 + mi * 16 + r8;
            const int c   = n0 + wn * 32 + ni * 8 + 2 * q;
            const float bx = bias[c], by = bias[c + 1];
            if (OUT_TF) {
                uint32_t* C = (uint32_t*)Cout;
                uint2 o0 = { f2tf(d[0] + bx), f2tf(d[1] + by) };
                uint2 o1 = { f2tf(d[2] + bx), f2tf(d[3] + by) };
                *(uint2*)(C + (size_t)r0g * Ndim + c)       = o0;
                *(uint2*)(C + (size_t)(r0g + 8) * Ndim + c) = o1;
            } else {
                float* C = (float*)Cout;
                float2 o0 = { d[0] + bx, d[1] + by };
                float2 o1 = { d[2] + bx, d[3] + by };
                *(float2*)(C + (size_t)r0g * Ndim + c)       = o0;
                *(float2*)(C + (size_t)(r0g + 8) * Ndim + c) = o1;
            }
        }
#endif
}

// ---------------------------------------------------------------------------
extern "C" void kernel_launch(void* const* d_in, const int* in_sizes, int n_in,
                              void* d_out, int out_size)
{
    const float* x      = (const float*)d_in[0];
    const float* qkv_w  = (const float*)d_in[1];
    const float* qkv_b  = (const float*)d_in[2];
    const float* proj_w = (const float*)d_in[3];
    const float* proj_b = (const float*)d_in[4];
    float* outp = (float*)d_out;

    uint32_t *x_tf, *qw_tf, *pw_tf, *qkv, *vt, *attn;
    cudaGetSymbolAddress((void**)&x_tf,  g_x_tf);
    cudaGetSymbolAddress((void**)&qw_tf, g_qw_tf);
    cudaGetSymbolAddress((void**)&pw_tf, g_pw_tf);
    cudaGetSymbolAddress((void**)&qkv,   g_qkv);
    cudaGetSymbolAddress((void**)&vt,    g_vt);
    cudaGetSymbolAddress((void**)&attn,  g_attn);

    // 0) Pre-convert inputs to tf32 bits
    {
        const int nx = MTOT * CDIM / 4, nw = QKVN * CDIM / 4, np = CDIM * PK / 4;
        cvt_tf32_kernel<<<(nx + 255) / 256, 256>>>((const float4*)x,      (uint4*)x_tf,  nx);
        cvt_tf32_kernel<<<(nw + 255) / 256, 256>>>((const float4*)qkv_w,  (uint4*)qw_tf, nw);
        cvt_tf32_kernel<<<(np + 255) / 256, 256>>>((const float4*)proj_w, (uint4*)pw_tf, np);
    }

    cudaFuncSetAttribute(gemm_tc<true>,  cudaFuncAttributeMaxDynamicSharedMemorySize, TC_SMEM);
    cudaFuncSetAttribute(gemm_tc<false>, cudaFuncAttributeMaxDynamicSharedMemorySize, TC_SMEM);
    cudaFuncSetAttribute(gemm_fb<true>,  cudaFuncAttributeMaxDynamicSharedMemorySize, G_SMEM_BYTES);
    cudaFuncSetAttribute(gemm_fb<false>, cudaFuncAttributeMaxDynamicSharedMemorySize, G_SMEM_BYTES);
    cudaFuncSetAttribute(attn_tc, cudaFuncAttributeMaxDynamicSharedMemorySize, AT3_SMEM);
    cudaFuncSetAttribute(attn_v2, cudaFuncAttributeMaxDynamicSharedMemorySize, AT_SMEM_BYTES);

    // 1) QKV projection -> tf32 bits (exactly one path does work)
    gemm_tc<true><<<dim3(QKVN / TC_BN, MTOT / 256), 256, TC_SMEM>>>(
        x_tf, qw_tf, qkv_b, qkv, CDIM, QKVN);
    gemm_fb<true><<<dim3(QKVN / 64, MTOT / 256), 256, G_SMEM_BYTES>>>(
        x_tf, qw_tf, qkv_b, qkv, CDIM, QKVN);

    // 1b) Transpose V for the tcgen05 attention's B operand
    transpose_v_kernel<<<dim3(SEQ / 32, HDIM / 32, BDIM * NH), dim3(32, 8)>>>(qkv, vt);

    // 2) Fused attention -> tf32 bits (exactly one path does work)
    attn_tc<<<dim3(SEQ / 128, BDIM * NH), 128, AT3_SMEM>>>(qkv, vt, attn);
    attn_v2<<<dim3(SEQ / 128, BDIM * NH), 256, AT_SMEM_BYTES>>>(qkv, attn);

    // 3) Output projection -> fp32 (exactly one path does work)
    gemm_tc<false><<<dim3(CDIM / TC_BN, MTOT / 256), 256, TC_SMEM>>>(
        attn, pw_tf, proj_b, outp, PK, CDIM);
    gemm_fb<false><<<dim3(CDIM / 64, MTOT / 256), 256, G_SMEM_BYTES>>>(
        attn, pw_tf, proj_b, outp, PK, CDIM);
}

// round 16
// speedup vs baseline: 1.7377x; 1.0424x over previous
#include <cuda_runtime.h>
#include <cstdint>

#define BDIM 16
#define SEQ  1024
#define CDIM 768
#define NH   9
#define HDIM 64
#define MTOT (BDIM*SEQ)        // 16384
#define QKVN (3*NH*HDIM)       // 1728
#define PK   (NH*HDIM)         // 576

// Does THIS device-compile stage support tcgen05 (arch-/family-specific target)?
#if defined(__CUDA_ARCH__)
#  if defined(__CUDA_ARCH_FEAT_SM103_ALL) || defined(__CUDA_ARCH_FEAT_SM100_ALL) || \
      (defined(__CUDA_ARCH_FAMILY_SPECIFIC__) && (__CUDA_ARCH_FAMILY_SPECIFIC__ >= 1000))
#    define HAS_TCGEN05 1
#  else
#    define HAS_TCGEN05 0
#  endif
#else
#  define HAS_TCGEN05 0
#endif

// Scratch (device globals: allocation-free per harness rules). tf32 bit patterns.
__device__ uint32_t g_x_tf[(size_t)MTOT * CDIM];
__device__ uint32_t g_qw_tf[(size_t)QKVN * CDIM];
__device__ uint32_t g_pw_tf[(size_t)CDIM * PK];
__device__ uint32_t g_qkv[(size_t)MTOT * QKVN];
__device__ uint32_t g_vt[(size_t)BDIM * NH * HDIM * SEQ];   // V^T [b,h,d,seq]
__device__ uint32_t g_attn[(size_t)MTOT * PK];

__device__ __forceinline__ uint32_t f2tf(float f) {
    uint32_t u;
    asm("cvt.rna.tf32.f32 %0, %1;" : "=r"(u) : "f"(f));
    return u;
}
__device__ __forceinline__ void mma_tf32(float* d, const uint32_t* a,
                                         uint32_t b0, uint32_t b1) {
    asm volatile(
        "mma.sync.aligned.m16n8k8.row.col.f32.tf32.tf32.f32 "
        "{%0,%1,%2,%3},{%4,%5,%6,%7},{%8,%9},{%0,%1,%2,%3};\n"
        : "+f"(d[0]), "+f"(d[1]), "+f"(d[2]), "+f"(d[3])
        : "r"(a[0]), "r"(a[1]), "r"(a[2]), "r"(a[3]), "r"(b0), "r"(b1));
}
__device__ __forceinline__ uint32_t smaddr(const void* p) {
    return (uint32_t)__cvta_generic_to_shared(p);
}
__device__ __forceinline__ void cpa16(uint32_t s, const void* g) {
    asm volatile("cp.async.cg.shared.global [%0], [%1], 16;" :: "r"(s), "l"(g));
}
#define CPA_COMMIT() asm volatile("cp.async.commit_group;")
#define CPA_WAIT0()  asm volatile("cp.async.wait_group 0;")
#define CPA_WAIT1()  asm volatile("cp.async.wait_group 1;")
#define SWZ128(x) ((x) ^ (((x) >> 3) & 0x70))

// ---------------------------------------------------------------------------
__global__ void cvt_tf32_kernel(const float4* __restrict__ in,
                                uint4* __restrict__ out, int n4) {
    const int i = blockIdx.x * blockDim.x + threadIdx.x;
    if (i < n4) {
        float4 v = in[i];
        uint4 o = { f2tf(v.x), f2tf(v.y), f2tf(v.z), f2tf(v.w) };
        out[i] = o;
    }
}

#if HAS_TCGEN05
__device__ __forceinline__ uint32_t elect_one_pred() {
    uint32_t pred;
    asm volatile("{\n\t.reg .pred p;\n\telect.sync _|p, 0xFFFFFFFF;\n\t"
                 "selp.b32 %0, 1, 0, p;\n\t}" : "=r"(pred));
    return pred;
}
#define TC_ALLOC(sm_res, n) \
    asm volatile("tcgen05.alloc.cta_group::1.sync.aligned.shared::cta.b32 [%0], %1;" \
                 :: "r"((uint32_t)(sm_res)), "r"((uint32_t)(n)) : "memory")
#define TC_RELINQ() \
    asm volatile("tcgen05.relinquish_alloc_permit.cta_group::1.sync.aligned;")
#define TC_DEALLOC(tm, n) \
    asm volatile("tcgen05.dealloc.cta_group::1.sync.aligned.b32 %0, %1;" :: "r"(tm), "r"((uint32_t)(n)))
#define TC_COMMIT(mb) \
    asm volatile("tcgen05.commit.cta_group::1.mbarrier::arrive::one.shared::cluster.b64 [%0];" \
                 :: "r"((uint32_t)(mb)) : "memory")
#define TC_FENCE_AFTER()  asm volatile("tcgen05.fence::after_thread_sync;" ::: "memory")
#define TC_FENCE_BEFORE() asm volatile("tcgen05.fence::before_thread_sync;" ::: "memory")
#define TC_WAIT_LD() asm volatile("tcgen05.wait::ld.sync.aligned;" ::: "memory")
#define TC_WAIT_ST() asm volatile("tcgen05.wait::st.sync.aligned;" ::: "memory")
#define MBAR_INIT(mb, c) \
    asm volatile("mbarrier.init.shared.b64 [%0], %1;" :: "r"((uint32_t)(mb)), "r"((uint32_t)(c)) : "memory")
#define MBAR_WAIT(mb, par) do { \
    uint32_t _m = (uint32_t)(mb), _p = (uint32_t)(par), _d; \
    asm volatile("{\n\t.reg .pred p;\n\t" \
        "mbarrier.try_wait.parity.acquire.cta.shared::cta.b64 p, [%1], %2;\n\t" \
        "selp.b32 %0, 1, 0, p;\n\t}" : "=r"(_d) : "r"(_m), "r"(_p) : "memory"); \
    if (!_d) { \
        asm volatile("{\n\t.reg .pred P1;\n\tWL_%=:\n\t" \
            "mbarrier.try_wait.parity.acquire.cta.shared::cta.b64 P1, [%0], %1, 0x989680;\n\t" \
            "@P1 bra.uni WD_%=;\n\tbra.uni WL_%=;\n\tWD_%=:\n\t}" \
            :: "r"(_m), "r"(_p) : "memory"); \
    } } while (0)

__device__ __forceinline__ void tc_mma_tf32_ss(uint32_t d_tmem, uint64_t ad,
                                               uint64_t bd, uint32_t idesc,
                                               uint32_t en) {
    asm volatile(
        "{\n\t.reg .pred p;\n\tsetp.ne.u32 p, %4, 0;\n\t"
        "tcgen05.mma.cta_group::1.kind::tf32 [%0], %1, %2, %3, p;\n\t}"
        :: "r"(d_tmem), "l"(ad), "l"(bd), "r"(idesc), "r"(en) : "memory");
}
__device__ __forceinline__ void tc_mma_tf32_ts(uint32_t d_tmem, uint32_t a_tmem,
                                               uint64_t bd, uint32_t idesc,
                                               uint32_t en) {
    asm volatile(
        "{\n\t.reg .pred p;\n\tsetp.ne.u32 p, %4, 0;\n\t"
        "tcgen05.mma.cta_group::1.kind::tf32 [%0], [%1], %2, %3, p;\n\t}"
        :: "r"(d_tmem), "r"(a_tmem), "l"(bd), "r"(idesc), "r"(en) : "memory");
}
#define TC_LD32(r, ta) \
    asm volatile( \
        "tcgen05.ld.sync.aligned.32x32b.x32.b32 " \
        "{%0,%1,%2,%3,%4,%5,%6,%7,%8,%9,%10,%11,%12,%13,%14,%15," \
        "%16,%17,%18,%19,%20,%21,%22,%23,%24,%25,%26,%27,%28,%29,%30,%31},[%32];" \
        : "=r"((r)[0]), "=r"((r)[1]), "=r"((r)[2]), "=r"((r)[3]), "=r"((r)[4]), \
          "=r"((r)[5]), "=r"((r)[6]), "=r"((r)[7]), "=r"((r)[8]), "=r"((r)[9]), \
          "=r"((r)[10]), "=r"((r)[11]), "=r"((r)[12]), "=r"((r)[13]), "=r"((r)[14]), \
          "=r"((r)[15]), "=r"((r)[16]), "=r"((r)[17]), "=r"((r)[18]), "=r"((r)[19]), \
          "=r"((r)[20]), "=r"((r)[21]), "=r"((r)[22]), "=r"((r)[23]), "=r"((r)[24]), \
          "=r"((r)[25]), "=r"((r)[26]), "=r"((r)[27]), "=r"((r)[28]), "=r"((r)[29]), \
          "=r"((r)[30]), "=r"((r)[31]) \
        : "r"(ta))
#define TC_ST32(ta, r) \
    asm volatile( \
        "tcgen05.st.sync.aligned.32x32b.x32.b32 [%0], " \
        "{%1,%2,%3,%4,%5,%6,%7,%8,%9,%10,%11,%12,%13,%14,%15,%16," \
        "%17,%18,%19,%20,%21,%22,%23,%24,%25,%26,%27,%28,%29,%30,%31,%32};" \
        :: "r"(ta), \
           "r"((r)[0]), "r"((r)[1]), "r"((r)[2]), "r"((r)[3]), "r"((r)[4]), \
           "r"((r)[5]), "r"((r)[6]), "r"((r)[7]), "r"((r)[8]), "r"((r)[9]), \
           "r"((r)[10]), "r"((r)[11]), "r"((r)[12]), "r"((r)[13]), "r"((r)[14]), \
           "r"((r)[15]), "r"((r)[16]), "r"((r)[17]), "r"((r)[18]), "r"((r)[19]), \
           "r"((r)[20]), "r"((r)[21]), "r"((r)[22]), "r"((r)[23]), "r"((r)[24]), \
           "r"((r)[25]), "r"((r)[26]), "r"((r)[27]), "r"((r)[28]), "r"((r)[29]), \
           "r"((r)[30]), "r"((r)[31]) \
        : "memory")
__device__ __forceinline__ uint64_t mk_desc(uint32_t addr) {
    return ((uint64_t)2 << 61) | ((uint64_t)1 << 46) | ((uint64_t)64 << 32)
         | ((uint64_t)1 << 16) | (uint64_t)((addr >> 4) & 0x3FFF);
}
#endif // HAS_TCGEN05

// ===========================================================================
// tcgen05 tf32 GEMM (R14-proven): BM=256, BN=192, 3-stage ring, 256 thr.
// NEW: V-tiles of gemm1 (n0 >= 1152, vtout != null) store TRANSPOSED into
// g_vt from the epilogue — transpose_v kernel deleted.
// ===========================================================================
#define TC_BN 192
#define G_ASTG 32768
#define G_BSTG (TC_BN*128)
#define OFF_A0 1024
#define OFF_B0 (OFF_A0 + 3*G_ASTG)
#define TC_SMEM (OFF_B0 + 3*G_BSTG)
#if HAS_TCGEN05
#define TC_IDESC ((1u<<4) | (2u<<7) | (2u<<10) | ((TC_BN/8)<<17) | (8u<<24))
#endif

template <bool OUT_TF>
__global__ __launch_bounds__(256) void gemm_tc(
    const uint32_t* __restrict__ A, const uint32_t* __restrict__ W,
    const float* __restrict__ bias, void* __restrict__ Cout,
    uint32_t* __restrict__ vtout,
    int Kdim, int Ndim)
{
#if HAS_TCGEN05
    extern __shared__ char smem[];
    const uint32_t sbase = smaddr(smem);
    const int t = threadIdx.x, lane = t & 31, warp = t >> 5;
    const int m0 = blockIdx.y * 256, n0 = blockIdx.x * TC_BN;
    const uint32_t mb0 = sbase + 8, mb1 = sbase + 16;

    if (warp == 0) { TC_ALLOC(sbase, 512); TC_RELINQ(); }
    if (t == 0) { MBAR_INIT(mb0, 1); MBAR_INIT(mb1, 1); }
    __syncthreads();
    uint32_t tmem;
    asm volatile("ld.shared.b32 %0, [%1];" : "=r"(tmem) : "r"(sbase));

    const int KT = Kdim >> 5;

    auto loadA = [&](int st, int k0) {
        const uint32_t base = sbase + OFF_A0 + st * G_ASTG;
        #pragma unroll
        for (int i = 0; i < 8; i++) {
            const int idx = t + 256 * i, row = idx >> 3, ch = idx & 7;
            cpa16(base + (uint32_t)((row >> 3) << 10)
                       + SWZ128((uint32_t)(((row & 7) << 7) + ch * 16)),
                  A + (size_t)(m0 + row) * Kdim + k0 + ch * 4);
        }
    };
    auto loadB = [&](int st, int k0) {
        const uint32_t base = sbase + OFF_B0 + st * G_BSTG;
        #pragma unroll
        for (int i = 0; i < 6; i++) {
            const int idx = t + 256 * i, row = idx >> 3, ch = idx & 7;
            cpa16(base + (uint32_t)((row >> 3) << 10)
                       + SWZ128((uint32_t)(((row & 7) << 7) + ch * 16)),
                  W + (size_t)(n0 + row) * Kdim + k0 + ch * 4);
        }
    };

    loadA(0, 0); loadB(0, 0); CPA_COMMIT();
    loadA(1, 32); loadB(1, 32); CPA_COMMIT();
    int pw0 = 0, pw1 = 0;

    for (int kt = 0; kt < KT; kt++) {
        CPA_WAIT1();
        asm volatile("fence.proxy.async.shared::cta;" ::: "memory");
        __syncthreads();
        if (warp == 0 && elect_one_pred()) {
            const int st = kt % 3;
            const uint32_t abase = sbase + OFF_A0 + st * G_ASTG;
            const uint64_t ad0 = mk_desc(abase);
            const uint64_t ad1 = mk_desc(abase + 16384);
            const uint64_t bd  = mk_desc(sbase + OFF_B0 + st * G_BSTG);
            const uint32_t en = (kt > 0) ? 1u : 0u;
            #pragma unroll
            for (int s = 0; s < 4; s++) {
                const uint32_t e = (en || s > 0) ? 1u : 0u;
                tc_mma_tf32_ss(tmem,          ad0 + 2 * s, bd + 2 * s, TC_IDESC, e);
                tc_mma_tf32_ss(tmem + TC_BN,  ad1 + 2 * s, bd + 2 * s, TC_IDESC, e);
            }
            TC_COMMIT((kt & 1) ? mb1 : mb0);
        }
        if (kt >= 1) {
            if ((kt - 1) & 1) { MBAR_WAIT(mb1, pw1 & 1); pw1++; }
            else              { MBAR_WAIT(mb0, pw0 & 1); pw0++; }
        }
        if (kt + 2 < KT) {
            loadA((kt + 2) % 3, (kt + 2) * 32);
            loadB((kt + 2) % 3, (kt + 2) * 32);
        }
        CPA_COMMIT();
    }
    if ((KT - 1) & 1) { MBAR_WAIT(mb1, pw1 & 1); }
    else              { MBAR_WAIT(mb0, pw0 & 1); }
    TC_FENCE_AFTER();

    const int row = m0 + (warp >> 2) * 128 + (warp & 3) * 32 + lane;
    const uint32_t dbase = tmem + (warp >> 2) * TC_BN;
    const bool vtile = OUT_TF && (vtout != nullptr) && (n0 >= 2 * NH * HDIM);
    const int bb = row >> 10, nn = row & 1023;   // token coords (SEQ=1024)
    #pragma unroll
    for (int cc = 0; cc < TC_BN; cc += 32) {
        uint32_t dr[32];
        TC_LD32(dr, dbase + cc);
        TC_WAIT_LD();
        #pragma unroll
        for (int j = 0; j < 32; j += 4) {
            const int c = n0 + cc + j;
            float v0 = __uint_as_float(dr[j])     + bias[c];
            float v1 = __uint_as_float(dr[j + 1]) + bias[c + 1];
            float v2 = __uint_as_float(dr[j + 2]) + bias[c + 2];
            float v3 = __uint_as_float(dr[j + 3]) + bias[c + 3];
            if (vtile) {
                // transposed store into g_vt[(b*NH+h)*HDIM + d][n]
                const int vd = c - 2 * NH * HDIM;          // 0..575
                const uint32_t tf[4] = { f2tf(v0), f2tf(v1), f2tf(v2), f2tf(v3) };
                #pragma unroll
                for (int e = 0; e < 4; e++) {
                    const int h = (vd + e) >> 6, d = (vd + e) & 63;
                    vtout[((size_t)(bb * NH + h) * HDIM + d) * SEQ + nn] = tf[e];
                }
            } else if (OUT_TF) {
                uint4 o = { f2tf(v0), f2tf(v1), f2tf(v2), f2tf(v3) };
                *(uint4*)((uint32_t*)Cout + (size_t)row * Ndim + c) = o;
            } else {
                float4 o = { v0, v1, v2, v3 };
                *(float4*)((float*)Cout + (size_t)row * Ndim + c) = o;
            }
        }
    }
    __syncthreads();
    if (warp == 0) TC_DEALLOC(tmem, 512);
#endif
}

// ===========================================================================
// tcgen05 fused attention v5: 256 threads, column-split softmax.
// Serial MMA chain (R13/R14-proven mbarrier discipline). Warp w: subpartition
// sp=w&3 (rows sp*32+lane), column-half ch=w>>2 (cols ch*32..+32). Per-thread
// l is a column-half partial, combined once at epilogue via smem.
// TMEM: O 0-63, S0 64-127, S1 128-191 (alloc 256; 2 CTAs/SM).
// ===========================================================================
#define AT3_Q   1024
#define AT3_K0  (AT3_Q  + 32768)
#define AT3_K1  (AT3_K0 + 16384)
#define AT3_V0  (AT3_K1 + 16384)
#define AT3_V1  (AT3_V0 + 16384)
#define AT3_SMEM (AT3_V1 + 16384)
#if HAS_TCGEN05
#define AT_IDESC ((1u<<4) | (2u<<7) | (2u<<10) | (8u<<17) | (8u<<24))
__device__ __forceinline__ uint32_t blk_off(int r, int cb, int atomrows) {
    const uint32_t local = (uint32_t)(((r & 7) << 7) | (cb & 127));
    const uint32_t atom = (uint32_t)((r >> 3) + ((cb >> 7) * atomrows));
    return (atom << 10) + SWZ128(local);
}
#endif

__global__ __launch_bounds__(256) void attn_tc(
    const uint32_t* __restrict__ qkv, const uint32_t* __restrict__ vt,
    uint32_t* __restrict__ outp)
{
#if HAS_TCGEN05
    extern __shared__ char smem[];
    const uint32_t sbase = smaddr(smem);
    const int t = threadIdx.x, lane = t & 31, warp = t >> 5;
    const int sp = warp & 3, chh = warp >> 2;
    const int bh = blockIdx.y, b = bh / NH, h = bh % NH;
    const int q0 = blockIdx.x * 128;
    const uint32_t mbS = sbase + 8, mbPV = sbase + 16;
    float* lsh = (float*)(smem + 32);          // [128] row-sum combine
    const uint32_t woff = (uint32_t)sp << 21;

    const uint32_t* Qg = qkv + (size_t)b * SEQ * QKVN + h * HDIM;
    const uint32_t* Kg = Qg + NH * HDIM;
    const uint32_t* Vt = vt + (size_t)bh * HDIM * SEQ;   // [d][seq]

    if (warp == 0) { TC_ALLOC(sbase, 256); TC_RELINQ(); }
    if (t == 0) { MBAR_INIT(mbS, 1); MBAR_INIT(mbPV, 1); }
    __syncthreads();
    uint32_t tmem;
    asm volatile("ld.shared.b32 %0, [%1];" : "=r"(tmem) : "r"(sbase));
    const uint32_t tO = tmem;
    const uint32_t tSb[2] = { tmem + 64, tmem + 128 };
    const uint32_t KST[2] = { sbase + AT3_K0, sbase + AT3_K1 };
    const uint32_t VST[2] = { sbase + AT3_V0, sbase + AT3_V1 };

    auto loadK = [&](int st, int j0) {   // 64 rows x 256B (256 thr: 4 cpa)
        #pragma unroll
        for (int i = 0; i < 4; i++) {
            const int c = t + 256 * i, row = c >> 4, cb = (c & 15) * 16;
            cpa16(KST[st] + blk_off(row, cb, 8),
                  Kg + (size_t)(j0 + row) * QKVN + (cb >> 2));
        }
    };
    auto loadV = [&](int st, int j0) {
        #pragma unroll
        for (int i = 0; i < 4; i++) {
            const int c = t + 256 * i, row = c >> 4, cb = (c & 15) * 16;
            cpa16(VST[st] + blk_off(row, cb, 8),
                  Vt + (size_t)row * SEQ + j0 + (cb >> 2));
        }
    };

    #pragma unroll
    for (int i = 0; i < 8; i++) {
        const int c = t + 256 * i, row = c >> 4, cb = (c & 15) * 16;
        cpa16(sbase + AT3_Q + blk_off(row, cb, 16),
              Qg + (size_t)(q0 + row) * QKVN + (cb >> 2));
    }
    loadK(0, 0); loadV(0, 0); CPA_COMMIT();
    loadK(1, 64); CPA_COMMIT();

    const uint64_t qdesc = mk_desc(sbase + AT3_Q);
    const uint32_t QSTEP[8] = {0, 2, 4, 6, 1024, 1026, 1028, 1030};
    const uint32_t KSTEP[8] = {0, 2, 4, 6, 512, 514, 516, 518};

    CPA_WAIT1();
    asm volatile("fence.proxy.async.shared::cta;" ::: "memory");
    __syncthreads();
    if (warp == 0 && elect_one_pred()) {
        const uint64_t kd = mk_desc(KST[0]);
        #pragma unroll
        for (int s = 0; s < 8; s++)
            tc_mma_tf32_ss(tSb[0], qdesc + QSTEP[s], kd + KSTEP[s],
                           AT_IDESC, s > 0 ? 1u : 0u);
        TC_COMMIT(mbS);
    }

    const int r0 = sp * 32 + lane;         // this thread's q-row
    float l = 0.f;                         // column-half partial
    const float cexp = 0.18033688f;        // 0.125 * log2(e)

    for (int jt = 0; jt < 16; jt++) {
        MBAR_WAIT(mbS, jt & 1);
        TC_FENCE_AFTER();

        if (jt + 2 < 16) loadK(jt & 1, (jt + 2) * 64);
        if (jt + 1 < 16) loadV((jt + 1) & 1, (jt + 1) * 64);
        CPA_COMMIT();
        CPA_WAIT1();
        asm volatile("fence.proxy.async.shared::cta;" ::: "memory");
        __syncthreads();

        // softmax(jt): warp handles 32 cols [chh*32, +32) of its 32 rows
        const uint32_t tS = tSb[jt & 1];
        {
            uint32_t sr[32];
            TC_LD32(sr, tS + chh * 32);
            TC_WAIT_LD();
            #pragma unroll
            for (int i = 0; i < 32; i++) {
                const float p = exp2f(__uint_as_float(sr[i]) * cexp);
                l += p;
                sr[i] = f2tf(p);
            }
            TC_ST32(tS + chh * 32 + woff, sr);
            TC_WAIT_ST();
        }
        TC_FENCE_BEFORE();
        __syncthreads();

        // issue PV(jt) then S(jt+1) back-to-back (in-order queue)
        if (warp == 0 && elect_one_pred()) {
            TC_FENCE_AFTER();
            const uint64_t vd = mk_desc(VST[jt & 1]);
            #pragma unroll
            for (int s = 0; s < 8; s++)
                tc_mma_tf32_ts(tO, tS + 8 * s, vd + KSTEP[s],
                               AT_IDESC, (jt > 0 || s > 0) ? 1u : 0u);
            if (jt == 15) {
                TC_COMMIT(mbPV);
            } else {
                const uint64_t kd = mk_desc(KST[(jt + 1) & 1]);
                #pragma unroll
                for (int s = 0; s < 8; s++)
                    tc_mma_tf32_ss(tSb[(jt + 1) & 1], qdesc + QSTEP[s],
                                   kd + KSTEP[s], AT_IDESC, s > 0 ? 1u : 0u);
                TC_COMMIT(mbS);
            }
        }
    }

    // combine l halves: warps 0-3 write, warps 4-7 add, all read
    if (chh == 0) lsh[r0] = l;
    __syncthreads();
    if (chh == 1) lsh[r0] += l;
    MBAR_WAIT(mbPV, 0);
    __syncthreads();
    TC_FENCE_AFTER();
    const float inv = 1.0f / lsh[r0];
    uint32_t* ob = outp + (size_t)(b * SEQ + q0 + r0) * PK + h * HDIM + chh * 32;
    {
        uint32_t orr[32];
        TC_LD32(orr, tO + chh * 32);
        TC_WAIT_LD();
        #pragma unroll
        for (int j = 0; j < 32; j += 4) {
            uint4 o = { f2tf(__uint_as_float(orr[j])     * inv),
                        f2tf(__uint_as_float(orr[j + 1]) * inv),
                        f2tf(__uint_as_float(orr[j + 2]) * inv),
                        f2tf(__uint_as_float(orr[j + 3]) * inv) };
            *(uint4*)(ob + j) = o;
        }
    }
    __syncthreads();
    if (warp == 0) TC_DEALLOC(tmem, 256);
#endif
}

// ===========================================================================
// Fallback attention (R6-proven mma.sync) — only in base-target stages.
// ===========================================================================
#define AT_KSTAGE (64 * 68)
#define AT_VSTAGE (64 * 72)
#define AT_SMEM_BYTES ((128 * 68 + 2 * AT_KSTAGE + 2 * AT_VSTAGE) * 4)

__global__ __launch_bounds__(256, 2) void attn_v2(
    const uint32_t* __restrict__ qkv, uint32_t* __restrict__ outp)
{
#if !HAS_TCGEN05
    extern __shared__ uint32_t sm[];
    uint32_t* Qs = sm;
    uint32_t* Ks = Qs + 128 * 68;
    uint32_t* Vs = Ks + 2 * AT_KSTAGE;

    const int t = threadIdx.x, lane = t & 31, warp = t >> 5;
    const int q = lane & 3, r8 = lane >> 2;
    const int bh = blockIdx.y, b = bh / NH, h = bh % NH;
    const int q0 = blockIdx.x * 128;
    const float scale = 0.125f;

    const uint32_t* Qg = qkv + (size_t)b * SEQ * QKVN + h * HDIM;
    const uint32_t* Kg = Qg + NH * HDIM;
    const uint32_t* Vg = Qg + 2 * NH * HDIM;
    const int r0 = warp * 16 + r8;
    const int c4 = (t & 15) * 4, rb = t >> 4;

    {
        #pragma unroll
        for (int i = 0; i < 8; i++) {
            const int r = rb + 16 * i;
            cpa16(smaddr(&Qs[r * 68 + c4]), Qg + (size_t)(q0 + r) * QKVN + c4);
        }
        #pragma unroll
        for (int i = 0; i < 4; i++) {
            const int r = rb + 16 * i;
            cpa16(smaddr(&Ks[r * 68 + c4]), Kg + (size_t)r * QKVN + c4);
            cpa16(smaddr(&Vs[r * 72 + c4]), Vg + (size_t)r * QKVN + c4);
        }
        CPA_COMMIT();
    }

    float O[8][4] = {};
    float m0 = -1e30f, m1 = -1e30f, l0 = 0.f, l1 = 0.f;
    const int src1 = (lane & 28) | (q >> 1);
    const int src2 = src1 | 2;

    for (int jt = 0; jt < SEQ / 64; jt++) {
        CPA_WAIT0();
        __syncthreads();
        if (jt + 1 < SEQ / 64) {
            const int s = (jt + 1) & 1;
            const int j0 = (jt + 1) * 64;
            #pragma unroll
            for (int i = 0; i < 4; i++) {
                const int r = rb + 16 * i;
                cpa16(smaddr(&Ks[s * AT_KSTAGE + r * 68 + c4]),
                      Kg + (size_t)(j0 + r) * QKVN + c4);
                cpa16(smaddr(&Vs[s * AT_VSTAGE + r * 72 + c4]),
                      Vg + (size_t)(j0 + r) * QKVN + c4);
            }
            CPA_COMMIT();
        }
        const uint32_t* Kst = Ks + (jt & 1) * AT_KSTAGE;
        const uint32_t* Vst = Vs + (jt & 1) * AT_VSTAGE;

        float s[8][4] = {};
        #pragma unroll
        for (int kc = 0; kc < 8; kc++) {
            const int kb = kc * 8 + q;
            uint32_t a[4];
            a[0] = Qs[r0 * 68 + kb];     a[1] = Qs[(r0 + 8) * 68 + kb];
            a[2] = Qs[r0 * 68 + kb + 4]; a[3] = Qs[(r0 + 8) * 68 + kb + 4];
            #pragma unroll
            for (int ni = 0; ni < 8; ni++) {
                const int n = ni * 8 + r8;
                mma_tf32(s[ni], a, Kst[n * 68 + kb], Kst[n * 68 + kb + 4]);
            }
        }

        float mx0 = -1e30f, mx1 = -1e30f;
        #pragma unroll
        for (int ni = 0; ni < 8; ni++) {
            s[ni][0] *= scale; s[ni][1] *= scale;
            s[ni][2] *= scale; s[ni][3] *= scale;
            mx0 = fmaxf(mx0, fmaxf(s[ni][0], s[ni][1]));
            mx1 = fmaxf(mx1, fmaxf(s[ni][2], s[ni][3]));
        }
        mx0 = fmaxf(mx0, __shfl_xor_sync(0xffffffffu, mx0, 1));
        mx0 = fmaxf(mx0, __shfl_xor_sync(0xffffffffu, mx0, 2));
        mx1 = fmaxf(mx1, __shfl_xor_sync(0xffffffffu, mx1, 1));
        mx1 = fmaxf(mx1, __shfl_xor_sync(0xffffffffu, mx1, 2));
        const float mn0 = fmaxf(m0, mx0), mn1 = fmaxf(m1, mx1);
        const float al0 = __expf(m0 - mn0), al1 = __expf(m1 - mn1);
        m0 = mn0; m1 = mn1;
        float sum0 = 0.f, sum1 = 0.f;
        #pragma unroll
        for (int ni = 0; ni < 8; ni++) {
            s[ni][0] = __expf(s[ni][0] - mn0); sum0 += s[ni][0];
            s[ni][1] = __expf(s[ni][1] - mn0); sum0 += s[ni][1];
            s[ni][2] = __expf(s[ni][2] - mn1); sum1 += s[ni][2];
            s[ni][3] = __expf(s[ni][3] - mn1); sum1 += s[ni][3];
        }
        sum0 += __shfl_xor_sync(0xffffffffu, sum0, 1);
        sum0 += __shfl_xor_sync(0xffffffffu, sum0, 2);
        sum1 += __shfl_xor_sync(0xffffffffu, sum1, 1);
        sum1 += __shfl_xor_sync(0xffffffffu, sum1, 2);
        l0 = l0 * al0 + sum0;
        l1 = l1 * al1 + sum1;
        #pragma unroll
        for (int ni = 0; ni < 8; ni++) {
            O[ni][0] *= al0; O[ni][1] *= al0;
            O[ni][2] *= al1; O[ni][3] *= al1;
        }

        #pragma unroll
        for (int kc = 0; kc < 8; kc++) {
            const float v0 = __shfl_sync(0xffffffffu, s[kc][0], src1);
            const float v1 = __shfl_sync(0xffffffffu, s[kc][1], src1);
            const float v2 = __shfl_sync(0xffffffffu, s[kc][2], src1);
            const float v3 = __shfl_sync(0xffffffffu, s[kc][3], src1);
            const float w0 = __shfl_sync(0xffffffffu, s[kc][0], src2);
            const float w1 = __shfl_sync(0xffffffffu, s[kc][1], src2);
            const float w2 = __shfl_sync(0xffffffffu, s[kc][2], src2);
            const float w3 = __shfl_sync(0xffffffffu, s[kc][3], src2);
            const bool odd = (q & 1);
            uint32_t a[4];
            a[0] = f2tf(odd ? v1 : v0);
            a[1] = f2tf(odd ? v3 : v2);
            a[2] = f2tf(odd ? w1 : w0);
            a[3] = f2tf(odd ? w3 : w2);
            const int kb = kc * 8 + q;
            #pragma unroll
            for (int ni = 0; ni < 8; ni++) {
                const int dv = ni * 8 + r8;
                mma_tf32(O[ni], a, Vst[kb * 72 + dv], Vst[(kb + 4) * 72 + dv]);
            }
        }
    }

    const float inv0 = 1.0f / l0, inv1 = 1.0f / l1;
    uint32_t* ob = outp + (size_t)(b * SEQ + q0) * PK + h * HDIM;
    #pragma unroll
    for (int ni = 0; ni < 8; ni++) {
        const int c = ni * 8 + 2 * q;
        uint2 o0 = { f2tf(O[ni][0] * inv0), f2tf(O[ni][1] * inv0) };
        uint2 o1 = { f2tf(O[ni][2] * inv1), f2tf(O[ni][3] * inv1) };
        *(uint2*)(ob + (size_t)r0 * PK + c)       = o0;
        *(uint2*)(ob + (size_t)(r0 + 8) * PK + c) = o1;
    }
#endif
}

// ===========================================================================
// Fallback GEMM (R6-proven mma.sync) — only in base-target stages.
// ===========================================================================
#define G_ASTRIDE 36
#define G_ASTAGE  (256 * G_ASTRIDE)
#define G_FBSTAGE (64 * G_ASTRIDE)
#define G_SMEM_BYTES ((2 * G_ASTAGE + 2 * G_FBSTAGE) * 4)

template <bool OUT_TF>
__global__ __launch_bounds__(256, 2) void gemm_fb(
    const uint32_t* __restrict__ A, const uint32_t* __restrict__ W,
    const float* __restrict__ bias, void* __restrict__ Cout,
    uint32_t* __restrict__ vtout,
    int Kdim, int Ndim)
{
#if !HAS_TCGEN05
    extern __shared__ uint32_t dsm[];
    uint32_t* As = dsm;
    uint32_t* Bs = dsm + 2 * G_ASTAGE;

    const int t = threadIdx.x, lane = t & 31, warp = t >> 5;
    const int wm = warp >> 1, wn = warp & 1;
    const int q = lane & 3, r8 = lane >> 2;
    const int m0 = blockIdx.y * 256, n0 = blockIdx.x * 64;
    const int lr = t >> 3, lc4 = (t & 7) * 4;
    const int KT = Kdim >> 5;
    (void)vtout;

    float acc[16][4] = {};

    const uint32_t* Ag = A + (size_t)(m0 + lr) * Kdim + lc4;
    const uint32_t* Wg = W + (size_t)(n0 + lr) * Kdim + lc4;

    {
        #pragma unroll
        for (int i = 0; i < 8; i++)
            cpa16(smaddr(&As[(lr + 32 * i) * G_ASTRIDE + lc4]),
                  Ag + (size_t)(32 * i) * Kdim);
        #pragma unroll
        for (int i = 0; i < 2; i++)
            cpa16(smaddr(&Bs[(lr + 32 * i) * G_ASTRIDE + lc4]),
                  Wg + (size_t)(32 * i) * Kdim);
        CPA_COMMIT();
    }

    for (int kt = 0; kt < KT; kt++) {
        CPA_WAIT0();
        __syncthreads();
        if (kt + 1 < KT) {
            const int s = (kt + 1) & 1;
            const int k0 = (kt + 1) << 5;
            #pragma unroll
            for (int i = 0; i < 8; i++)
                cpa16(smaddr(&As[s * G_ASTAGE + (lr + 32 * i) * G_ASTRIDE + lc4]),
                      Ag + (size_t)(32 * i) * Kdim + k0);
            #pragma unroll
            for (int i = 0; i < 2; i++)
                cpa16(smaddr(&Bs[s * G_FBSTAGE + (lr + 32 * i) * G_ASTRIDE + lc4]),
                      Wg + (size_t)(32 * i) * Kdim + k0);
            CPA_COMMIT();
        }
        const uint32_t* Ast = As + (kt & 1) * G_ASTAGE;
        const uint32_t* Bst = Bs + (kt & 1) * G_FBSTAGE;
        #pragma unroll
        for (int kc = 0; kc < 4; kc++) {
            const int kb = kc * 8 + q;
            uint32_t a[4][4];
            #pragma unroll
            for (int mi = 0; mi < 4; mi++) {
                const int r = wm * 64 + mi * 16 + r8;
                a[mi][0] = Ast[r * G_ASTRIDE + kb];
                a[mi][1] = Ast[(r + 8) * G_ASTRIDE + kb];
                a[mi][2] = Ast[r * G_ASTRIDE + kb + 4];
                a[mi][3] = Ast[(r + 8) * G_ASTRIDE + kb + 4];
            }
            #pragma unroll
            for (int ni = 0; ni < 4; ni++) {
                const int n = wn * 32 + ni * 8 + r8;
                const uint32_t b0 = Bst[n * G_ASTRIDE + kb];
                const uint32_t b1 = Bst[n * G_ASTRIDE + kb + 4];
                #pragma unroll
                for (int mi = 0; mi < 4; mi++)
                    mma_tf32(acc[mi * 4 + ni], a[mi], b0, b1);
            }
        }
    }

    #pragma unroll
    for (int mi = 0; mi < 4; mi++)
        #pragma unroll
        for (int ni = 0; ni < 4; ni++) {
            const float* d = acc[mi * 4 + ni];
            const int r0g = m0 + wm * 64 + mi * 16 + r8;
            const int c   = n0 + wn * 32 + ni * 8 + 2 * q;
            const float bx = bias[c], by = bias[c + 1];
            if (OUT_TF) {
                uint32_t* C = (uint32_t*)Cout;
                uint2 o0 = { f2tf(d[0] + bx), f2tf(d[1] + by) };
                uint2 o1 = { f2tf(d[2] + bx), f2tf(d[3] + by) };
                *(uint2*)(C + (size_t)r0g * Ndim + c)       = o0;
                *(uint2*)(C + (size_t)(r0g + 8) * Ndim + c) = o1;
            } else {
                float* C = (float*)Cout;
                float2 o0 = { d[0] + bx, d[1] + by };
                float2 o1 = { d[2] + bx, d[3] + by };
                *(float2*)(C + (size_t)r0g * Ndim + c)       = o0;
                *(float2*)(C + (size_t)(r0g + 8) * Ndim + c) = o1;
            }
        }
#endif
}

// ---------------------------------------------------------------------------
extern "C" void kernel_launch(void* const* d_in, const int* in_sizes, int n_in,
                              void* d_out, int out_size)
{
    const float* x      = (const float*)d_in[0];
    const float* qkv_w  = (const float*)d_in[1];
    const float* qkv_b  = (const float*)d_in[2];
    const float* proj_w = (const float*)d_in[3];
    const float* proj_b = (const float*)d_in[4];
    float* outp = (float*)d_out;

    uint32_t *x_tf, *qw_tf, *pw_tf, *qkv, *vt, *attn;
    cudaGetSymbolAddress((void**)&x_tf,  g_x_tf);
    cudaGetSymbolAddress((void**)&qw_tf, g_qw_tf);
    cudaGetSymbolAddress((void**)&pw_tf, g_pw_tf);
    cudaGetSymbolAddress((void**)&qkv,   g_qkv);
    cudaGetSymbolAddress((void**)&vt,    g_vt);
    cudaGetSymbolAddress((void**)&attn,  g_attn);

    // 0) Pre-convert inputs to tf32 bits
    {
        const int nx = MTOT * CDIM / 4, nw = QKVN * CDIM / 4, np = CDIM * PK / 4;
        cvt_tf32_kernel<<<(nx + 255) / 256, 256>>>((const float4*)x,      (uint4*)x_tf,  nx);
        cvt_tf32_kernel<<<(nw + 255) / 256, 256>>>((const float4*)qkv_w,  (uint4*)qw_tf, nw);
        cvt_tf32_kernel<<<(np + 255) / 256, 256>>>((const float4*)proj_w, (uint4*)pw_tf, np);
    }

    cudaFuncSetAttribute(gemm_tc<true>,  cudaFuncAttributeMaxDynamicSharedMemorySize, TC_SMEM);
    cudaFuncSetAttribute(gemm_tc<false>, cudaFuncAttributeMaxDynamicSharedMemorySize, TC_SMEM);
    cudaFuncSetAttribute(gemm_fb<true>,  cudaFuncAttributeMaxDynamicSharedMemorySize, G_SMEM_BYTES);
    cudaFuncSetAttribute(gemm_fb<false>, cudaFuncAttributeMaxDynamicSharedMemorySize, G_SMEM_BYTES);
    cudaFuncSetAttribute(attn_tc, cudaFuncAttributeMaxDynamicSharedMemorySize, AT3_SMEM);
    cudaFuncSetAttribute(attn_v2, cudaFuncAttributeMaxDynamicSharedMemorySize, AT_SMEM_BYTES);

    // 1) QKV projection -> tf32 bits; V tiles go straight to g_vt transposed
    gemm_tc<true><<<dim3(QKVN / TC_BN, MTOT / 256), 256, TC_SMEM>>>(
        x_tf, qw_tf, qkv_b, qkv, vt, CDIM, QKVN);
    gemm_fb<true><<<dim3(QKVN / 64, MTOT / 256), 256, G_SMEM_BYTES>>>(
        x_tf, qw_tf, qkv_b, qkv, nullptr, CDIM, QKVN);

    // 2) Fused attention -> tf32 bits (exactly one path does work)
    attn_tc<<<dim3(SEQ / 128, BDIM * NH), 256, AT3_SMEM>>>(qkv, vt, attn);
    attn_v2<<<dim3(SEQ / 128, BDIM * NH), 256, AT_SMEM_BYTES>>>(qkv, attn);

    // 3) Output projection -> fp32 (exactly one path does work)
    gemm_tc<false><<<dim3(CDIM / TC_BN, MTOT / 256), 256, TC_SMEM>>>(
        attn, pw_tf, proj_b, outp, nullptr, PK, CDIM);
    gemm_fb<false><<<dim3(CDIM / 64, MTOT / 256), 256, G_SMEM_BYTES>>>(
        attn, pw_tf, proj_b, outp, nullptr, PK, CDIM);
}

// round 17
// speedup vs baseline: 1.7702x; 1.0187x over previous
#include <cuda_runtime.h>
#include <cstdint>

#define BDIM 16
#define SEQ  1024
#define CDIM 768
#define NH   9
#define HDIM 64
#define MTOT (BDIM*SEQ)        // 16384
#define QKVN (3*NH*HDIM)       // 1728
#define PK   (NH*HDIM)         // 576

// Does THIS device-compile stage support tcgen05 (arch-/family-specific target)?
#if defined(__CUDA_ARCH__)
#  if defined(__CUDA_ARCH_FEAT_SM103_ALL) || defined(__CUDA_ARCH_FEAT_SM100_ALL) || \
      (defined(__CUDA_ARCH_FAMILY_SPECIFIC__) && (__CUDA_ARCH_FAMILY_SPECIFIC__ >= 1000))
#    define HAS_TCGEN05 1
#  else
#    define HAS_TCGEN05 0
#  endif
#else
#  define HAS_TCGEN05 0
#endif

// Scratch (device globals: allocation-free per harness rules). tf32 bit patterns.
__device__ uint32_t g_x_tf[(size_t)MTOT * CDIM];
__device__ uint32_t g_qw_tf[(size_t)QKVN * CDIM];
__device__ uint32_t g_pw_tf[(size_t)CDIM * PK];
__device__ uint32_t g_qkv[(size_t)MTOT * QKVN];
__device__ uint32_t g_vt[(size_t)BDIM * NH * HDIM * SEQ];   // V^T [b,h,d,seq]
__device__ uint32_t g_attn[(size_t)MTOT * PK];

__device__ __forceinline__ uint32_t f2tf(float f) {
    uint32_t u;
    asm("cvt.rna.tf32.f32 %0, %1;" : "=r"(u) : "f"(f));
    return u;
}
__device__ __forceinline__ void mma_tf32(float* d, const uint32_t* a,
                                         uint32_t b0, uint32_t b1) {
    asm volatile(
        "mma.sync.aligned.m16n8k8.row.col.f32.tf32.tf32.f32 "
        "{%0,%1,%2,%3},{%4,%5,%6,%7},{%8,%9},{%0,%1,%2,%3};\n"
        : "+f"(d[0]), "+f"(d[1]), "+f"(d[2]), "+f"(d[3])
        : "r"(a[0]), "r"(a[1]), "r"(a[2]), "r"(a[3]), "r"(b0), "r"(b1));
}
__device__ __forceinline__ uint32_t smaddr(const void* p) {
    return (uint32_t)__cvta_generic_to_shared(p);
}
__device__ __forceinline__ void cpa16(uint32_t s, const void* g) {
    asm volatile("cp.async.cg.shared.global [%0], [%1], 16;" :: "r"(s), "l"(g));
}
#define CPA_COMMIT() asm volatile("cp.async.commit_group;")
#define CPA_WAIT0()  asm volatile("cp.async.wait_group 0;")
#define CPA_WAIT1()  asm volatile("cp.async.wait_group 1;")
#define SWZ128(x) ((x) ^ (((x) >> 3) & 0x70))

// ---------------------------------------------------------------------------
__global__ void cvt_tf32_kernel(const float4* __restrict__ in,
                                uint4* __restrict__ out, int n4) {
    const int i = blockIdx.x * blockDim.x + threadIdx.x;
    if (i < n4) {
        float4 v = in[i];
        uint4 o = { f2tf(v.x), f2tf(v.y), f2tf(v.z), f2tf(v.w) };
        out[i] = o;
    }
}

#if HAS_TCGEN05
__device__ __forceinline__ uint32_t elect_one_pred() {
    uint32_t pred;
    asm volatile("{\n\t.reg .pred p;\n\telect.sync _|p, 0xFFFFFFFF;\n\t"
                 "selp.b32 %0, 1, 0, p;\n\t}" : "=r"(pred));
    return pred;
}
#define TC_ALLOC(sm_res, n) \
    asm volatile("tcgen05.alloc.cta_group::1.sync.aligned.shared::cta.b32 [%0], %1;" \
                 :: "r"((uint32_t)(sm_res)), "r"((uint32_t)(n)) : "memory")
#define TC_RELINQ() \
    asm volatile("tcgen05.relinquish_alloc_permit.cta_group::1.sync.aligned;")
#define TC_DEALLOC(tm, n) \
    asm volatile("tcgen05.dealloc.cta_group::1.sync.aligned.b32 %0, %1;" :: "r"(tm), "r"((uint32_t)(n)))
#define TC_COMMIT(mb) \
    asm volatile("tcgen05.commit.cta_group::1.mbarrier::arrive::one.shared::cluster.b64 [%0];" \
                 :: "r"((uint32_t)(mb)) : "memory")
#define TC_FENCE_AFTER()  asm volatile("tcgen05.fence::after_thread_sync;" ::: "memory")
#define TC_FENCE_BEFORE() asm volatile("tcgen05.fence::before_thread_sync;" ::: "memory")
#define TC_WAIT_LD() asm volatile("tcgen05.wait::ld.sync.aligned;" ::: "memory")
#define TC_WAIT_ST() asm volatile("tcgen05.wait::st.sync.aligned;" ::: "memory")
#define MBAR_INIT(mb, c) \
    asm volatile("mbarrier.init.shared.b64 [%0], %1;" :: "r"((uint32_t)(mb)), "r"((uint32_t)(c)) : "memory")
#define MBAR_WAIT(mb, par) do { \
    uint32_t _m = (uint32_t)(mb), _p = (uint32_t)(par), _d; \
    asm volatile("{\n\t.reg .pred p;\n\t" \
        "mbarrier.try_wait.parity.acquire.cta.shared::cta.b64 p, [%1], %2;\n\t" \
        "selp.b32 %0, 1, 0, p;\n\t}" : "=r"(_d) : "r"(_m), "r"(_p) : "memory"); \
    if (!_d) { \
        asm volatile("{\n\t.reg .pred P1;\n\tWL_%=:\n\t" \
            "mbarrier.try_wait.parity.acquire.cta.shared::cta.b64 P1, [%0], %1, 0x989680;\n\t" \
            "@P1 bra.uni WD_%=;\n\tbra.uni WL_%=;\n\tWD_%=:\n\t}" \
            :: "r"(_m), "r"(_p) : "memory"); \
    } } while (0)

__device__ __forceinline__ void tc_mma_tf32_ss(uint32_t d_tmem, uint64_t ad,
                                               uint64_t bd, uint32_t idesc,
                                               uint32_t en) {
    asm volatile(
        "{\n\t.reg .pred p;\n\tsetp.ne.u32 p, %4, 0;\n\t"
        "tcgen05.mma.cta_group::1.kind::tf32 [%0], %1, %2, %3, p;\n\t}"
        :: "r"(d_tmem), "l"(ad), "l"(bd), "r"(idesc), "r"(en) : "memory");
}
__device__ __forceinline__ void tc_mma_tf32_ts(uint32_t d_tmem, uint32_t a_tmem,
                                               uint64_t bd, uint32_t idesc,
                                               uint32_t en) {
    asm volatile(
        "{\n\t.reg .pred p;\n\tsetp.ne.u32 p, %4, 0;\n\t"
        "tcgen05.mma.cta_group::1.kind::tf32 [%0], [%1], %2, %3, p;\n\t}"
        :: "r"(d_tmem), "r"(a_tmem), "l"(bd), "r"(idesc), "r"(en) : "memory");
}
#define TC_LD32(r, ta) \
    asm volatile( \
        "tcgen05.ld.sync.aligned.32x32b.x32.b32 " \
        "{%0,%1,%2,%3,%4,%5,%6,%7,%8,%9,%10,%11,%12,%13,%14,%15," \
        "%16,%17,%18,%19,%20,%21,%22,%23,%24,%25,%26,%27,%28,%29,%30,%31},[%32];" \
        : "=r"((r)[0]), "=r"((r)[1]), "=r"((r)[2]), "=r"((r)[3]), "=r"((r)[4]), \
          "=r"((r)[5]), "=r"((r)[6]), "=r"((r)[7]), "=r"((r)[8]), "=r"((r)[9]), \
          "=r"((r)[10]), "=r"((r)[11]), "=r"((r)[12]), "=r"((r)[13]), "=r"((r)[14]), \
          "=r"((r)[15]), "=r"((r)[16]), "=r"((r)[17]), "=r"((r)[18]), "=r"((r)[19]), \
          "=r"((r)[20]), "=r"((r)[21]), "=r"((r)[22]), "=r"((r)[23]), "=r"((r)[24]), \
          "=r"((r)[25]), "=r"((r)[26]), "=r"((r)[27]), "=r"((r)[28]), "=r"((r)[29]), \
          "=r"((r)[30]), "=r"((r)[31]) \
        : "r"(ta))
#define TC_ST32(ta, r) \
    asm volatile( \
        "tcgen05.st.sync.aligned.32x32b.x32.b32 [%0], " \
        "{%1,%2,%3,%4,%5,%6,%7,%8,%9,%10,%11,%12,%13,%14,%15,%16," \
        "%17,%18,%19,%20,%21,%22,%23,%24,%25,%26,%27,%28,%29,%30,%31,%32};" \
        :: "r"(ta), \
           "r"((r)[0]), "r"((r)[1]), "r"((r)[2]), "r"((r)[3]), "r"((r)[4]), \
           "r"((r)[5]), "r"((r)[6]), "r"((r)[7]), "r"((r)[8]), "r"((r)[9]), \
           "r"((r)[10]), "r"((r)[11]), "r"((r)[12]), "r"((r)[13]), "r"((r)[14]), \
           "r"((r)[15]), "r"((r)[16]), "r"((r)[17]), "r"((r)[18]), "r"((r)[19]), \
           "r"((r)[20]), "r"((r)[21]), "r"((r)[22]), "r"((r)[23]), "r"((r)[24]), \
           "r"((r)[25]), "r"((r)[26]), "r"((r)[27]), "r"((r)[28]), "r"((r)[29]), \
           "r"((r)[30]), "r"((r)[31]) \
        : "memory")
__device__ __forceinline__ uint64_t mk_desc(uint32_t addr) {
    return ((uint64_t)2 << 61) | ((uint64_t)1 << 46) | ((uint64_t)64 << 32)
         | ((uint64_t)1 << 16) | (uint64_t)((addr >> 4) & 0x3FFF);
}
#endif // HAS_TCGEN05

// ===========================================================================
// tcgen05 tf32 GEMM (R14/R16-proven, FROZEN): BM=256, BN=192, 3-stage ring.
// V-tiles of gemm1 (vtout != null, n0 >= 1152) store transposed into g_vt.
// ===========================================================================
#define TC_BN 192
#define G_ASTG 32768
#define G_BSTG (TC_BN*128)
#define OFF_A0 1024
#define OFF_B0 (OFF_A0 + 3*G_ASTG)
#define TC_SMEM (OFF_B0 + 3*G_BSTG)
#if HAS_TCGEN05
#define TC_IDESC ((1u<<4) | (2u<<7) | (2u<<10) | ((TC_BN/8)<<17) | (8u<<24))
#endif

template <bool OUT_TF>
__global__ __launch_bounds__(256) void gemm_tc(
    const uint32_t* __restrict__ A, const uint32_t* __restrict__ W,
    const float* __restrict__ bias, void* __restrict__ Cout,
    uint32_t* __restrict__ vtout,
    int Kdim, int Ndim)
{
#if HAS_TCGEN05
    extern __shared__ char smem[];
    const uint32_t sbase = smaddr(smem);
    const int t = threadIdx.x, lane = t & 31, warp = t >> 5;
    const int m0 = blockIdx.y * 256, n0 = blockIdx.x * TC_BN;
    const uint32_t mb0 = sbase + 8, mb1 = sbase + 16;

    if (warp == 0) { TC_ALLOC(sbase, 512); TC_RELINQ(); }
    if (t == 0) { MBAR_INIT(mb0, 1); MBAR_INIT(mb1, 1); }
    __syncthreads();
    uint32_t tmem;
    asm volatile("ld.shared.b32 %0, [%1];" : "=r"(tmem) : "r"(sbase));

    const int KT = Kdim >> 5;

    auto loadA = [&](int st, int k0) {
        const uint32_t base = sbase + OFF_A0 + st * G_ASTG;
        #pragma unroll
        for (int i = 0; i < 8; i++) {
            const int idx = t + 256 * i, row = idx >> 3, ch = idx & 7;
            cpa16(base + (uint32_t)((row >> 3) << 10)
                       + SWZ128((uint32_t)(((row & 7) << 7) + ch * 16)),
                  A + (size_t)(m0 + row) * Kdim + k0 + ch * 4);
        }
    };
    auto loadB = [&](int st, int k0) {
        const uint32_t base = sbase + OFF_B0 + st * G_BSTG;
        #pragma unroll
        for (int i = 0; i < 6; i++) {
            const int idx = t + 256 * i, row = idx >> 3, ch = idx & 7;
            cpa16(base + (uint32_t)((row >> 3) << 10)
                       + SWZ128((uint32_t)(((row & 7) << 7) + ch * 16)),
                  W + (size_t)(n0 + row) * Kdim + k0 + ch * 4);
        }
    };

    loadA(0, 0); loadB(0, 0); CPA_COMMIT();
    loadA(1, 32); loadB(1, 32); CPA_COMMIT();
    int pw0 = 0, pw1 = 0;

    for (int kt = 0; kt < KT; kt++) {
        CPA_WAIT1();
        asm volatile("fence.proxy.async.shared::cta;" ::: "memory");
        __syncthreads();
        if (warp == 0 && elect_one_pred()) {
            const int st = kt % 3;
            const uint32_t abase = sbase + OFF_A0 + st * G_ASTG;
            const uint64_t ad0 = mk_desc(abase);
            const uint64_t ad1 = mk_desc(abase + 16384);
            const uint64_t bd  = mk_desc(sbase + OFF_B0 + st * G_BSTG);
            const uint32_t en = (kt > 0) ? 1u : 0u;
            #pragma unroll
            for (int s = 0; s < 4; s++) {
                const uint32_t e = (en || s > 0) ? 1u : 0u;
                tc_mma_tf32_ss(tmem,          ad0 + 2 * s, bd + 2 * s, TC_IDESC, e);
                tc_mma_tf32_ss(tmem + TC_BN,  ad1 + 2 * s, bd + 2 * s, TC_IDESC, e);
            }
            TC_COMMIT((kt & 1) ? mb1 : mb0);
        }
        if (kt >= 1) {
            if ((kt - 1) & 1) { MBAR_WAIT(mb1, pw1 & 1); pw1++; }
            else              { MBAR_WAIT(mb0, pw0 & 1); pw0++; }
        }
        if (kt + 2 < KT) {
            loadA((kt + 2) % 3, (kt + 2) * 32);
            loadB((kt + 2) % 3, (kt + 2) * 32);
        }
        CPA_COMMIT();
    }
    if ((KT - 1) & 1) { MBAR_WAIT(mb1, pw1 & 1); }
    else              { MBAR_WAIT(mb0, pw0 & 1); }
    TC_FENCE_AFTER();

    const int row = m0 + (warp >> 2) * 128 + (warp & 3) * 32 + lane;
    const uint32_t dbase = tmem + (warp >> 2) * TC_BN;
    const bool vtile = OUT_TF && (vtout != nullptr) && (n0 >= 2 * NH * HDIM);
    const int bb = row >> 10, nn = row & 1023;
    #pragma unroll
    for (int cc = 0; cc < TC_BN; cc += 32) {
        uint32_t dr[32];
        TC_LD32(dr, dbase + cc);
        TC_WAIT_LD();
        #pragma unroll
        for (int j = 0; j < 32; j += 4) {
            const int c = n0 + cc + j;
            float v0 = __uint_as_float(dr[j])     + bias[c];
            float v1 = __uint_as_float(dr[j + 1]) + bias[c + 1];
            float v2 = __uint_as_float(dr[j + 2]) + bias[c + 2];
            float v3 = __uint_as_float(dr[j + 3]) + bias[c + 3];
            if (vtile) {
                const int vd = c - 2 * NH * HDIM;
                const uint32_t tf[4] = { f2tf(v0), f2tf(v1), f2tf(v2), f2tf(v3) };
                #pragma unroll
                for (int e = 0; e < 4; e++) {
                    const int h = (vd + e) >> 6, d = (vd + e) & 63;
                    vtout[((size_t)(bb * NH + h) * HDIM + d) * SEQ + nn] = tf[e];
                }
            } else if (OUT_TF) {
                uint4 o = { f2tf(v0), f2tf(v1), f2tf(v2), f2tf(v3) };
                *(uint4*)((uint32_t*)Cout + (size_t)row * Ndim + c) = o;
            } else {
                float4 o = { v0, v1, v2, v3 };
                *(float4*)((float*)Cout + (size_t)row * Ndim + c) = o;
            }
        }
    }
    __syncthreads();
    if (warp == 0) TC_DEALLOC(tmem, 512);
#endif
}

// ===========================================================================
// tcgen05 fused attention v6: v5 (256 thr, column-split softmax) + v3b
// two-barrier overlap: S(jt+1) issued BEFORE softmax(jt) so the tensor pipe
// computes the next S during the MUFU-heavy softmax.
//   mbS  <- S commits only;  wait cursor jt before S(jt+1) issues  (k<=c+1)
//   mbPV <- PV commits only; wait cursor jt-1 before PV(jt) issues (k<=c+1)
// Stage reuse: K(jt+2) over stage jt&1 (reader S(jt) waited); VT(jt+1) over
// stage (jt+1)&1 (reader PV(jt-1) waited). S-buffer WAR: S(jt+1) writes the
// buffer last read by PV(jt-1), already waited.
// TMEM: O 0-63, S0 64-127, S1 128-191 (alloc 256; 2 CTAs/SM).
// ===========================================================================
#define AT3_Q   1024
#define AT3_K0  (AT3_Q  + 32768)
#define AT3_K1  (AT3_K0 + 16384)
#define AT3_V0  (AT3_K1 + 16384)
#define AT3_V1  (AT3_V0 + 16384)
#define AT3_SMEM (AT3_V1 + 16384)
#if HAS_TCGEN05
#define AT_IDESC ((1u<<4) | (2u<<7) | (2u<<10) | (8u<<17) | (8u<<24))
__device__ __forceinline__ uint32_t blk_off(int r, int cb, int atomrows) {
    const uint32_t local = (uint32_t)(((r & 7) << 7) | (cb & 127));
    const uint32_t atom = (uint32_t)((r >> 3) + ((cb >> 7) * atomrows));
    return (atom << 10) + SWZ128(local);
}
#endif

__global__ __launch_bounds__(256) void attn_tc(
    const uint32_t* __restrict__ qkv, const uint32_t* __restrict__ vt,
    uint32_t* __restrict__ outp)
{
#if HAS_TCGEN05
    extern __shared__ char smem[];
    const uint32_t sbase = smaddr(smem);
    const int t = threadIdx.x, lane = t & 31, warp = t >> 5;
    const int sp = warp & 3, chh = warp >> 2;
    const int bh = blockIdx.y, b = bh / NH, h = bh % NH;
    const int q0 = blockIdx.x * 128;
    const uint32_t mbS = sbase + 8, mbPV = sbase + 16;
    float* lsh = (float*)(smem + 32);
    const uint32_t woff = (uint32_t)sp << 21;

    const uint32_t* Qg = qkv + (size_t)b * SEQ * QKVN + h * HDIM;
    const uint32_t* Kg = Qg + NH * HDIM;
    const uint32_t* Vt = vt + (size_t)bh * HDIM * SEQ;

    if (warp == 0) { TC_ALLOC(sbase, 256); TC_RELINQ(); }
    if (t == 0) { MBAR_INIT(mbS, 1); MBAR_INIT(mbPV, 1); }
    __syncthreads();
    uint32_t tmem;
    asm volatile("ld.shared.b32 %0, [%1];" : "=r"(tmem) : "r"(sbase));
    const uint32_t tO = tmem;
    const uint32_t tSb[2] = { tmem + 64, tmem + 128 };
    const uint32_t KST[2] = { sbase + AT3_K0, sbase + AT3_K1 };
    const uint32_t VST[2] = { sbase + AT3_V0, sbase + AT3_V1 };

    auto loadK = [&](int st, int j0) {
        #pragma unroll
        for (int i = 0; i < 4; i++) {
            const int c = t + 256 * i, row = c >> 4, cb = (c & 15) * 16;
            cpa16(KST[st] + blk_off(row, cb, 8),
                  Kg + (size_t)(j0 + row) * QKVN + (cb >> 2));
        }
    };
    auto loadV = [&](int st, int j0) {
        #pragma unroll
        for (int i = 0; i < 4; i++) {
            const int c = t + 256 * i, row = c >> 4, cb = (c & 15) * 16;
            cpa16(VST[st] + blk_off(row, cb, 8),
                  Vt + (size_t)row * SEQ + j0 + (cb >> 2));
        }
    };

    #pragma unroll
    for (int i = 0; i < 8; i++) {
        const int c = t + 256 * i, row = c >> 4, cb = (c & 15) * 16;
        cpa16(sbase + AT3_Q + blk_off(row, cb, 16),
              Qg + (size_t)(q0 + row) * QKVN + (cb >> 2));
    }
    loadK(0, 0); loadV(0, 0); CPA_COMMIT();
    loadK(1, 64); CPA_COMMIT();

    const uint64_t qdesc = mk_desc(sbase + AT3_Q);
    const uint32_t QSTEP[8] = {0, 2, 4, 6, 1024, 1026, 1028, 1030};
    const uint32_t KSTEP[8] = {0, 2, 4, 6, 512, 514, 516, 518};

    CPA_WAIT1();
    asm volatile("fence.proxy.async.shared::cta;" ::: "memory");
    __syncthreads();
    if (warp == 0 && elect_one_pred()) {   // S(0) -> mbS
        const uint64_t kd = mk_desc(KST[0]);
        #pragma unroll
        for (int s = 0; s < 8; s++)
            tc_mma_tf32_ss(tSb[0], qdesc + QSTEP[s], kd + KSTEP[s],
                           AT_IDESC, s > 0 ? 1u : 0u);
        TC_COMMIT(mbS);
    }

    const int r0 = sp * 32 + lane;
    float l = 0.f;
    const float cexp = 0.18033688f;   // 0.125 * log2(e)

    for (int jt = 0; jt < 16; jt++) {
        MBAR_WAIT(mbS, jt & 1);                       // S(jt) done
        if (jt > 0) MBAR_WAIT(mbPV, (jt - 1) & 1);    // PV(jt-1) done
        TC_FENCE_AFTER();

        if (jt + 2 < 16) loadK(jt & 1, (jt + 2) * 64);
        if (jt + 1 < 16) loadV((jt + 1) & 1, (jt + 1) * 64);
        CPA_COMMIT();
        CPA_WAIT1();
        asm volatile("fence.proxy.async.shared::cta;" ::: "memory");
        __syncthreads();

        // issue S(jt+1) NOW -> overlaps the softmax below
        if (jt + 1 < 16 && warp == 0 && elect_one_pred()) {
            const uint64_t kd = mk_desc(KST[(jt + 1) & 1]);
            #pragma unroll
            for (int s = 0; s < 8; s++)
                tc_mma_tf32_ss(tSb[(jt + 1) & 1], qdesc + QSTEP[s],
                               kd + KSTEP[s], AT_IDESC, s > 0 ? 1u : 0u);
            TC_COMMIT(mbS);
        }

        // softmax(jt): warp handles 32 cols [chh*32, +32) of its 32 rows
        const uint32_t tS = tSb[jt & 1];
        {
            uint32_t sr[32];
            TC_LD32(sr, tS + chh * 32);
            TC_WAIT_LD();
            #pragma unroll
            for (int i = 0; i < 32; i++) {
                const float p = exp2f(__uint_as_float(sr[i]) * cexp);
                l += p;
                sr[i] = f2tf(p);
            }
            TC_ST32(tS + chh * 32 + woff, sr);
            TC_WAIT_ST();
        }
        TC_FENCE_BEFORE();
        __syncthreads();

        // PV(jt) -> mbPV
        if (warp == 0 && elect_one_pred()) {
            TC_FENCE_AFTER();
            const uint64_t vd = mk_desc(VST[jt & 1]);
            #pragma unroll
            for (int s = 0; s < 8; s++)
                tc_mma_tf32_ts(tO, tS + 8 * s, vd + KSTEP[s],
                               AT_IDESC, (jt > 0 || s > 0) ? 1u : 0u);
            TC_COMMIT(mbPV);
        }
    }

    // combine l halves; wait PV(15) at cursor 15 (parity 1)
    if (chh == 0) lsh[r0] = l;
    __syncthreads();
    if (chh == 1) lsh[r0] += l;
    MBAR_WAIT(mbPV, 1);
    __syncthreads();
    TC_FENCE_AFTER();
    const float inv = 1.0f / lsh[r0];
    uint32_t* ob = outp + (size_t)(b * SEQ + q0 + r0) * PK + h * HDIM + chh * 32;
    {
        uint32_t orr[32];
        TC_LD32(orr, tO + chh * 32);
        TC_WAIT_LD();
        #pragma unroll
        for (int j = 0; j < 32; j += 4) {
            uint4 o = { f2tf(__uint_as_float(orr[j])     * inv),
                        f2tf(__uint_as_float(orr[j + 1]) * inv),
                        f2tf(__uint_as_float(orr[j + 2]) * inv),
                        f2tf(__uint_as_float(orr[j + 3]) * inv) };
            *(uint4*)(ob + j) = o;
        }
    }
    __syncthreads();
    if (warp == 0) TC_DEALLOC(tmem, 256);
#endif
}

// ===========================================================================
// Fallback attention (R6-proven mma.sync) — only in base-target stages.
// ===========================================================================
#define AT_KSTAGE (64 * 68)
#define AT_VSTAGE (64 * 72)
#define AT_SMEM_BYTES ((128 * 68 + 2 * AT_KSTAGE + 2 * AT_VSTAGE) * 4)

__global__ __launch_bounds__(256, 2) void attn_v2(
    const uint32_t* __restrict__ qkv, uint32_t* __restrict__ outp)
{
#if !HAS_TCGEN05
    extern __shared__ uint32_t sm[];
    uint32_t* Qs = sm;
    uint32_t* Ks = Qs + 128 * 68;
    uint32_t* Vs = Ks + 2 * AT_KSTAGE;

    const int t = threadIdx.x, lane = t & 31, warp = t >> 5;
    const int q = lane & 3, r8 = lane >> 2;
    const int bh = blockIdx.y, b = bh / NH, h = bh % NH;
    const int q0 = blockIdx.x * 128;
    const float scale = 0.125f;

    const uint32_t* Qg = qkv + (size_t)b * SEQ * QKVN + h * HDIM;
    const uint32_t* Kg = Qg + NH * HDIM;
    const uint32_t* Vg = Qg + 2 * NH * HDIM;
    const int r0 = warp * 16 + r8;
    const int c4 = (t & 15) * 4, rb = t >> 4;

    {
        #pragma unroll
        for (int i = 0; i < 8; i++) {
            const int r = rb + 16 * i;
            cpa16(smaddr(&Qs[r * 68 + c4]), Qg + (size_t)(q0 + r) * QKVN + c4);
        }
        #pragma unroll
        for (int i = 0; i < 4; i++) {
            const int r = rb + 16 * i;
            cpa16(smaddr(&Ks[r * 68 + c4]), Kg + (size_t)r * QKVN + c4);
            cpa16(smaddr(&Vs[r * 72 + c4]), Vg + (size_t)r * QKVN + c4);
        }
        CPA_COMMIT();
    }

    float O[8][4] = {};
    float m0 = -1e30f, m1 = -1e30f, l0 = 0.f, l1 = 0.f;
    const int src1 = (lane & 28) | (q >> 1);
    const int src2 = src1 | 2;

    for (int jt = 0; jt < SEQ / 64; jt++) {
        CPA_WAIT0();
        __syncthreads();
        if (jt + 1 < SEQ / 64) {
            const int s = (jt + 1) & 1;
            const int j0 = (jt + 1) * 64;
            #pragma unroll
            for (int i = 0; i < 4; i++) {
                const int r = rb + 16 * i;
                cpa16(smaddr(&Ks[s * AT_KSTAGE + r * 68 + c4]),
                      Kg + (size_t)(j0 + r) * QKVN + c4);
                cpa16(smaddr(&Vs[s * AT_VSTAGE + r * 72 + c4]),
                      Vg + (size_t)(j0 + r) * QKVN + c4);
            }
            CPA_COMMIT();
        }
        const uint32_t* Kst = Ks + (jt & 1) * AT_KSTAGE;
        const uint32_t* Vst = Vs + (jt & 1) * AT_VSTAGE;

        float s[8][4] = {};
        #pragma unroll
        for (int kc = 0; kc < 8; kc++) {
            const int kb = kc * 8 + q;
            uint32_t a[4];
            a[0] = Qs[r0 * 68 + kb];     a[1] = Qs[(r0 + 8) * 68 + kb];
            a[2] = Qs[r0 * 68 + kb + 4]; a[3] = Qs[(r0 + 8) * 68 + kb + 4];
            #pragma unroll
            for (int ni = 0; ni < 8; ni++) {
                const int n = ni * 8 + r8;
                mma_tf32(s[ni], a, Kst[n * 68 + kb], Kst[n * 68 + kb + 4]);
            }
        }

        float mx0 = -1e30f, mx1 = -1e30f;
        #pragma unroll
        for (int ni = 0; ni < 8; ni++) {
            s[ni][0] *= scale; s[ni][1] *= scale;
            s[ni][2] *= scale; s[ni][3] *= scale;
            mx0 = fmaxf(mx0, fmaxf(s[ni][0], s[ni][1]));
            mx1 = fmaxf(mx1, fmaxf(s[ni][2], s[ni][3]));
        }
        mx0 = fmaxf(mx0, __shfl_xor_sync(0xffffffffu, mx0, 1));
        mx0 = fmaxf(mx0, __shfl_xor_sync(0xffffffffu, mx0, 2));
        mx1 = fmaxf(mx1, __shfl_xor_sync(0xffffffffu, mx1, 1));
        mx1 = fmaxf(mx1, __shfl_xor_sync(0xffffffffu, mx1, 2));
        const float mn0 = fmaxf(m0, mx0), mn1 = fmaxf(m1, mx1);
        const float al0 = __expf(m0 - mn0), al1 = __expf(m1 - mn1);
        m0 = mn0; m1 = mn1;
        float sum0 = 0.f, sum1 = 0.f;
        #pragma unroll
        for (int ni = 0; ni < 8; ni++) {
            s[ni][0] = __expf(s[ni][0] - mn0); sum0 += s[ni][0];
            s[ni][1] = __expf(s[ni][1] - mn0); sum0 += s[ni][1];
            s[ni][2] = __expf(s[ni][2] - mn1); sum1 += s[ni][2];
            s[ni][3] = __expf(s[ni][3] - mn1); sum1 += s[ni][3];
        }
        sum0 += __shfl_xor_sync(0xffffffffu, sum0, 1);
        sum0 += __shfl_xor_sync(0xffffffffu, sum0, 2);
        sum1 += __shfl_xor_sync(0xffffffffu, sum1, 1);
        sum1 += __shfl_xor_sync(0xffffffffu, sum1, 2);
        l0 = l0 * al0 + sum0;
        l1 = l1 * al1 + sum1;
        #pragma unroll
        for (int ni = 0; ni < 8; ni++) {
            O[ni][0] *= al0; O[ni][1] *= al0;
            O[ni][2] *= al1; O[ni][3] *= al1;
        }

        #pragma unroll
        for (int kc = 0; kc < 8; kc++) {
            const float v0 = __shfl_sync(0xffffffffu, s[kc][0], src1);
            const float v1 = __shfl_sync(0xffffffffu, s[kc][1], src1);
            const float v2 = __shfl_sync(0xffffffffu, s[kc][2], src1);
            const float v3 = __shfl_sync(0xffffffffu, s[kc][3], src1);
            const float w0 = __shfl_sync(0xffffffffu, s[kc][0], src2);
            const float w1 = __shfl_sync(0xffffffffu, s[kc][1], src2);
            const float w2 = __shfl_sync(0xffffffffu, s[kc][2], src2);
            const float w3 = __shfl_sync(0xffffffffu, s[kc][3], src2);
            const bool odd = (q & 1);
            uint32_t a[4];
            a[0] = f2tf(odd ? v1 : v0);
            a[1] = f2tf(odd ? v3 : v2);
            a[2] = f2tf(odd ? w1 : w0);
            a[3] = f2tf(odd ? w3 : w2);
            const int kb = kc * 8 + q;
            #pragma unroll
            for (int ni = 0; ni < 8; ni++) {
                const int dv = ni * 8 + r8;
                mma_tf32(O[ni], a, Vst[kb * 72 + dv], Vst[(kb + 4) * 72 + dv]);
            }
        }
    }

    const float inv0 = 1.0f / l0, inv1 = 1.0f / l1;
    uint32_t* ob = outp + (size_t)(b * SEQ + q0) * PK + h * HDIM;
    #pragma unroll
    for (int ni = 0; ni < 8; ni++) {
        const int c = ni * 8 + 2 * q;
        uint2 o0 = { f2tf(O[ni][0] * inv0), f2tf(O[ni][1] * inv0) };
        uint2 o1 = { f2tf(O[ni][2] * inv1), f2tf(O[ni][3] * inv1) };
        *(uint2*)(ob + (size_t)r0 * PK + c)       = o0;
        *(uint2*)(ob + (size_t)(r0 + 8) * PK + c) = o1;
    }
#endif
}

// ===========================================================================
// Fallback GEMM (R6-proven mma.sync) — only in base-target stages.
// ===========================================================================
#define G_ASTRIDE 36
#define G_ASTAGE  (256 * G_ASTRIDE)
#define G_FBSTAGE (64 * G_ASTRIDE)
#define G_SMEM_BYTES ((2 * G_ASTAGE + 2 * G_FBSTAGE) * 4)

template <bool OUT_TF>
__global__ __launch_bounds__(256, 2) void gemm_fb(
    const uint32_t* __restrict__ A, const uint32_t* __restrict__ W,
    const float* __restrict__ bias, void* __restrict__ Cout,
    uint32_t* __restrict__ vtout,
    int Kdim, int Ndim)
{
#if !HAS_TCGEN05
    extern __shared__ uint32_t dsm[];
    uint32_t* As = dsm;
    uint32_t* Bs = dsm + 2 * G_ASTAGE;

    const int t = threadIdx.x, lane = t & 31, warp = t >> 5;
    const int wm = warp >> 1, wn = warp & 1;
    const int q = lane & 3, r8 = lane >> 2;
    const int m0 = blockIdx.y * 256, n0 = blockIdx.x * 64;
    const int lr = t >> 3, lc4 = (t & 7) * 4;
    const int KT = Kdim >> 5;
    (void)vtout;

    float acc[16][4] = {};

    const uint32_t* Ag = A + (size_t)(m0 + lr) * Kdim + lc4;
    const uint32_t* Wg = W + (size_t)(n0 + lr) * Kdim + lc4;

    {
        #pragma unroll
        for (int i = 0; i < 8; i++)
            cpa16(smaddr(&As[(lr + 32 * i) * G_ASTRIDE + lc4]),
                  Ag + (size_t)(32 * i) * Kdim);
        #pragma unroll
        for (int i = 0; i < 2; i++)
            cpa16(smaddr(&Bs[(lr + 32 * i) * G_ASTRIDE + lc4]),
                  Wg + (size_t)(32 * i) * Kdim);
        CPA_COMMIT();
    }

    for (int kt = 0; kt < KT; kt++) {
        CPA_WAIT0();
        __syncthreads();
        if (kt + 1 < KT) {
            const int s = (kt + 1) & 1;
            const int k0 = (kt + 1) << 5;
            #pragma unroll
            for (int i = 0; i < 8; i++)
                cpa16(smaddr(&As[s * G_ASTAGE + (lr + 32 * i) * G_ASTRIDE + lc4]),
                      Ag + (size_t)(32 * i) * Kdim + k0);
            #pragma unroll
            for (int i = 0; i < 2; i++)
                cpa16(smaddr(&Bs[s * G_FBSTAGE + (lr + 32 * i) * G_ASTRIDE + lc4]),
                      Wg + (size_t)(32 * i) * Kdim + k0);
            CPA_COMMIT();
        }
        const uint32_t* Ast = As + (kt & 1) * G_ASTAGE;
        const uint32_t* Bst = Bs + (kt & 1) * G_FBSTAGE;
        #pragma unroll
        for (int kc = 0; kc < 4; kc++) {
            const int kb = kc * 8 + q;
            uint32_t a[4][4];
            #pragma unroll
            for (int mi = 0; mi < 4; mi++) {
                const int r = wm * 64 + mi * 16 + r8;
                a[mi][0] = Ast[r * G_ASTRIDE + kb];
                a[mi][1] = Ast[(r + 8) * G_ASTRIDE + kb];
                a[mi][2] = Ast[r * G_ASTRIDE + kb + 4];
                a[mi][3] = Ast[(r + 8) * G_ASTRIDE + kb + 4];
            }
            #pragma unroll
            for (int ni = 0; ni < 4; ni++) {
                const int n = wn * 32 + ni * 8 + r8;
                const uint32_t b0 = Bst[n * G_ASTRIDE + kb];
                const uint32_t b1 = Bst[n * G_ASTRIDE + kb + 4];
                #pragma unroll
                for (int mi = 0; mi < 4; mi++)
                    mma_tf32(acc[mi * 4 + ni], a[mi], b0, b1);
            }
        }
    }

    #pragma unroll
    for (int mi = 0; mi < 4; mi++)
        #pragma unroll
        for (int ni = 0; ni < 4; ni++) {
            const float* d = acc[mi * 4 + ni];
            const int r0g = m0 + wm * 64 + mi * 16 + r8;
            const int c   = n0 + wn * 32 + ni * 8 + 2 * q;
            const float bx = bias[c], by = bias[c + 1];
            if (OUT_TF) {
                uint32_t* C = (uint32_t*)Cout;
                uint2 o0 = { f2tf(d[0] + bx), f2tf(d[1] + by) };
                uint2 o1 = { f2tf(d[2] + bx), f2tf(d[3] + by) };
                *(uint2*)(C + (size_t)r0g * Ndim + c)       = o0;
                *(uint2*)(C + (size_t)(r0g + 8) * Ndim + c) = o1;
            } else {
                float* C = (float*)Cout;
                float2 o0 = { d[0] + bx, d[1] + by };
                float2 o1 = { d[2] + bx, d[3] + by };
                *(float2*)(C + (size_t)r0g * Ndim + c)       = o0;
                *(float2*)(C + (size_t)(r0g + 8) * Ndim + c) = o1;
            }
        }
#endif
}

// ---------------------------------------------------------------------------
extern "C" void kernel_launch(void* const* d_in, const int* in_sizes, int n_in,
                              void* d_out, int out_size)
{
    const float* x      = (const float*)d_in[0];
    const float* qkv_w  = (const float*)d_in[1];
    const float* qkv_b  = (const float*)d_in[2];
    const float* proj_w = (const float*)d_in[3];
    const float* proj_b = (const float*)d_in[4];
    float* outp = (float*)d_out;

    uint32_t *x_tf, *qw_tf, *pw_tf, *qkv, *vt, *attn;
    cudaGetSymbolAddress((void**)&x_tf,  g_x_tf);
    cudaGetSymbolAddress((void**)&qw_tf, g_qw_tf);
    cudaGetSymbolAddress((void**)&pw_tf, g_pw_tf);
    cudaGetSymbolAddress((void**)&qkv,   g_qkv);
    cudaGetSymbolAddress((void**)&vt,    g_vt);
    cudaGetSymbolAddress((void**)&attn,  g_attn);

    // 0) Pre-convert inputs to tf32 bits
    {
        const int nx = MTOT * CDIM / 4, nw = QKVN * CDIM / 4, np = CDIM * PK / 4;
        cvt_tf32_kernel<<<(nx + 255) / 256, 256>>>((const float4*)x,      (uint4*)x_tf,  nx);
        cvt_tf32_kernel<<<(nw + 255) / 256, 256>>>((const float4*)qkv_w,  (uint4*)qw_tf, nw);
        cvt_tf32_kernel<<<(np + 255) / 256, 256>>>((const float4*)proj_w, (uint4*)pw_tf, np);
    }

    cudaFuncSetAttribute(gemm_tc<true>,  cudaFuncAttributeMaxDynamicSharedMemorySize, TC_SMEM);
    cudaFuncSetAttribute(gemm_tc<false>, cudaFuncAttributeMaxDynamicSharedMemorySize, TC_SMEM);
    cudaFuncSetAttribute(gemm_fb<true>,  cudaFuncAttributeMaxDynamicSharedMemorySize, G_SMEM_BYTES);
    cudaFuncSetAttribute(gemm_fb<false>, cudaFuncAttributeMaxDynamicSharedMemorySize, G_SMEM_BYTES);
    cudaFuncSetAttribute(attn_tc, cudaFuncAttributeMaxDynamicSharedMemorySize, AT3_SMEM);
    cudaFuncSetAttribute(attn_v2, cudaFuncAttributeMaxDynamicSharedMemorySize, AT_SMEM_BYTES);

    // 1) QKV projection -> tf32 bits; V tiles go straight to g_vt transposed
    gemm_tc<true><<<dim3(QKVN / TC_BN, MTOT / 256), 256, TC_SMEM>>>(
        x_tf, qw_tf, qkv_b, qkv, vt, CDIM, QKVN);
    gemm_fb<true><<<dim3(QKVN / 64, MTOT / 256), 256, G_SMEM_BYTES>>>(
        x_tf, qw_tf, qkv_b, qkv, nullptr, CDIM, QKVN);

    // 2) Fused attention -> tf32 bits (exactly one path does work)
    attn_tc<<<dim3(SEQ / 128, BDIM * NH), 256, AT3_SMEM>>>(qkv, vt, attn);
    attn_v2<<<dim3(SEQ / 128, BDIM * NH), 256, AT_SMEM_BYTES>>>(qkv, attn);

    // 3) Output projection -> fp32 (exactly one path does work)
    gemm_tc<false><<<dim3(CDIM / TC_BN, MTOT / 256), 256, TC_SMEM>>>(
        attn, pw_tf, proj_b, outp, nullptr, PK, CDIM);
    gemm_fb<false><<<dim3(CDIM / 64, MTOT / 256), 256, G_SMEM_BYTES>>>(
        attn, pw_tf, proj_b, outp, nullptr, PK, CDIM);
}